// round 1
// baseline (speedup 1.0000x reference)
#include <cuda_runtime.h>
#include <math.h>

#define NB 2
#define HH 256
#define WW 256
#define HW 65536
#define DHW 16384   // 128*128

// ---------------- scratch (static device allocations) ----------------
__device__ float g_US [NB*96 *HW];   // resized ds_latent (2,96,256,256)
__device__ float g_SU [NB*189*HW];   // su_emb (2,189,256,256)
__device__ float g_WARP[NB*128*HW];  // warped temporal kv
__device__ float g_DSS[NB*128*DHW];  // ds embedding at half res (128 ch)
__device__ float g_DSE[NB*128*HW];   // ds embedding full res
__device__ float g_ATT[NB*64 *HW];   // folded attention output
__device__ float g_H1 [NB*128*HW];   // ffn hidden
__device__ float g_S[192];           // folded BN scale (reused per stage)
__device__ float g_T[192];           // folded BN shift

// ---------------- BN stats -> folded scale/shift ----------------
__global__ void bn_stats_kernel(const float* __restrict__ src0, int C0,
                                const float* __restrict__ src1, int C1,
                                const float* __restrict__ g, const float* __restrict__ b,
                                int hw) {
    int c = blockIdx.x;
    const float* base; int cs;
    if (c < C0) { base = src0 + (size_t)c * hw; cs = C0; }
    else        { base = src1 + (size_t)(c - C0) * hw; cs = C1; }
    float sum = 0.f, sq = 0.f;
    for (int n = 0; n < NB; n++) {
        const float* p = base + (size_t)n * cs * hw;
        for (int i = threadIdx.x; i < hw; i += blockDim.x) {
            float v = p[i]; sum += v; sq += v * v;
        }
    }
    __shared__ float ssum[256], ssq[256];
    ssum[threadIdx.x] = sum; ssq[threadIdx.x] = sq; __syncthreads();
    for (int o = 128; o > 0; o >>= 1) {
        if (threadIdx.x < o) { ssum[threadIdx.x] += ssum[threadIdx.x+o]; ssq[threadIdx.x] += ssq[threadIdx.x+o]; }
        __syncthreads();
    }
    if (threadIdx.x == 0) {
        float inv = 1.f / (float)(NB * hw);
        float m = ssum[0] * inv;
        float v = ssq[0] * inv - m * m;
        float s = g[c] * rsqrtf(v + 1e-5f);
        g_S[c] = s; g_T[c] = b[c] - m * s;
    }
}

// ---------------- fused BN + conv1x1 (tiled GEMM) ----------------
// tile: 128 pixels x 64 out-channels; 256 thr; thread = 4 px x 8 oc
__global__ __launch_bounds__(256)
void conv1x1_kernel(const float* __restrict__ src0, int C0,
                    const float* __restrict__ src1, int C1,
                    const float* __restrict__ w, const float* __restrict__ bias,
                    int Cout, int hw, float* __restrict__ out, int outStride, int relu) {
    __shared__ float xs[32*128];
    __shared__ float ws[64*32];
    int Cin = C0 + C1;
    int tid = threadIdx.x;
    int lane = tid & 31;
    int obase = (tid >> 5) * 8;
    int p0 = blockIdx.x * 128;
    int n = p0 / hw, hw0 = p0 % hw;
    int ot = blockIdx.y;
    float acc[4][8];
    #pragma unroll
    for (int i = 0; i < 4; i++)
        #pragma unroll
        for (int j = 0; j < 8; j++) acc[i][j] = 0.f;

    for (int cc = 0; cc < Cin; cc += 32) {
        for (int idx = tid; idx < 32*128; idx += 256) {
            int cl = idx >> 7, pl = idx & 127;
            int c = cc + cl;
            const float* src = (c < C0) ? (src0 + (size_t)(n*C0 + c) * hw)
                                        : (src1 + (size_t)(n*C1 + (c - C0)) * hw);
            xs[cl*128 + pl] = src[hw0 + pl] * g_S[c] + g_T[c];
        }
        for (int idx = tid; idx < 64*32; idx += 256) {
            int ol = idx >> 5, cl = idx & 31;
            int o = ot*64 + ol;
            ws[ol*32 + cl] = (o < Cout) ? w[(size_t)o * Cin + cc + cl] : 0.f;
        }
        __syncthreads();
        #pragma unroll 4
        for (int cl = 0; cl < 32; cl++) {
            float xv[4];
            #pragma unroll
            for (int i = 0; i < 4; i++) xv[i] = xs[cl*128 + lane + 32*i];
            #pragma unroll
            for (int j = 0; j < 8; j++) {
                float wv = ws[(obase + j)*32 + cl];
                #pragma unroll
                for (int i = 0; i < 4; i++) acc[i][j] += xv[i] * wv;
            }
        }
        __syncthreads();
    }
    #pragma unroll
    for (int j = 0; j < 8; j++) {
        int o = ot*64 + obase + j;
        if (o >= Cout) continue;
        float bv = bias[o];
        #pragma unroll
        for (int i = 0; i < 4; i++) {
            float v = acc[i][j] + bv;
            if (relu) v = fmaxf(v, 0.f);
            out[(size_t)(n*outStride + o) * hw + hw0 + lane + 32*i] = v;
        }
    }
}

// ---------------- align-corners bilinear resize ----------------
__global__ void resize_kernel(const float* __restrict__ src, float* __restrict__ dst,
                              int C, int Hs, int Ws, int Hd, int Wd) {
    int idx = blockIdx.x * blockDim.x + threadIdx.x;
    int total = NB * C * Hd * Wd;
    if (idx >= total) return;
    int x = idx % Wd; int y = (idx / Wd) % Hd; int nc = idx / (Wd * Hd);
    float sy = y * (float)(Hs - 1) / (float)(Hd - 1);
    float sx = x * (float)(Ws - 1) / (float)(Wd - 1);
    int y0 = (int)floorf(sy); int x0 = (int)floorf(sx);
    float wy = sy - y0, wx = sx - x0;
    int y1 = min(y0 + 1, Hs - 1), x1 = min(x0 + 1, Ws - 1);
    const float* p = src + (size_t)nc * Hs * Ws;
    float v00 = p[y0*Ws + x0], v01 = p[y0*Ws + x1];
    float v10 = p[y1*Ws + x0], v11 = p[y1*Ws + x1];
    float top = v00 + (v10 - v00) * wy;
    float bot = v01 + (v11 - v01) * wy;
    dst[idx] = top + (bot - top) * wx;
}

// ---------------- grid_sample (border) of temporal_kv ----------------
// second resize 256->256 is exact identity (align-corners integer grid)
__global__ void warp_kernel(const float* __restrict__ temporal, const float* __restrict__ mv) {
    int idx = blockIdx.x * blockDim.x + threadIdx.x;
    if (idx >= NB * HW) return;
    int n = idx / HW; int hw = idx % HW;
    int h = hw >> 8; int w = hw & 255;
    float xsv = -1.f + 2.f * w / (float)(WW - 1);
    float ysv = -1.f + 2.f * h / (float)(HH - 1);
    float gx = mv[(size_t)(n*2 + 0) * HW + hw] * (2.f / WW) + xsv;
    float gy = ysv - mv[(size_t)(n*2 + 1) * HW + hw] * (2.f / HH);
    float ix = fminf(fmaxf((gx + 1.f) * 0.5f * (WW - 1), 0.f), (float)(WW - 1));
    float iy = fminf(fmaxf((gy + 1.f) * 0.5f * (HH - 1), 0.f), (float)(HH - 1));
    int x0 = (int)floorf(ix), y0 = (int)floorf(iy);
    float wx = ix - x0, wy = iy - y0;
    int x1 = min(x0 + 1, WW - 1), y1 = min(y0 + 1, HH - 1);
    const float* base = temporal + (size_t)n * 128 * HW;
    #pragma unroll 4
    for (int c = 0; c < 128; c++) {
        const float* p = base + (size_t)c * HW;
        float v00 = p[y0*WW + x0], v01 = p[y0*WW + x1];
        float v10 = p[y1*WW + x0], v11 = p[y1*WW + x1];
        g_WARP[(size_t)(n*128 + c) * HW + hw] =
            v00*(1-wy)*(1-wx) + v01*(1-wy)*wx + v10*wy*(1-wx) + v11*wy*wx;
    }
}

// ---------------- copy ds_latent tail channels into g_DSS ----------------
__global__ void dscopy_kernel(const float* __restrict__ dsl) {
    int idx = blockIdx.x * blockDim.x + threadIdx.x;
    if (idx >= NB * 3 * DHW) return;
    int n = idx / (3 * DHW); int rem = idx % (3 * DHW);
    int c = rem / DHW; int i = rem % DHW;
    g_DSS[(size_t)(n*128 + 125 + c) * DHW + i] = dsl[(size_t)(n*96 + 93 + c) * DHW + i];
}

// ---------------- windowed attention (flash-style, fused tokenize+LN+fold) ----------------
// block = one 8x8 window; 64 Q rows x 384 KV rows processed in 6 chunks of 64
__global__ __launch_bounds__(256)
void attn_kernel(const float* __restrict__ radiance,
                 const float* __restrict__ qg, const float* __restrict__ qb,
                 const float* __restrict__ kg, const float* __restrict__ kb,
                 const float* __restrict__ vg, const float* __restrict__ vb) {
    extern __shared__ float sm[];
    float* Qs = sm;            // 64 x 65
    float* Ks = Qs + 64*65;
    float* Vs = Ks + 64*65;
    float* Ss = Vs + 64*65;
    int tid = threadIdx.x;
    int n = blockIdx.x >> 10;
    int l = blockIdx.x & 1023;
    int wh = l >> 5, ww = l & 31;
    int by = wh * 8, bx = ww * 8;
    int q = tid >> 2, r4 = tid & 3;

    // load Q (su_emb ch 0..63, this window)
    for (int idx = tid; idx < 4096; idx += 256) {
        int r = idx & 63, c = idx >> 6;
        int y = by + (r >> 3), x = bx + (r & 7);
        Qs[r*65 + c] = g_SU[(size_t)(n*189 + c) * HW + y*256 + x];
    }
    __syncthreads();
    if (tid < 64) {
        float mu = 0.f;
        for (int c = 0; c < 64; c++) mu += Qs[tid*65 + c];
        mu *= (1.f/64.f);
        float var = 0.f;
        for (int c = 0; c < 64; c++) { float d = Qs[tid*65 + c] - mu; var += d*d; }
        var *= (1.f/64.f);
        float rs = rsqrtf(var + 1e-5f);
        for (int c = 0; c < 64; c++)
            Qs[tid*65 + c] = ((Qs[tid*65 + c] - mu) * rs * qg[c] + qb[c]) * 0.125f;
    }
    __syncthreads();

    float acc[16];
    #pragma unroll
    for (int i = 0; i < 16; i++) acc[i] = 0.f;
    float mrow = -1e30f, lrow = 0.f;

    for (int ci = 0; ci < 6; ci++) {
        // load K/V chunk (64 rows x 64 ch each)
        for (int idx = tid; idx < 4096; idx += 256) {
            int r = idx & 63, c = idx >> 6;
            float kvv, vvv;
            if (ci < 4) {              // main kv: 16x16 window with halo 4, zero pad
                int ky = ci*4 + (r >> 4), kx = r & 15;
                int y = by - 4 + ky, x = bx - 4 + kx;
                if (y >= 0 && y < 256 && x >= 0 && x < 256) {
                    int off = y*256 + x;
                    kvv = g_SU[(size_t)(n*189 + 64 + c) * HW + off];
                    vvv = (c < 61) ? g_SU[(size_t)(n*189 + 128 + c) * HW + off]
                                   : radiance[(size_t)(n*3 + c - 61) * HW + off];
                } else { kvv = 0.f; vvv = 0.f; }
            } else {                   // temporal (ci==4) / ds (ci==5): 8x8 window
                int y = by + (r >> 3), x = bx + (r & 7);
                int off = y*256 + x;
                const float* src = (ci == 4) ? g_WARP : g_DSE;
                kvv = src[(size_t)(n*128 + c) * HW + off];
                vvv = src[(size_t)(n*128 + 64 + c) * HW + off];
            }
            Ks[r*65 + c] = kvv; Vs[r*65 + c] = vvv;
        }
        __syncthreads();
        // LN rows: threads 0..63 -> K, 64..127 -> V (first 61 ch)
        if (tid < 64) {
            int r = tid;
            float mu = 0.f;
            for (int c = 0; c < 64; c++) mu += Ks[r*65 + c];
            mu *= (1.f/64.f);
            float var = 0.f;
            for (int c = 0; c < 64; c++) { float d = Ks[r*65 + c] - mu; var += d*d; }
            var *= (1.f/64.f);
            float rs = rsqrtf(var + 1e-5f);
            for (int c = 0; c < 64; c++) Ks[r*65 + c] = (Ks[r*65 + c] - mu) * rs * kg[c] + kb[c];
        } else if (tid < 128) {
            int r = tid - 64;
            float mu = 0.f;
            for (int c = 0; c < 61; c++) mu += Vs[r*65 + c];
            mu *= (1.f/61.f);
            float var = 0.f;
            for (int c = 0; c < 61; c++) { float d = Vs[r*65 + c] - mu; var += d*d; }
            var *= (1.f/61.f);
            float rs = rsqrtf(var + 1e-5f);
            for (int c = 0; c < 61; c++) Vs[r*65 + c] = (Vs[r*65 + c] - mu) * rs * vg[c] + vb[c];
        }
        __syncthreads();

        // S = Qn Kn^T for this thread's 16 k columns
        float sv[16];
        #pragma unroll
        for (int j = 0; j < 16; j++) sv[j] = 0.f;
        #pragma unroll
        for (int cb = 0; cb < 4; cb++) {
            float qv[16];
            #pragma unroll
            for (int u = 0; u < 16; u++) qv[u] = Qs[q*65 + cb*16 + u];
            #pragma unroll
            for (int j = 0; j < 16; j++) {
                int k = r4*16 + j;
                float s = sv[j];
                #pragma unroll
                for (int u = 0; u < 16; u++) s += qv[u] * Ks[k*65 + cb*16 + u];
                sv[j] = s;
            }
        }
        // online softmax (4 lanes per q row)
        float mx = sv[0];
        #pragma unroll
        for (int j = 1; j < 16; j++) mx = fmaxf(mx, sv[j]);
        mx = fmaxf(mx, __shfl_xor_sync(0xffffffffu, mx, 1));
        mx = fmaxf(mx, __shfl_xor_sync(0xffffffffu, mx, 2));
        float mnew = fmaxf(mrow, mx);
        float corr = __expf(mrow - mnew);
        float lsum = 0.f;
        #pragma unroll
        for (int j = 0; j < 16; j++) {
            float p = __expf(sv[j] - mnew);
            Ss[q*65 + r4*16 + j] = p;
            lsum += p;
        }
        lsum += __shfl_xor_sync(0xffffffffu, lsum, 1);
        lsum += __shfl_xor_sync(0xffffffffu, lsum, 2);
        lrow = lrow * corr + lsum;
        mrow = mnew;
        #pragma unroll
        for (int i = 0; i < 16; i++) acc[i] *= corr;
        __syncthreads();
        // O += P V
        #pragma unroll 4
        for (int k = 0; k < 64; k++) {
            float p = Ss[q*65 + k];
            #pragma unroll
            for (int i = 0; i < 16; i++) acc[i] += p * Vs[k*65 + r4*16 + i];
        }
        __syncthreads();
    }
    float inv = 1.f / lrow;
    int y = by + (q >> 3), x = bx + (q & 7);
    #pragma unroll
    for (int i = 0; i < 16; i++) {
        int c = r4*16 + i;
        g_ATT[(size_t)(n*64 + c) * HW + y*256 + x] = acc[i] * inv;
    }
}

// ---------------- output assembly: temporal_out + decoded tail ----------------
__global__ void tail_kernel(float* __restrict__ out) {
    int idx = blockIdx.x * blockDim.x + threadIdx.x;
    const int T1 = NB * 128 * HW;
    const int T2 = NB * 3 * HW;
    if (idx < T1) {
        int n = idx / (128 * HW); int rem = idx % (128 * HW);
        int c = rem / HW; int hw = rem % HW;
        float v = (c < 125) ? g_SU[(size_t)(n*189 + 64 + c) * HW + hw]
                            : g_ATT[(size_t)(n*64 + 61 + (c - 125)) * HW + hw];
        out[(size_t)NB*64*HW + idx] = v;
    } else if (idx < T1 + T2) {
        int j = idx - T1;
        int n = j / (3 * HW); int rem = j % (3 * HW);
        int c = rem / HW; int hw = rem % HW;
        out[(size_t)(n*64 + 61 + c) * HW + hw] = g_ATT[(size_t)(n*64 + 61 + c) * HW + hw];
    }
}

// ---------------- host launcher ----------------
extern "C" void kernel_launch(void* const* d_in, const int* in_sizes, int n_in,
                              void* d_out, int out_size) {
    const float* radiance = (const float*)d_in[0];
    const float* skip     = (const float*)d_in[1];
    const float* dsl      = (const float*)d_in[2];
    const float* temporal = (const float*)d_in[3];
    const float* mv       = (const float*)d_in[4];
    const float* su_bn_g  = (const float*)d_in[5];
    const float* su_bn_b  = (const float*)d_in[6];
    const float* su_w     = (const float*)d_in[7];
    const float* su_b     = (const float*)d_in[8];
    const float* ds_bn_g  = (const float*)d_in[9];
    const float* ds_bn_b  = (const float*)d_in[10];
    const float* ds_w     = (const float*)d_in[11];
    const float* ds_b     = (const float*)d_in[12];
    const float* qln_g    = (const float*)d_in[13];
    const float* qln_b    = (const float*)d_in[14];
    const float* kln_g    = (const float*)d_in[15];
    const float* kln_b    = (const float*)d_in[16];
    const float* vln_g    = (const float*)d_in[17];
    const float* vln_b    = (const float*)d_in[18];
    const float* f1_g     = (const float*)d_in[19];
    const float* f1_b     = (const float*)d_in[20];
    const float* w1       = (const float*)d_in[21];
    const float* b1       = (const float*)d_in[22];
    const float* f2_g     = (const float*)d_in[23];
    const float* f2_b     = (const float*)d_in[24];
    const float* w2       = (const float*)d_in[25];
    const float* b2       = (const float*)d_in[26];
    float* out = (float*)d_out;

    float *dUS, *dSU, *dDSS, *dDSE, *dATT, *dH1;
    cudaGetSymbolAddress((void**)&dUS,  g_US);
    cudaGetSymbolAddress((void**)&dSU,  g_SU);
    cudaGetSymbolAddress((void**)&dDSS, g_DSS);
    cudaGetSymbolAddress((void**)&dDSE, g_DSE);
    cudaGetSymbolAddress((void**)&dATT, g_ATT);
    cudaGetSymbolAddress((void**)&dH1,  g_H1);

    const int ATTN_SMEM = 4*64*65*4;
    cudaFuncSetAttribute(attn_kernel, cudaFuncAttributeMaxDynamicSharedMemorySize, ATTN_SMEM);

    // 1. us = resize(ds_latent, 128->256)
    resize_kernel<<<(NB*96*HW + 255)/256, 256>>>(dsl, dUS, 96, 128, 128, 256, 256);
    // 2-3. su BN stats + conv1x1 -> su_emb (189 ch)
    bn_stats_kernel<<<192, 256>>>(skip, 96, dUS, 96, su_bn_g, su_bn_b, HW);
    conv1x1_kernel<<<dim3((NB*HW)/128, 3), 256>>>(skip, 96, dUS, 96, su_w, su_b, 189, HW, dSU, 189, 0);
    // 4. warped temporal kv (grid_sample; trailing resize is identity)
    warp_kernel<<<(NB*HW + 255)/256, 256>>>(temporal, mv);
    // 5-8. ds embedding: BN+conv at 128x128, append tail channels, resize to 256
    bn_stats_kernel<<<96, 256>>>(dsl, 96, (const float*)0, 0, ds_bn_g, ds_bn_b, DHW);
    conv1x1_kernel<<<dim3((NB*DHW)/128, 2), 256>>>(dsl, 96, (const float*)0, 0, ds_w, ds_b, 125, DHW, dDSS, 128, 0);
    dscopy_kernel<<<(NB*3*DHW + 255)/256, 256>>>(dsl);
    resize_kernel<<<(NB*128*HW + 255)/256, 256>>>(dDSS, dDSE, 128, 128, 128, 256, 256);
    // 9. attention (fused tokenize + LN + sdpa + fold)
    attn_kernel<<<NB*1024, 256, ATTN_SMEM>>>(radiance, qln_g, qln_b, kln_g, kln_b, vln_g, vln_b);
    // 10-13. FFN
    bn_stats_kernel<<<64, 256>>>(dATT, 64, (const float*)0, 0, f1_g, f1_b, HW);
    conv1x1_kernel<<<dim3((NB*HW)/128, 2), 256>>>(dATT, 64, (const float*)0, 0, w1, b1, 128, HW, dH1, 128, 1);
    bn_stats_kernel<<<128, 256>>>(dH1, 128, (const float*)0, 0, f2_g, f2_b, HW);
    conv1x1_kernel<<<dim3((NB*HW)/128, 1), 256>>>(dH1, 128, (const float*)0, 0, w2, b2, 61, HW, out, 64, 0);
    // 14. assemble temporal_out + decoded tail channels
    tail_kernel<<<(NB*128*HW + NB*3*HW + 255)/256, 256>>>(out);
}

// round 2
// speedup vs baseline: 1.7419x; 1.7419x over previous
#include <cuda_runtime.h>
#include <cuda_fp16.h>
#include <math.h>

#define NB 2
#define HH 256
#define WW 256
#define HW 65536
#define DHW 16384   // 128*128
#define PAD 72      // fp16 row stride for ldmatrix tiles

// ---------------- scratch (static device allocations) ----------------
__device__ float g_US [NB*96 *HW];   // resized ds_latent (2,96,256,256)
__device__ float g_SU [NB*189*HW];   // su_emb (2,189,256,256)
__device__ float g_WARP[NB*128*HW];  // warped temporal kv
__device__ float g_DSS[NB*128*DHW]; // ds embedding at half res (128 ch)
__device__ float g_DSE[NB*128*HW];   // ds embedding full res
__device__ float g_ATT[NB*64 *HW];   // folded attention output
__device__ float g_H1 [NB*128*HW];   // ffn hidden
__device__ float g_S[192];           // folded BN scale (reused per stage)
__device__ float g_T[192];           // folded BN shift

// ---------------- BN stats -> folded scale/shift ----------------
__global__ void bn_stats_kernel(const float* __restrict__ src0, int C0,
                                const float* __restrict__ src1, int C1,
                                const float* __restrict__ g, const float* __restrict__ b,
                                int hw) {
    int c = blockIdx.x;
    const float* base; int cs;
    if (c < C0) { base = src0 + (size_t)c * hw; cs = C0; }
    else        { base = src1 + (size_t)(c - C0) * hw; cs = C1; }
    float sum = 0.f, sq = 0.f;
    for (int n = 0; n < NB; n++) {
        const float* p = base + (size_t)n * cs * hw;
        for (int i = threadIdx.x; i < hw; i += blockDim.x) {
            float v = p[i]; sum += v; sq += v * v;
        }
    }
    __shared__ float ssum[256], ssq[256];
    ssum[threadIdx.x] = sum; ssq[threadIdx.x] = sq; __syncthreads();
    for (int o = 128; o > 0; o >>= 1) {
        if (threadIdx.x < o) { ssum[threadIdx.x] += ssum[threadIdx.x+o]; ssq[threadIdx.x] += ssq[threadIdx.x+o]; }
        __syncthreads();
    }
    if (threadIdx.x == 0) {
        float inv = 1.f / (float)(NB * hw);
        float m = ssum[0] * inv;
        float v = ssq[0] * inv - m * m;
        float s = g[c] * rsqrtf(v + 1e-5f);
        g_S[c] = s; g_T[c] = b[c] - m * s;
    }
}

// ---------------- fused BN + conv1x1 (tiled GEMM) ----------------
__global__ __launch_bounds__(256)
void conv1x1_kernel(const float* __restrict__ src0, int C0,
                    const float* __restrict__ src1, int C1,
                    const float* __restrict__ w, const float* __restrict__ bias,
                    int Cout, int hw, float* __restrict__ out, int outStride, int relu) {
    __shared__ float xs[32*128];
    __shared__ float ws[64*32];
    int Cin = C0 + C1;
    int tid = threadIdx.x;
    int lane = tid & 31;
    int obase = (tid >> 5) * 8;
    int p0 = blockIdx.x * 128;
    int n = p0 / hw, hw0 = p0 % hw;
    int ot = blockIdx.y;
    float acc[4][8];
    #pragma unroll
    for (int i = 0; i < 4; i++)
        #pragma unroll
        for (int j = 0; j < 8; j++) acc[i][j] = 0.f;

    for (int cc = 0; cc < Cin; cc += 32) {
        for (int idx = tid; idx < 32*128; idx += 256) {
            int cl = idx >> 7, pl = idx & 127;
            int c = cc + cl;
            const float* src = (c < C0) ? (src0 + (size_t)(n*C0 + c) * hw)
                                        : (src1 + (size_t)(n*C1 + (c - C0)) * hw);
            xs[cl*128 + pl] = src[hw0 + pl] * g_S[c] + g_T[c];
        }
        for (int idx = tid; idx < 64*32; idx += 256) {
            int ol = idx >> 5, cl = idx & 31;
            int o = ot*64 + ol;
            ws[ol*32 + cl] = (o < Cout) ? w[(size_t)o * Cin + cc + cl] : 0.f;
        }
        __syncthreads();
        #pragma unroll 4
        for (int cl = 0; cl < 32; cl++) {
            float xv[4];
            #pragma unroll
            for (int i = 0; i < 4; i++) xv[i] = xs[cl*128 + lane + 32*i];
            #pragma unroll
            for (int j = 0; j < 8; j++) {
                float wv = ws[(obase + j)*32 + cl];
                #pragma unroll
                for (int i = 0; i < 4; i++) acc[i][j] += xv[i] * wv;
            }
        }
        __syncthreads();
    }
    #pragma unroll
    for (int j = 0; j < 8; j++) {
        int o = ot*64 + obase + j;
        if (o >= Cout) continue;
        float bv = bias[o];
        #pragma unroll
        for (int i = 0; i < 4; i++) {
            float v = acc[i][j] + bv;
            if (relu) v = fmaxf(v, 0.f);
            out[(size_t)(n*outStride + o) * hw + hw0 + lane + 32*i] = v;
        }
    }
}

// ---------------- align-corners bilinear resize ----------------
__global__ void resize_kernel(const float* __restrict__ src, float* __restrict__ dst,
                              int C, int Hs, int Ws, int Hd, int Wd) {
    int idx = blockIdx.x * blockDim.x + threadIdx.x;
    int total = NB * C * Hd * Wd;
    if (idx >= total) return;
    int x = idx % Wd; int y = (idx / Wd) % Hd; int nc = idx / (Wd * Hd);
    float sy = y * (float)(Hs - 1) / (float)(Hd - 1);
    float sx = x * (float)(Ws - 1) / (float)(Wd - 1);
    int y0 = (int)floorf(sy); int x0 = (int)floorf(sx);
    float wy = sy - y0, wx = sx - x0;
    int y1 = min(y0 + 1, Hs - 1), x1 = min(x0 + 1, Ws - 1);
    const float* p = src + (size_t)nc * Hs * Ws;
    float v00 = p[y0*Ws + x0], v01 = p[y0*Ws + x1];
    float v10 = p[y1*Ws + x0], v11 = p[y1*Ws + x1];
    float top = v00 + (v10 - v00) * wy;
    float bot = v01 + (v11 - v01) * wy;
    dst[idx] = top + (bot - top) * wx;
}

// ---------------- grid_sample (border) of temporal_kv ----------------
__global__ void warp_kernel(const float* __restrict__ temporal, const float* __restrict__ mv) {
    int idx = blockIdx.x * blockDim.x + threadIdx.x;
    if (idx >= NB * HW) return;
    int n = idx / HW; int hw = idx % HW;
    int h = hw >> 8; int w = hw & 255;
    float xsv = -1.f + 2.f * w / (float)(WW - 1);
    float ysv = -1.f + 2.f * h / (float)(HH - 1);
    float gx = mv[(size_t)(n*2 + 0) * HW + hw] * (2.f / WW) + xsv;
    float gy = ysv - mv[(size_t)(n*2 + 1) * HW + hw] * (2.f / HH);
    float ix = fminf(fmaxf((gx + 1.f) * 0.5f * (WW - 1), 0.f), (float)(WW - 1));
    float iy = fminf(fmaxf((gy + 1.f) * 0.5f * (HH - 1), 0.f), (float)(HH - 1));
    int x0 = (int)floorf(ix), y0 = (int)floorf(iy);
    float wx = ix - x0, wy = iy - y0;
    int x1 = min(x0 + 1, WW - 1), y1 = min(y0 + 1, HH - 1);
    const float* base = temporal + (size_t)n * 128 * HW;
    #pragma unroll 4
    for (int c = 0; c < 128; c++) {
        const float* p = base + (size_t)c * HW;
        float v00 = p[y0*WW + x0], v01 = p[y0*WW + x1];
        float v10 = p[y1*WW + x0], v11 = p[y1*WW + x1];
        g_WARP[(size_t)(n*128 + c) * HW + hw] =
            v00*(1-wy)*(1-wx) + v01*(1-wy)*wx + v10*wy*(1-wx) + v11*wy*wx;
    }
}

// ---------------- copy ds_latent tail channels into g_DSS ----------------
__global__ void dscopy_kernel(const float* __restrict__ dsl) {
    int idx = blockIdx.x * blockDim.x + threadIdx.x;
    if (idx >= NB * 3 * DHW) return;
    int n = idx / (3 * DHW); int rem = idx % (3 * DHW);
    int c = rem / DHW; int i = rem % DHW;
    g_DSS[(size_t)(n*128 + 125 + c) * DHW + i] = dsl[(size_t)(n*96 + 93 + c) * DHW + i];
}

// ---------------- mma helpers ----------------
__device__ __forceinline__ void ldm4(unsigned& r0, unsigned& r1, unsigned& r2, unsigned& r3,
                                     const __half* p) {
    unsigned a = (unsigned)__cvta_generic_to_shared(p);
    asm volatile("ldmatrix.sync.aligned.m8n8.x4.shared.b16 {%0,%1,%2,%3}, [%4];"
                 : "=r"(r0), "=r"(r1), "=r"(r2), "=r"(r3) : "r"(a));
}
__device__ __forceinline__ void ldm4t(unsigned& r0, unsigned& r1, unsigned& r2, unsigned& r3,
                                      const __half* p) {
    unsigned a = (unsigned)__cvta_generic_to_shared(p);
    asm volatile("ldmatrix.sync.aligned.m8n8.x4.trans.shared.b16 {%0,%1,%2,%3}, [%4];"
                 : "=r"(r0), "=r"(r1), "=r"(r2), "=r"(r3) : "r"(a));
}
__device__ __forceinline__ void mma16816(float* d, unsigned a0, unsigned a1, unsigned a2, unsigned a3,
                                         unsigned b0, unsigned b1) {
    asm volatile("mma.sync.aligned.m16n8k16.row.col.f32.f16.f16.f32 "
                 "{%0,%1,%2,%3}, {%4,%5,%6,%7}, {%8,%9}, {%0,%1,%2,%3};"
                 : "+f"(d[0]), "+f"(d[1]), "+f"(d[2]), "+f"(d[3])
                 : "r"(a0), "r"(a1), "r"(a2), "r"(a3), "r"(b0), "r"(b1));
}
__device__ __forceinline__ unsigned packh2(float lo, float hi) {
    __half2 h = __floats2half2_rn(lo, hi);
    return *(unsigned*)&h;
}

// ---------------- windowed attention: tensor-core fp16 QK/PV, fp32 LN+softmax ----------------
// block = one 8x8 window, 128 threads (4 warps), warp w owns q rows 16w..16w+15
__global__ __launch_bounds__(128)
void attn_kernel(const float* __restrict__ radiance,
                 const float* __restrict__ qg, const float* __restrict__ qb,
                 const float* __restrict__ kg, const float* __restrict__ kb,
                 const float* __restrict__ vg, const float* __restrict__ vb) {
    extern __shared__ char smraw[];
    __half* Qh = (__half*)smraw;           // 64 x PAD
    __half* Kh = Qh + 64*PAD;
    __half* Vh = Kh + 64*PAD;
    float* Raw0 = (float*)(Vh + 64*PAD);   // 64 x 65
    float* Raw1 = Raw0 + 64*65;

    int tid = threadIdx.x;
    int lane = tid & 31;
    int w = tid >> 5;
    int n = blockIdx.x >> 10;
    int l = blockIdx.x & 1023;
    int by = (l >> 5) * 8, bx = (l & 31) * 8;

    // ---- load + LN Q ----
    for (int idx = tid; idx < 4096; idx += 128) {
        int r = idx & 63, c = idx >> 6;
        int y = by + (r >> 3), x = bx + (r & 7);
        Raw0[r*65 + c] = g_SU[(size_t)(n*189 + c) * HW + y*256 + x];
    }
    __syncthreads();
    if (tid < 64) {
        const float* row = Raw0 + tid*65;
        float mu = 0.f;
        #pragma unroll 8
        for (int c = 0; c < 64; c++) mu += row[c];
        mu *= (1.f/64.f);
        float var = 0.f;
        #pragma unroll 8
        for (int c = 0; c < 64; c++) { float d = row[c] - mu; var += d*d; }
        float rs = rsqrtf(var * (1.f/64.f) + 1e-5f);
        #pragma unroll 8
        for (int c = 0; c < 64; c++)
            Qh[tid*PAD + c] = __float2half_rn(((row[c] - mu) * rs * qg[c] + qb[c]) * 0.125f);
    }
    __syncthreads();

    // A-fragments of Q for this warp (loaded once)
    unsigned qa[4][4];
    {
        int q0 = w * 16;
        #pragma unroll
        for (int kk = 0; kk < 4; kk++) {
            const __half* p = Qh + (q0 + (lane & 15))*PAD + kk*16 + ((lane >> 4) << 3);
            ldm4(qa[kk][0], qa[kk][1], qa[kk][2], qa[kk][3], p);
        }
    }

    float o[8][4];
    #pragma unroll
    for (int t = 0; t < 8; t++)
        #pragma unroll
        for (int j = 0; j < 4; j++) o[t][j] = 0.f;
    float m0 = -1e30f, m1 = -1e30f, l0 = 0.f, l1 = 0.f;

    for (int ci = 0; ci < 6; ci++) {
        // ---- gather K/V chunk ----
        for (int idx = tid; idx < 4096; idx += 128) {
            int r = idx & 63, c = idx >> 6;
            float kvv, vvv;
            if (ci < 4) {
                int ky = ci*4 + (r >> 4), kx = r & 15;
                int y = by - 4 + ky, x = bx - 4 + kx;
                if (y >= 0 && y < 256 && x >= 0 && x < 256) {
                    int off = y*256 + x;
                    kvv = g_SU[(size_t)(n*189 + 64 + c) * HW + off];
                    vvv = (c < 61) ? g_SU[(size_t)(n*189 + 128 + c) * HW + off]
                                   : radiance[(size_t)(n*3 + c - 61) * HW + off];
                } else { kvv = 0.f; vvv = 0.f; }
            } else {
                int y = by + (r >> 3), x = bx + (r & 7);
                int off = y*256 + x;
                const float* src = (ci == 4) ? g_WARP : g_DSE;
                kvv = src[(size_t)(n*128 + c) * HW + off];
                vvv = src[(size_t)(n*128 + 64 + c) * HW + off];
            }
            Raw0[r*65 + c] = kvv; Raw1[r*65 + c] = vvv;
        }
        __syncthreads();
        // ---- LN rows -> fp16 tiles ----
        if (tid < 64) {
            const float* row = Raw0 + tid*65;
            float mu = 0.f;
            #pragma unroll 8
            for (int c = 0; c < 64; c++) mu += row[c];
            mu *= (1.f/64.f);
            float var = 0.f;
            #pragma unroll 8
            for (int c = 0; c < 64; c++) { float d = row[c] - mu; var += d*d; }
            float rs = rsqrtf(var * (1.f/64.f) + 1e-5f);
            #pragma unroll 8
            for (int c = 0; c < 64; c++)
                Kh[tid*PAD + c] = __float2half_rn((row[c] - mu) * rs * kg[c] + kb[c]);
        } else {
            int r = tid - 64;
            const float* row = Raw1 + r*65;
            float mu = 0.f;
            for (int c = 0; c < 61; c++) mu += row[c];
            mu *= (1.f/61.f);
            float var = 0.f;
            for (int c = 0; c < 61; c++) { float d = row[c] - mu; var += d*d; }
            float rs = rsqrtf(var * (1.f/61.f) + 1e-5f);
            for (int c = 0; c < 61; c++)
                Vh[r*PAD + c] = __float2half_rn((row[c] - mu) * rs * vg[c] + vb[c]);
            for (int c = 61; c < 64; c++)
                Vh[r*PAD + c] = __float2half_rn(row[c]);
        }
        __syncthreads();

        // ---- S = Q K^T (64x64 per warp: 16 rows x 64 cols) ----
        float s[8][4];
        #pragma unroll
        for (int t = 0; t < 8; t++)
            #pragma unroll
            for (int j = 0; j < 4; j++) s[t][j] = 0.f;
        #pragma unroll
        for (int kk = 0; kk < 4; kk++) {
            #pragma unroll
            for (int np = 0; np < 4; np++) {
                unsigned b0, b1, b2, b3;
                // row = n0 + (lane&7) + 8*(lane>>4); col = k0 + 8*((lane>>3)&1)
                const __half* p = Kh + (np*16 + (lane & 7) + ((lane >> 4) << 3))*PAD
                                     + kk*16 + (((lane >> 3) & 1) << 3);
                ldm4(b0, b1, b2, b3, p);
                mma16816(s[2*np],   qa[kk][0], qa[kk][1], qa[kk][2], qa[kk][3], b0, b1);
                mma16816(s[2*np+1], qa[kk][0], qa[kk][1], qa[kk][2], qa[kk][3], b2, b3);
            }
        }

        // ---- online softmax (rows lane/4 and lane/4+8) ----
        float mx0 = -1e30f, mx1 = -1e30f;
        #pragma unroll
        for (int t = 0; t < 8; t++) {
            mx0 = fmaxf(mx0, fmaxf(s[t][0], s[t][1]));
            mx1 = fmaxf(mx1, fmaxf(s[t][2], s[t][3]));
        }
        mx0 = fmaxf(mx0, __shfl_xor_sync(0xffffffffu, mx0, 1));
        mx0 = fmaxf(mx0, __shfl_xor_sync(0xffffffffu, mx0, 2));
        mx1 = fmaxf(mx1, __shfl_xor_sync(0xffffffffu, mx1, 1));
        mx1 = fmaxf(mx1, __shfl_xor_sync(0xffffffffu, mx1, 2));
        float mn0 = fmaxf(m0, mx0), mn1 = fmaxf(m1, mx1);
        float corr0 = __expf(m0 - mn0), corr1 = __expf(m1 - mn1);
        m0 = mn0; m1 = mn1;
        float sum0 = 0.f, sum1 = 0.f;
        #pragma unroll
        for (int t = 0; t < 8; t++) {
            s[t][0] = __expf(s[t][0] - m0); s[t][1] = __expf(s[t][1] - m0);
            s[t][2] = __expf(s[t][2] - m1); s[t][3] = __expf(s[t][3] - m1);
            sum0 += s[t][0] + s[t][1];
            sum1 += s[t][2] + s[t][3];
        }
        sum0 += __shfl_xor_sync(0xffffffffu, sum0, 1);
        sum0 += __shfl_xor_sync(0xffffffffu, sum0, 2);
        sum1 += __shfl_xor_sync(0xffffffffu, sum1, 1);
        sum1 += __shfl_xor_sync(0xffffffffu, sum1, 2);
        l0 = l0 * corr0 + sum0;
        l1 = l1 * corr1 + sum1;
        #pragma unroll
        for (int t = 0; t < 8; t++) {
            o[t][0] *= corr0; o[t][1] *= corr0;
            o[t][2] *= corr1; o[t][3] *= corr1;
        }

        // ---- P (fp16 in regs) x V ----
        #pragma unroll
        for (int jp = 0; jp < 4; jp++) {  // kv k-steps of 16
            unsigned a0 = packh2(s[2*jp][0],   s[2*jp][1]);
            unsigned a1 = packh2(s[2*jp][2],   s[2*jp][3]);
            unsigned a2 = packh2(s[2*jp+1][0], s[2*jp+1][1]);
            unsigned a3 = packh2(s[2*jp+1][2], s[2*jp+1][3]);
            #pragma unroll
            for (int np = 0; np < 4; np++) {
                unsigned b0, b1, b2, b3;
                // row = kv0 + (lane&7) + 8*((lane>>3)&1); col = c0 + 8*(lane>>4)
                const __half* p = Vh + (jp*16 + (lane & 7) + (((lane >> 3) & 1) << 3))*PAD
                                     + np*16 + ((lane >> 4) << 3);
                ldm4t(b0, b1, b2, b3, p);
                mma16816(o[2*np],   a0, a1, a2, a3, b0, b1);
                mma16816(o[2*np+1], a0, a1, a2, a3, b2, b3);
            }
        }
        __syncthreads();
    }

    // ---- normalize + fold-write ----
    float inv0 = 1.f / l0, inv1 = 1.f / l1;
    int r0 = w*16 + (lane >> 2);
    int r1 = r0 + 8;
    int y0 = by + (r0 >> 3), x0 = bx + (r0 & 7);
    int y1 = by + (r1 >> 3), x1 = bx + (r1 & 7);
    #pragma unroll
    for (int t = 0; t < 8; t++) {
        int c = t*8 + 2*(lane & 3);
        g_ATT[(size_t)(n*64 + c    ) * HW + y0*256 + x0] = o[t][0] * inv0;
        g_ATT[(size_t)(n*64 + c + 1) * HW + y0*256 + x0] = o[t][1] * inv0;
        g_ATT[(size_t)(n*64 + c    ) * HW + y1*256 + x1] = o[t][2] * inv1;
        g_ATT[(size_t)(n*64 + c + 1) * HW + y1*256 + x1] = o[t][3] * inv1;
    }
}

// ---------------- output assembly: temporal_out + decoded tail ----------------
__global__ void tail_kernel(float* __restrict__ out) {
    int idx = blockIdx.x * blockDim.x + threadIdx.x;
    const int T1 = NB * 128 * HW;
    const int T2 = NB * 3 * HW;
    if (idx < T1) {
        int n = idx / (128 * HW); int rem = idx % (128 * HW);
        int c = rem / HW; int hw = rem % HW;
        float v = (c < 125) ? g_SU[(size_t)(n*189 + 64 + c) * HW + hw]
                            : g_ATT[(size_t)(n*64 + 61 + (c - 125)) * HW + hw];
        out[(size_t)NB*64*HW + idx] = v;
    } else if (idx < T1 + T2) {
        int j = idx - T1;
        int n = j / (3 * HW); int rem = j % (3 * HW);
        int c = rem / HW; int hw = rem % HW;
        out[(size_t)(n*64 + 61 + c) * HW + hw] = g_ATT[(size_t)(n*64 + 61 + c) * HW + hw];
    }
}

// ---------------- host launcher ----------------
extern "C" void kernel_launch(void* const* d_in, const int* in_sizes, int n_in,
                              void* d_out, int out_size) {
    const float* radiance = (const float*)d_in[0];
    const float* skip     = (const float*)d_in[1];
    const float* dsl      = (const float*)d_in[2];
    const float* temporal = (const float*)d_in[3];
    const float* mv       = (const float*)d_in[4];
    const float* su_bn_g  = (const float*)d_in[5];
    const float* su_bn_b  = (const float*)d_in[6];
    const float* su_w     = (const float*)d_in[7];
    const float* su_b     = (const float*)d_in[8];
    const float* ds_bn_g  = (const float*)d_in[9];
    const float* ds_bn_b  = (const float*)d_in[10];
    const float* ds_w     = (const float*)d_in[11];
    const float* ds_b     = (const float*)d_in[12];
    const float* qln_g    = (const float*)d_in[13];
    const float* qln_b    = (const float*)d_in[14];
    const float* kln_g    = (const float*)d_in[15];
    const float* kln_b    = (const float*)d_in[16];
    const float* vln_g    = (const float*)d_in[17];
    const float* vln_b    = (const float*)d_in[18];
    const float* f1_g     = (const float*)d_in[19];
    const float* f1_b     = (const float*)d_in[20];
    const float* w1       = (const float*)d_in[21];
    const float* b1       = (const float*)d_in[22];
    const float* f2_g     = (const float*)d_in[23];
    const float* f2_b     = (const float*)d_in[24];
    const float* w2       = (const float*)d_in[25];
    const float* b2       = (const float*)d_in[26];
    float* out = (float*)d_out;

    float *dUS, *dSU, *dDSS, *dDSE, *dATT, *dH1;
    cudaGetSymbolAddress((void**)&dUS,  g_US);
    cudaGetSymbolAddress((void**)&dSU,  g_SU);
    cudaGetSymbolAddress((void**)&dDSS, g_DSS);
    cudaGetSymbolAddress((void**)&dDSE, g_DSE);
    cudaGetSymbolAddress((void**)&dATT, g_ATT);
    cudaGetSymbolAddress((void**)&dH1,  g_H1);

    const int ATTN_SMEM = 3*64*PAD*2 + 2*64*65*4;  // 60928 B
    cudaFuncSetAttribute(attn_kernel, cudaFuncAttributeMaxDynamicSharedMemorySize, ATTN_SMEM);

    // 1. us = resize(ds_latent, 128->256)
    resize_kernel<<<(NB*96*HW + 255)/256, 256>>>(dsl, dUS, 96, 128, 128, 256, 256);
    // 2-3. su BN stats + conv1x1 -> su_emb (189 ch)
    bn_stats_kernel<<<192, 256>>>(skip, 96, dUS, 96, su_bn_g, su_bn_b, HW);
    conv1x1_kernel<<<dim3((NB*HW)/128, 3), 256>>>(skip, 96, dUS, 96, su_w, su_b, 189, HW, dSU, 189, 0);
    // 4. warped temporal kv (grid_sample; trailing resize is identity)
    warp_kernel<<<(NB*HW + 255)/256, 256>>>(temporal, mv);
    // 5-8. ds embedding
    bn_stats_kernel<<<96, 256>>>(dsl, 96, (const float*)0, 0, ds_bn_g, ds_bn_b, DHW);
    conv1x1_kernel<<<dim3((NB*DHW)/128, 2), 256>>>(dsl, 96, (const float*)0, 0, ds_w, ds_b, 125, DHW, dDSS, 128, 0);
    dscopy_kernel<<<(NB*3*DHW + 255)/256, 256>>>(dsl);
    resize_kernel<<<(NB*128*HW + 255)/256, 256>>>(dDSS, dDSE, 128, 128, 128, 256, 256);
    // 9. attention (tensor-core)
    attn_kernel<<<NB*1024, 128, ATTN_SMEM>>>(radiance, qln_g, qln_b, kln_g, kln_b, vln_g, vln_b);
    // 10-13. FFN
    bn_stats_kernel<<<64, 256>>>(dATT, 64, (const float*)0, 0, f1_g, f1_b, HW);
    conv1x1_kernel<<<dim3((NB*HW)/128, 2), 256>>>(dATT, 64, (const float*)0, 0, w1, b1, 128, HW, dH1, 128, 1);
    bn_stats_kernel<<<128, 256>>>(dH1, 128, (const float*)0, 0, f2_g, f2_b, HW);
    conv1x1_kernel<<<dim3((NB*HW)/128, 1), 256>>>(dH1, 128, (const float*)0, 0, w2, b2, 61, HW, out, 64, 0);
    // 14. assemble temporal_out + decoded tail channels
    tail_kernel<<<(NB*128*HW + NB*3*HW + 255)/256, 256>>>(out);
}

// round 3
// speedup vs baseline: 3.2131x; 1.8446x over previous
#include <cuda_runtime.h>
#include <cuda_fp16.h>
#include <math.h>

#define NB 2
#define HH 256
#define WW 256
#define HW 65536
#define DHW 16384   // 128*128
#define PAD 72      // fp16 row stride for ldmatrix tiles
#define NSLAB 16

// ---------------- scratch (static device allocations) ----------------
__device__ float g_US [NB*96 *HW];   // resized ds_latent (2,96,256,256)
__device__ float g_SU [NB*189*HW];   // su_emb (2,189,256,256)
__device__ float g_WARP[NB*128*HW];  // warped temporal kv
__device__ float g_DSS[NB*128*DHW]; // ds embedding at half res (128 ch)
__device__ float g_DSE[NB*128*HW];   // ds embedding full res
__device__ float g_ATT[NB*64 *HW];   // folded attention output
__device__ float g_H1 [NB*128*HW];   // ffn hidden
__device__ float g_S[192];           // folded BN scale (reused per stage)
__device__ float g_T[192];           // folded BN shift
__device__ float g_PSUM[192*NSLAB];
__device__ float g_PSQ [192*NSLAB];

// ---------------- BN stats stage 1: per-(channel,slab) partial sums ----------------
__global__ void bn_stats1_kernel(const float* __restrict__ src0, int C0,
                                 const float* __restrict__ src1, int C1,
                                 int hw) {
    int c = blockIdx.x;
    int slab = blockIdx.y;
    const float* base; int cs;
    if (c < C0) { base = src0 + (size_t)c * hw; cs = C0; }
    else        { base = src1 + (size_t)(c - C0) * hw; cs = C1; }
    int sl = hw / NSLAB;            // elements per slab per image (mult of 4)
    float sum = 0.f, sq = 0.f;
    for (int n = 0; n < NB; n++) {
        const float4* p = (const float4*)(base + (size_t)n * cs * hw + (size_t)slab * sl);
        int nv = sl >> 2;
        for (int i = threadIdx.x; i < nv; i += blockDim.x) {
            float4 v = p[i];
            sum += v.x + v.y + v.z + v.w;
            sq  += v.x*v.x + v.y*v.y + v.z*v.z + v.w*v.w;
        }
    }
    __shared__ float ssum[256], ssq[256];
    ssum[threadIdx.x] = sum; ssq[threadIdx.x] = sq; __syncthreads();
    for (int o = 128; o > 0; o >>= 1) {
        if (threadIdx.x < o) { ssum[threadIdx.x] += ssum[threadIdx.x+o]; ssq[threadIdx.x] += ssq[threadIdx.x+o]; }
        __syncthreads();
    }
    if (threadIdx.x == 0) {
        g_PSUM[c*NSLAB + slab] = ssum[0];
        g_PSQ [c*NSLAB + slab] = ssq[0];
    }
}

// ---------------- BN stats stage 2: finalize folded scale/shift ----------------
__global__ void bn_stats2_kernel(const float* __restrict__ g, const float* __restrict__ b,
                                 int hw) {
    int c = blockIdx.x;
    if (threadIdx.x == 0) {
        float sum = 0.f, sq = 0.f;
        #pragma unroll
        for (int s = 0; s < NSLAB; s++) { sum += g_PSUM[c*NSLAB + s]; sq += g_PSQ[c*NSLAB + s]; }
        float inv = 1.f / (float)(NB * hw);
        float m = sum * inv;
        float v = sq * inv - m * m;
        float s = g[c] * rsqrtf(v + 1e-5f);
        g_S[c] = s; g_T[c] = b[c] - m * s;
    }
}

// ---------------- fused BN + conv1x1 (tiled GEMM, float4) ----------------
// tile: 256 pixels x 64 out-channels; 256 thr; thread = 8 px x 8 oc
__global__ __launch_bounds__(256)
void conv1x1_kernel(const float* __restrict__ src0, int C0,
                    const float* __restrict__ src1, int C1,
                    const float* __restrict__ w, const float* __restrict__ bias,
                    int Cout, int hw, float* __restrict__ out, int outStride, int relu) {
    __shared__ float4 xs4[32*64];   // 32 ch x 256 px
    __shared__ float  ws [64*32];   // 64 oc x 32 ch
    int Cin = C0 + C1;
    int tid = threadIdx.x;
    int lane = tid & 31;
    int obase = (tid >> 5) * 8;
    int p0 = blockIdx.x * 256;
    int n = p0 / hw, hw0 = p0 % hw;
    int ot = blockIdx.y;
    float acc[8][8];
    #pragma unroll
    for (int i = 0; i < 8; i++)
        #pragma unroll
        for (int j = 0; j < 8; j++) acc[i][j] = 0.f;

    for (int cc = 0; cc < Cin; cc += 32) {
        #pragma unroll
        for (int it = 0; it < 8; it++) {
            int idx = tid + it * 256;          // 0..2047
            int cl = idx >> 6, p4 = idx & 63;
            int c = cc + cl;
            const float* src = (c < C0) ? (src0 + (size_t)(n*C0 + c) * hw)
                                        : (src1 + (size_t)(n*C1 + (c - C0)) * hw);
            float4 v = *(const float4*)(src + hw0 + p4*4);
            float s = g_S[c], t = g_T[c];
            v.x = v.x*s + t; v.y = v.y*s + t; v.z = v.z*s + t; v.w = v.w*s + t;
            xs4[cl*64 + p4] = v;
        }
        #pragma unroll
        for (int it = 0; it < 8; it++) {
            int idx = tid + it * 256;          // 0..2047
            int ol = idx >> 5, cl = idx & 31;
            int o = ot*64 + ol;
            ws[ol*32 + cl] = (o < Cout) ? w[(size_t)o * Cin + cc + cl] : 0.f;
        }
        __syncthreads();
        #pragma unroll 2
        for (int cl = 0; cl < 32; cl++) {
            float4 a = xs4[cl*64 + lane];
            float4 bb = xs4[cl*64 + 32 + lane];
            float av[8] = {a.x, a.y, a.z, a.w, bb.x, bb.y, bb.z, bb.w};
            #pragma unroll
            for (int j = 0; j < 8; j++) {
                float wv = ws[(obase + j)*32 + cl];
                #pragma unroll
                for (int i = 0; i < 8; i++) acc[i][j] += av[i] * wv;
            }
        }
        __syncthreads();
    }
    #pragma unroll
    for (int j = 0; j < 8; j++) {
        int o = ot*64 + obase + j;
        if (o >= Cout) continue;
        float bv = bias[o];
        float4 r0, r1;
        r0.x = acc[0][j]+bv; r0.y = acc[1][j]+bv; r0.z = acc[2][j]+bv; r0.w = acc[3][j]+bv;
        r1.x = acc[4][j]+bv; r1.y = acc[5][j]+bv; r1.z = acc[6][j]+bv; r1.w = acc[7][j]+bv;
        if (relu) {
            r0.x = fmaxf(r0.x,0.f); r0.y = fmaxf(r0.y,0.f); r0.z = fmaxf(r0.z,0.f); r0.w = fmaxf(r0.w,0.f);
            r1.x = fmaxf(r1.x,0.f); r1.y = fmaxf(r1.y,0.f); r1.z = fmaxf(r1.z,0.f); r1.w = fmaxf(r1.w,0.f);
        }
        float* op = out + (size_t)(n*outStride + o) * hw + hw0;
        *(float4*)(op + lane*4)       = r0;
        *(float4*)(op + 128 + lane*4) = r1;
    }
}

// ---------------- align-corners bilinear resize ----------------
__global__ void resize_kernel(const float* __restrict__ src, float* __restrict__ dst,
                              int C, int Hs, int Ws, int Hd, int Wd) {
    int idx = blockIdx.x * blockDim.x + threadIdx.x;
    int total = NB * C * Hd * Wd;
    if (idx >= total) return;
    int x = idx % Wd; int y = (idx / Wd) % Hd; int nc = idx / (Wd * Hd);
    float sy = y * (float)(Hs - 1) / (float)(Hd - 1);
    float sx = x * (float)(Ws - 1) / (float)(Wd - 1);
    int y0 = (int)floorf(sy); int x0 = (int)floorf(sx);
    float wy = sy - y0, wx = sx - x0;
    int y1 = min(y0 + 1, Hs - 1), x1 = min(x0 + 1, Ws - 1);
    const float* p = src + (size_t)nc * Hs * Ws;
    float v00 = p[y0*Ws + x0], v01 = p[y0*Ws + x1];
    float v10 = p[y1*Ws + x0], v11 = p[y1*Ws + x1];
    float top = v00 + (v10 - v00) * wy;
    float bot = v01 + (v11 - v01) * wy;
    dst[idx] = top + (bot - top) * wx;
}

// ---------------- grid_sample (border) of temporal_kv; 16 channels per thread ----------------
__global__ void warp_kernel(const float* __restrict__ temporal, const float* __restrict__ mv) {
    int p = blockIdx.x * blockDim.x + threadIdx.x;
    if (p >= NB * HW) return;
    int chunk = blockIdx.y;             // 0..7, 16 channels each
    int n = p / HW; int hw = p % HW;
    int h = hw >> 8; int w = hw & 255;
    float xsv = -1.f + 2.f * w / (float)(WW - 1);
    float ysv = -1.f + 2.f * h / (float)(HH - 1);
    float gx = mv[(size_t)(n*2 + 0) * HW + hw] * (2.f / WW) + xsv;
    float gy = ysv - mv[(size_t)(n*2 + 1) * HW + hw] * (2.f / HH);
    float ix = fminf(fmaxf((gx + 1.f) * 0.5f * (WW - 1), 0.f), (float)(WW - 1));
    float iy = fminf(fmaxf((gy + 1.f) * 0.5f * (HH - 1), 0.f), (float)(HH - 1));
    int x0 = (int)floorf(ix), y0 = (int)floorf(iy);
    float wx = ix - x0, wy = iy - y0;
    int x1 = min(x0 + 1, WW - 1), y1 = min(y0 + 1, HH - 1);
    float w00 = (1.f-wy)*(1.f-wx), w01 = (1.f-wy)*wx, w10 = wy*(1.f-wx), w11 = wy*wx;
    int i00 = y0*WW + x0, i01 = y0*WW + x1, i10 = y1*WW + x0, i11 = y1*WW + x1;
    const float* base = temporal + (size_t)(n*128 + chunk*16) * HW;
    float* dst = &g_WARP[(size_t)(n*128 + chunk*16) * HW + hw];
    #pragma unroll 4
    for (int c = 0; c < 16; c++) {
        const float* pp = base + (size_t)c * HW;
        dst[(size_t)c * HW] = pp[i00]*w00 + pp[i01]*w01 + pp[i10]*w10 + pp[i11]*w11;
    }
}

// ---------------- copy ds_latent tail channels into g_DSS ----------------
__global__ void dscopy_kernel(const float* __restrict__ dsl) {
    int idx = blockIdx.x * blockDim.x + threadIdx.x;
    if (idx >= NB * 3 * DHW) return;
    int n = idx / (3 * DHW); int rem = idx % (3 * DHW);
    int c = rem / DHW; int i = rem % DHW;
    g_DSS[(size_t)(n*128 + 125 + c) * DHW + i] = dsl[(size_t)(n*96 + 93 + c) * DHW + i];
}

// ---------------- mma helpers ----------------
__device__ __forceinline__ void ldm4(unsigned& r0, unsigned& r1, unsigned& r2, unsigned& r3,
                                     const __half* p) {
    unsigned a = (unsigned)__cvta_generic_to_shared(p);
    asm volatile("ldmatrix.sync.aligned.m8n8.x4.shared.b16 {%0,%1,%2,%3}, [%4];"
                 : "=r"(r0), "=r"(r1), "=r"(r2), "=r"(r3) : "r"(a));
}
__device__ __forceinline__ void ldm4t(unsigned& r0, unsigned& r1, unsigned& r2, unsigned& r3,
                                      const __half* p) {
    unsigned a = (unsigned)__cvta_generic_to_shared(p);
    asm volatile("ldmatrix.sync.aligned.m8n8.x4.trans.shared.b16 {%0,%1,%2,%3}, [%4];"
                 : "=r"(r0), "=r"(r1), "=r"(r2), "=r"(r3) : "r"(a));
}
__device__ __forceinline__ void mma16816(float* d, unsigned a0, unsigned a1, unsigned a2, unsigned a3,
                                         unsigned b0, unsigned b1) {
    asm volatile("mma.sync.aligned.m16n8k16.row.col.f32.f16.f16.f32 "
                 "{%0,%1,%2,%3}, {%4,%5,%6,%7}, {%8,%9}, {%0,%1,%2,%3};"
                 : "+f"(d[0]), "+f"(d[1]), "+f"(d[2]), "+f"(d[3])
                 : "r"(a0), "r"(a1), "r"(a2), "r"(a3), "r"(b0), "r"(b1));
}
__device__ __forceinline__ unsigned packh2(float lo, float hi) {
    __half2 h = __floats2half2_rn(lo, hi);
    return *(unsigned*)&h;
}

// ---------------- windowed attention: tensor-core fp16 QK/PV, fp32 LN+softmax ----------------
__global__ __launch_bounds__(128)
void attn_kernel(const float* __restrict__ radiance,
                 const float* __restrict__ qg, const float* __restrict__ qb,
                 const float* __restrict__ kg, const float* __restrict__ kb,
                 const float* __restrict__ vg, const float* __restrict__ vb) {
    extern __shared__ char smraw[];
    __half* Qh = (__half*)smraw;           // 64 x PAD
    __half* Kh = Qh + 64*PAD;
    __half* Vh = Kh + 64*PAD;
    float* Raw0 = (float*)(Vh + 64*PAD);   // 64 x 65
    float* Raw1 = Raw0 + 64*65;

    int tid = threadIdx.x;
    int lane = tid & 31;
    int w = tid >> 5;
    int n = blockIdx.x >> 10;
    int l = blockIdx.x & 1023;
    int by = (l >> 5) * 8, bx = (l & 31) * 8;

    // ---- load + LN Q ----
    for (int idx = tid; idx < 4096; idx += 128) {
        int r = idx & 63, c = idx >> 6;
        int y = by + (r >> 3), x = bx + (r & 7);
        Raw0[r*65 + c] = g_SU[(size_t)(n*189 + c) * HW + y*256 + x];
    }
    __syncthreads();
    if (tid < 64) {
        const float* row = Raw0 + tid*65;
        float mu = 0.f;
        #pragma unroll 8
        for (int c = 0; c < 64; c++) mu += row[c];
        mu *= (1.f/64.f);
        float var = 0.f;
        #pragma unroll 8
        for (int c = 0; c < 64; c++) { float d = row[c] - mu; var += d*d; }
        float rs = rsqrtf(var * (1.f/64.f) + 1e-5f);
        #pragma unroll 8
        for (int c = 0; c < 64; c++)
            Qh[tid*PAD + c] = __float2half_rn(((row[c] - mu) * rs * qg[c] + qb[c]) * 0.125f);
    }
    __syncthreads();

    unsigned qa[4][4];
    {
        int q0 = w * 16;
        #pragma unroll
        for (int kk = 0; kk < 4; kk++) {
            const __half* p = Qh + (q0 + (lane & 15))*PAD + kk*16 + ((lane >> 4) << 3);
            ldm4(qa[kk][0], qa[kk][1], qa[kk][2], qa[kk][3], p);
        }
    }

    float o[8][4];
    #pragma unroll
    for (int t = 0; t < 8; t++)
        #pragma unroll
        for (int j = 0; j < 4; j++) o[t][j] = 0.f;
    float m0 = -1e30f, m1 = -1e30f, l0 = 0.f, l1 = 0.f;

    for (int ci = 0; ci < 6; ci++) {
        for (int idx = tid; idx < 4096; idx += 128) {
            int r = idx & 63, c = idx >> 6;
            float kvv, vvv;
            if (ci < 4) {
                int ky = ci*4 + (r >> 4), kx = r & 15;
                int y = by - 4 + ky, x = bx - 4 + kx;
                if (y >= 0 && y < 256 && x >= 0 && x < 256) {
                    int off = y*256 + x;
                    kvv = g_SU[(size_t)(n*189 + 64 + c) * HW + off];
                    vvv = (c < 61) ? g_SU[(size_t)(n*189 + 128 + c) * HW + off]
                                   : radiance[(size_t)(n*3 + c - 61) * HW + off];
                } else { kvv = 0.f; vvv = 0.f; }
            } else {
                int y = by + (r >> 3), x = bx + (r & 7);
                int off = y*256 + x;
                const float* src = (ci == 4) ? g_WARP : g_DSE;
                kvv = src[(size_t)(n*128 + c) * HW + off];
                vvv = src[(size_t)(n*128 + 64 + c) * HW + off];
            }
            Raw0[r*65 + c] = kvv; Raw1[r*65 + c] = vvv;
        }
        __syncthreads();
        if (tid < 64) {
            const float* row = Raw0 + tid*65;
            float mu = 0.f;
            #pragma unroll 8
            for (int c = 0; c < 64; c++) mu += row[c];
            mu *= (1.f/64.f);
            float var = 0.f;
            #pragma unroll 8
            for (int c = 0; c < 64; c++) { float d = row[c] - mu; var += d*d; }
            float rs = rsqrtf(var * (1.f/64.f) + 1e-5f);
            #pragma unroll 8
            for (int c = 0; c < 64; c++)
                Kh[tid*PAD + c] = __float2half_rn((row[c] - mu) * rs * kg[c] + kb[c]);
        } else {
            int r = tid - 64;
            const float* row = Raw1 + r*65;
            float mu = 0.f;
            for (int c = 0; c < 61; c++) mu += row[c];
            mu *= (1.f/61.f);
            float var = 0.f;
            for (int c = 0; c < 61; c++) { float d = row[c] - mu; var += d*d; }
            float rs = rsqrtf(var * (1.f/61.f) + 1e-5f);
            for (int c = 0; c < 61; c++)
                Vh[r*PAD + c] = __float2half_rn((row[c] - mu) * rs * vg[c] + vb[c]);
            for (int c = 61; c < 64; c++)
                Vh[r*PAD + c] = __float2half_rn(row[c]);
        }
        __syncthreads();

        float s[8][4];
        #pragma unroll
        for (int t = 0; t < 8; t++)
            #pragma unroll
            for (int j = 0; j < 4; j++) s[t][j] = 0.f;
        #pragma unroll
        for (int kk = 0; kk < 4; kk++) {
            #pragma unroll
            for (int np = 0; np < 4; np++) {
                unsigned b0, b1, b2, b3;
                const __half* p = Kh + (np*16 + (lane & 7) + ((lane >> 4) << 3))*PAD
                                     + kk*16 + (((lane >> 3) & 1) << 3);
                ldm4(b0, b1, b2, b3, p);
                mma16816(s[2*np],   qa[kk][0], qa[kk][1], qa[kk][2], qa[kk][3], b0, b1);
                mma16816(s[2*np+1], qa[kk][0], qa[kk][1], qa[kk][2], qa[kk][3], b2, b3);
            }
        }

        float mx0 = -1e30f, mx1 = -1e30f;
        #pragma unroll
        for (int t = 0; t < 8; t++) {
            mx0 = fmaxf(mx0, fmaxf(s[t][0], s[t][1]));
            mx1 = fmaxf(mx1, fmaxf(s[t][2], s[t][3]));
        }
        mx0 = fmaxf(mx0, __shfl_xor_sync(0xffffffffu, mx0, 1));
        mx0 = fmaxf(mx0, __shfl_xor_sync(0xffffffffu, mx0, 2));
        mx1 = fmaxf(mx1, __shfl_xor_sync(0xffffffffu, mx1, 1));
        mx1 = fmaxf(mx1, __shfl_xor_sync(0xffffffffu, mx1, 2));
        float mn0 = fmaxf(m0, mx0), mn1 = fmaxf(m1, mx1);
        float corr0 = __expf(m0 - mn0), corr1 = __expf(m1 - mn1);
        m0 = mn0; m1 = mn1;
        float sum0 = 0.f, sum1 = 0.f;
        #pragma unroll
        for (int t = 0; t < 8; t++) {
            s[t][0] = __expf(s[t][0] - m0); s[t][1] = __expf(s[t][1] - m0);
            s[t][2] = __expf(s[t][2] - m1); s[t][3] = __expf(s[t][3] - m1);
            sum0 += s[t][0] + s[t][1];
            sum1 += s[t][2] + s[t][3];
        }
        sum0 += __shfl_xor_sync(0xffffffffu, sum0, 1);
        sum0 += __shfl_xor_sync(0xffffffffu, sum0, 2);
        sum1 += __shfl_xor_sync(0xffffffffu, sum1, 1);
        sum1 += __shfl_xor_sync(0xffffffffu, sum1, 2);
        l0 = l0 * corr0 + sum0;
        l1 = l1 * corr1 + sum1;
        #pragma unroll
        for (int t = 0; t < 8; t++) {
            o[t][0] *= corr0; o[t][1] *= corr0;
            o[t][2] *= corr1; o[t][3] *= corr1;
        }

        #pragma unroll
        for (int jp = 0; jp < 4; jp++) {
            unsigned a0 = packh2(s[2*jp][0],   s[2*jp][1]);
            unsigned a1 = packh2(s[2*jp][2],   s[2*jp][3]);
            unsigned a2 = packh2(s[2*jp+1][0], s[2*jp+1][1]);
            unsigned a3 = packh2(s[2*jp+1][2], s[2*jp+1][3]);
            #pragma unroll
            for (int np = 0; np < 4; np++) {
                unsigned b0, b1, b2, b3;
                const __half* p = Vh + (jp*16 + (lane & 7) + (((lane >> 3) & 1) << 3))*PAD
                                     + np*16 + ((lane >> 4) << 3);
                ldm4t(b0, b1, b2, b3, p);
                mma16816(o[2*np],   a0, a1, a2, a3, b0, b1);
                mma16816(o[2*np+1], a0, a1, a2, a3, b2, b3);
            }
        }
        __syncthreads();
    }

    float inv0 = 1.f / l0, inv1 = 1.f / l1;
    int r0 = w*16 + (lane >> 2);
    int r1 = r0 + 8;
    int y0 = by + (r0 >> 3), x0 = bx + (r0 & 7);
    int y1 = by + (r1 >> 3), x1 = bx + (r1 & 7);
    #pragma unroll
    for (int t = 0; t < 8; t++) {
        int c = t*8 + 2*(lane & 3);
        g_ATT[(size_t)(n*64 + c    ) * HW + y0*256 + x0] = o[t][0] * inv0;
        g_ATT[(size_t)(n*64 + c + 1) * HW + y0*256 + x0] = o[t][1] * inv0;
        g_ATT[(size_t)(n*64 + c    ) * HW + y1*256 + x1] = o[t][2] * inv1;
        g_ATT[(size_t)(n*64 + c + 1) * HW + y1*256 + x1] = o[t][3] * inv1;
    }
}

// ---------------- output assembly: temporal_out + decoded tail (float4) ----------------
__global__ void tail_kernel(float* __restrict__ out) {
    int idx = blockIdx.x * blockDim.x + threadIdx.x;   // float4 index
    const int T1 = NB * 128 * HW / 4;
    const int T2 = NB * 3 * HW / 4;
    const int HW4 = HW / 4;
    if (idx < T1) {
        int n = idx / (128 * HW4); int rem = idx % (128 * HW4);
        int c = rem / HW4; int hw4 = rem % HW4;
        float4 v = (c < 125)
            ? *(const float4*)&g_SU[(size_t)(n*189 + 64 + c) * HW + hw4*4]
            : *(const float4*)&g_ATT[(size_t)(n*64 + 61 + (c - 125)) * HW + hw4*4];
        *(float4*)&out[(size_t)NB*64*HW + (size_t)idx*4] = v;
    } else if (idx < T1 + T2) {
        int j = idx - T1;
        int n = j / (3 * HW4); int rem = j % (3 * HW4);
        int c = rem / HW4; int hw4 = rem % HW4;
        *(float4*)&out[(size_t)(n*64 + 61 + c) * HW + hw4*4] =
            *(const float4*)&g_ATT[(size_t)(n*64 + 61 + c) * HW + hw4*4];
    }
}

// ---------------- host launcher ----------------
extern "C" void kernel_launch(void* const* d_in, const int* in_sizes, int n_in,
                              void* d_out, int out_size) {
    const float* radiance = (const float*)d_in[0];
    const float* skip     = (const float*)d_in[1];
    const float* dsl      = (const float*)d_in[2];
    const float* temporal = (const float*)d_in[3];
    const float* mv       = (const float*)d_in[4];
    const float* su_bn_g  = (const float*)d_in[5];
    const float* su_bn_b  = (const float*)d_in[6];
    const float* su_w     = (const float*)d_in[7];
    const float* su_b     = (const float*)d_in[8];
    const float* ds_bn_g  = (const float*)d_in[9];
    const float* ds_bn_b  = (const float*)d_in[10];
    const float* ds_w     = (const float*)d_in[11];
    const float* ds_b     = (const float*)d_in[12];
    const float* qln_g    = (const float*)d_in[13];
    const float* qln_b    = (const float*)d_in[14];
    const float* kln_g    = (const float*)d_in[15];
    const float* kln_b    = (const float*)d_in[16];
    const float* vln_g    = (const float*)d_in[17];
    const float* vln_b    = (const float*)d_in[18];
    const float* f1_g     = (const float*)d_in[19];
    const float* f1_b     = (const float*)d_in[20];
    const float* w1       = (const float*)d_in[21];
    const float* b1       = (const float*)d_in[22];
    const float* f2_g     = (const float*)d_in[23];
    const float* f2_b     = (const float*)d_in[24];
    const float* w2       = (const float*)d_in[25];
    const float* b2       = (const float*)d_in[26];
    float* out = (float*)d_out;

    float *dUS, *dSU, *dDSS, *dDSE, *dATT, *dH1;
    cudaGetSymbolAddress((void**)&dUS,  g_US);
    cudaGetSymbolAddress((void**)&dSU,  g_SU);
    cudaGetSymbolAddress((void**)&dDSS, g_DSS);
    cudaGetSymbolAddress((void**)&dDSE, g_DSE);
    cudaGetSymbolAddress((void**)&dATT, g_ATT);
    cudaGetSymbolAddress((void**)&dH1,  g_H1);

    const int ATTN_SMEM = 3*64*PAD*2 + 2*64*65*4;  // 60928 B
    cudaFuncSetAttribute(attn_kernel, cudaFuncAttributeMaxDynamicSharedMemorySize, ATTN_SMEM);

    // 1. us = resize(ds_latent, 128->256)
    resize_kernel<<<(NB*96*HW + 255)/256, 256>>>(dsl, dUS, 96, 128, 128, 256, 256);
    // 2-3. su BN stats + conv1x1 -> su_emb (189 ch)
    bn_stats1_kernel<<<dim3(192, NSLAB), 256>>>(skip, 96, dUS, 96, HW);
    bn_stats2_kernel<<<192, 32>>>(su_bn_g, su_bn_b, HW);
    conv1x1_kernel<<<dim3((NB*HW)/256, 3), 256>>>(skip, 96, dUS, 96, su_w, su_b, 189, HW, dSU, 189, 0);
    // 4. warped temporal kv (grid_sample; trailing resize is identity)
    warp_kernel<<<dim3((NB*HW + 255)/256, 8), 256>>>(temporal, mv);
    // 5-8. ds embedding
    bn_stats1_kernel<<<dim3(96, NSLAB), 256>>>(dsl, 96, (const float*)0, 0, DHW);
    bn_stats2_kernel<<<96, 32>>>(ds_bn_g, ds_bn_b, DHW);
    conv1x1_kernel<<<dim3((NB*DHW)/256, 2), 256>>>(dsl, 96, (const float*)0, 0, ds_w, ds_b, 125, DHW, dDSS, 128, 0);
    dscopy_kernel<<<(NB*3*DHW + 255)/256, 256>>>(dsl);
    resize_kernel<<<(NB*128*HW + 255)/256, 256>>>(dDSS, dDSE, 128, 128, 128, 256, 256);
    // 9. attention (tensor-core)
    attn_kernel<<<NB*1024, 128, ATTN_SMEM>>>(radiance, qln_g, qln_b, kln_g, kln_b, vln_g, vln_b);
    // 10-13. FFN
    bn_stats1_kernel<<<dim3(64, NSLAB), 256>>>(dATT, 64, (const float*)0, 0, HW);
    bn_stats2_kernel<<<64, 32>>>(f1_g, f1_b, HW);
    conv1x1_kernel<<<dim3((NB*HW)/256, 2), 256>>>(dATT, 64, (const float*)0, 0, w1, b1, 128, HW, dH1, 128, 1);
    bn_stats1_kernel<<<dim3(128, NSLAB), 256>>>(dH1, 128, (const float*)0, 0, HW);
    bn_stats2_kernel<<<128, 32>>>(f2_g, f2_b, HW);
    conv1x1_kernel<<<dim3((NB*HW)/256, 1), 256>>>(dH1, 128, (const float*)0, 0, w2, b2, 61, HW, out, 64, 0);
    // 14. assemble temporal_out + decoded tail channels
    tail_kernel<<<((NB*128*HW + NB*3*HW)/4 + 255)/256, 256>>>(out);
}

// round 7
// speedup vs baseline: 3.2421x; 1.0090x over previous
#include <cuda_runtime.h>
#include <cuda_fp16.h>
#include <math.h>

#define NB 2
#define HH 256
#define WW 256
#define HW 65536
#define DHW 16384   // 128*128
#define PAD 72      // fp16 row stride for ldmatrix tiles (attention)
#define NSLAB 16

// ---------------- scratch (static device allocations) ----------------
__device__ float g_US [NB*96 *HW];
__device__ float g_SU [NB*189*HW];
__device__ float g_WARP[NB*128*HW];
__device__ float g_DSS[NB*128*DHW];
__device__ float g_DSE[NB*128*HW];
__device__ float g_ATT[NB*64 *HW];
__device__ float g_H1 [NB*128*HW];
__device__ float g_S[192];
__device__ float g_T[192];
__device__ float g_PSUM[192*NSLAB];
__device__ float g_PSQ [192*NSLAB];

// ---------------- BN stats stage 1 ----------------
__global__ void bn_stats1_kernel(const float* __restrict__ src0, int C0,
                                 const float* __restrict__ src1, int C1,
                                 int hw) {
    int c = blockIdx.x;
    int slab = blockIdx.y;
    const float* base; int cs;
    if (c < C0) { base = src0 + (size_t)c * hw; cs = C0; }
    else        { base = src1 + (size_t)(c - C0) * hw; cs = C1; }
    int sl = hw / NSLAB;
    float sum = 0.f, sq = 0.f;
    for (int n = 0; n < NB; n++) {
        const float4* p = (const float4*)(base + (size_t)n * cs * hw + (size_t)slab * sl);
        int nv = sl >> 2;
        for (int i = threadIdx.x; i < nv; i += blockDim.x) {
            float4 v = p[i];
            sum += v.x + v.y + v.z + v.w;
            sq  += v.x*v.x + v.y*v.y + v.z*v.z + v.w*v.w;
        }
    }
    __shared__ float ssum[256], ssq[256];
    ssum[threadIdx.x] = sum; ssq[threadIdx.x] = sq; __syncthreads();
    for (int o = 128; o > 0; o >>= 1) {
        if (threadIdx.x < o) { ssum[threadIdx.x] += ssum[threadIdx.x+o]; ssq[threadIdx.x] += ssq[threadIdx.x+o]; }
        __syncthreads();
    }
    if (threadIdx.x == 0) {
        g_PSUM[c*NSLAB + slab] = ssum[0];
        g_PSQ [c*NSLAB + slab] = ssq[0];
    }
}

// ---------------- BN stats stage 2 ----------------
__global__ void bn_stats2_kernel(const float* __restrict__ g, const float* __restrict__ b,
                                 int hw) {
    int c = blockIdx.x;
    if (threadIdx.x == 0) {
        float sum = 0.f, sq = 0.f;
        #pragma unroll
        for (int s = 0; s < NSLAB; s++) { sum += g_PSUM[c*NSLAB + s]; sq += g_PSQ[c*NSLAB + s]; }
        float inv = 1.f / (float)(NB * hw);
        float m = sum * inv;
        float v = sq * inv - m * m;
        float s = g[c] * rsqrtf(v + 1e-5f);
        g_S[c] = s; g_T[c] = b[c] - m * s;
    }
}

// ---------------- fused BN + conv1x1 (tiled GEMM, float4) — proven R3 version ----------------
// tile: 256 pixels x 64 out-channels; 256 thr; thread = 8 px x 8 oc
// mirror: optional second destination (128-ch stride) receiving channels oc>=64 at (oc-64)
__global__ __launch_bounds__(256)
void conv1x1_kernel(const float* __restrict__ src0, int C0,
                    const float* __restrict__ src1, int C1,
                    const float* __restrict__ w, const float* __restrict__ bias,
                    int Cout, int hw, float* __restrict__ out, int outStride, int relu,
                    float* __restrict__ mirror) {
    __shared__ float4 xs4[32*64];   // 32 ch x 256 px
    __shared__ float  ws [64*32];   // 64 oc x 32 ch
    int Cin = C0 + C1;
    int tid = threadIdx.x;
    int lane = tid & 31;
    int obase = (tid >> 5) * 8;
    int p0 = blockIdx.x * 256;
    int n = p0 / hw, hw0 = p0 % hw;
    int ot = blockIdx.y;
    float acc[8][8];
    #pragma unroll
    for (int i = 0; i < 8; i++)
        #pragma unroll
        for (int j = 0; j < 8; j++) acc[i][j] = 0.f;

    for (int cc = 0; cc < Cin; cc += 32) {
        #pragma unroll
        for (int it = 0; it < 8; it++) {
            int idx = tid + it * 256;          // 0..2047
            int cl = idx >> 6, p4 = idx & 63;
            int c = cc + cl;
            const float* src = (c < C0) ? (src0 + (size_t)(n*C0 + c) * hw)
                                        : (src1 + (size_t)(n*C1 + (c - C0)) * hw);
            float4 v = *(const float4*)(src + hw0 + p4*4);
            float s = g_S[c], t = g_T[c];
            v.x = v.x*s + t; v.y = v.y*s + t; v.z = v.z*s + t; v.w = v.w*s + t;
            xs4[cl*64 + p4] = v;
        }
        #pragma unroll
        for (int it = 0; it < 8; it++) {
            int idx = tid + it * 256;          // 0..2047
            int ol = idx >> 5, cl = idx & 31;
            int o = ot*64 + ol;
            ws[ol*32 + cl] = (o < Cout) ? w[(size_t)o * Cin + cc + cl] : 0.f;
        }
        __syncthreads();
        #pragma unroll 2
        for (int cl = 0; cl < 32; cl++) {
            float4 a = xs4[cl*64 + lane];
            float4 bb = xs4[cl*64 + 32 + lane];
            float av[8] = {a.x, a.y, a.z, a.w, bb.x, bb.y, bb.z, bb.w};
            #pragma unroll
            for (int j = 0; j < 8; j++) {
                float wv = ws[(obase + j)*32 + cl];
                #pragma unroll
                for (int i = 0; i < 8; i++) acc[i][j] += av[i] * wv;
            }
        }
        __syncthreads();
    }
    #pragma unroll
    for (int j = 0; j < 8; j++) {
        int o = ot*64 + obase + j;
        if (o >= Cout) continue;
        float bv = bias[o];
        float4 r0, r1;
        r0.x = acc[0][j]+bv; r0.y = acc[1][j]+bv; r0.z = acc[2][j]+bv; r0.w = acc[3][j]+bv;
        r1.x = acc[4][j]+bv; r1.y = acc[5][j]+bv; r1.z = acc[6][j]+bv; r1.w = acc[7][j]+bv;
        if (relu) {
            r0.x = fmaxf(r0.x,0.f); r0.y = fmaxf(r0.y,0.f); r0.z = fmaxf(r0.z,0.f); r0.w = fmaxf(r0.w,0.f);
            r1.x = fmaxf(r1.x,0.f); r1.y = fmaxf(r1.y,0.f); r1.z = fmaxf(r1.z,0.f); r1.w = fmaxf(r1.w,0.f);
        }
        float* op = out + (size_t)(n*outStride + o) * hw + hw0;
        *(float4*)(op + lane*4)       = r0;
        *(float4*)(op + 128 + lane*4) = r1;
        if (mirror != 0 && o >= 64) {
            float* mp = mirror + (size_t)(n*128 + (o - 64)) * hw + hw0;
            *(float4*)(mp + lane*4)       = r0;
            *(float4*)(mp + 128 + lane*4) = r1;
        }
    }
}

// ---------------- align-corners bilinear resize ----------------
__global__ void resize_kernel(const float* __restrict__ src, float* __restrict__ dst,
                              int C, int Hs, int Ws, int Hd, int Wd) {
    int idx = blockIdx.x * blockDim.x + threadIdx.x;
    int total = NB * C * Hd * Wd;
    if (idx >= total) return;
    int x = idx % Wd; int y = (idx / Wd) % Hd; int nc = idx / (Wd * Hd);
    float sy = y * (float)(Hs - 1) / (float)(Hd - 1);
    float sx = x * (float)(Ws - 1) / (float)(Wd - 1);
    int y0 = (int)floorf(sy); int x0 = (int)floorf(sx);
    float wy = sy - y0, wx = sx - x0;
    int y1 = min(y0 + 1, Hs - 1), x1 = min(x0 + 1, Ws - 1);
    const float* p = src + (size_t)nc * Hs * Ws;
    float v00 = p[y0*Ws + x0], v01 = p[y0*Ws + x1];
    float v10 = p[y1*Ws + x0], v11 = p[y1*Ws + x1];
    float top = v00 + (v10 - v00) * wy;
    float bot = v01 + (v11 - v01) * wy;
    dst[idx] = top + (bot - top) * wx;
}

// ---------------- grid_sample (border) of temporal_kv; 8 channels per thread ----------------
__global__ void warp_kernel(const float* __restrict__ temporal, const float* __restrict__ mv) {
    int p = blockIdx.x * blockDim.x + threadIdx.x;
    if (p >= NB * HW) return;
    int chunk = blockIdx.y;             // 0..15, 8 channels each
    int n = p / HW; int hw = p % HW;
    int h = hw >> 8; int w = hw & 255;
    float xsv = -1.f + 2.f * w / (float)(WW - 1);
    float ysv = -1.f + 2.f * h / (float)(HH - 1);
    float gx = mv[(size_t)(n*2 + 0) * HW + hw] * (2.f / WW) + xsv;
    float gy = ysv - mv[(size_t)(n*2 + 1) * HW + hw] * (2.f / HH);
    float ix = fminf(fmaxf((gx + 1.f) * 0.5f * (WW - 1), 0.f), (float)(WW - 1));
    float iy = fminf(fmaxf((gy + 1.f) * 0.5f * (HH - 1), 0.f), (float)(HH - 1));
    int x0 = (int)floorf(ix), y0 = (int)floorf(iy);
    float wx = ix - x0, wy = iy - y0;
    int x1 = min(x0 + 1, WW - 1), y1 = min(y0 + 1, HH - 1);
    float w00 = (1.f-wy)*(1.f-wx), w01 = (1.f-wy)*wx, w10 = wy*(1.f-wx), w11 = wy*wx;
    int i00 = y0*WW + x0, i01 = y0*WW + x1, i10 = y1*WW + x0, i11 = y1*WW + x1;
    const float* base = temporal + (size_t)(n*128 + chunk*8) * HW;
    float* dst = &g_WARP[(size_t)(n*128 + chunk*8) * HW + hw];
    #pragma unroll
    for (int c = 0; c < 8; c++) {
        const float* pp = base + (size_t)c * HW;
        dst[(size_t)c * HW] = pp[i00]*w00 + pp[i01]*w01 + pp[i10]*w10 + pp[i11]*w11;
    }
}

// ---------------- copy ds_latent tail channels into g_DSS ----------------
__global__ void dscopy_kernel(const float* __restrict__ dsl) {
    int idx = blockIdx.x * blockDim.x + threadIdx.x;
    if (idx >= NB * 3 * DHW) return;
    int n = idx / (3 * DHW); int rem = idx % (3 * DHW);
    int c = rem / DHW; int i = rem % DHW;
    g_DSS[(size_t)(n*128 + 125 + c) * DHW + i] = dsl[(size_t)(n*96 + 93 + c) * DHW + i];
}

// ---------------- mma helpers ----------------
__device__ __forceinline__ void ldm4(unsigned& r0, unsigned& r1, unsigned& r2, unsigned& r3,
                                     const __half* p) {
    unsigned a = (unsigned)__cvta_generic_to_shared(p);
    asm volatile("ldmatrix.sync.aligned.m8n8.x4.shared.b16 {%0,%1,%2,%3}, [%4];"
                 : "=r"(r0), "=r"(r1), "=r"(r2), "=r"(r3) : "r"(a));
}
__device__ __forceinline__ void ldm4t(unsigned& r0, unsigned& r1, unsigned& r2, unsigned& r3,
                                      const __half* p) {
    unsigned a = (unsigned)__cvta_generic_to_shared(p);
    asm volatile("ldmatrix.sync.aligned.m8n8.x4.trans.shared.b16 {%0,%1,%2,%3}, [%4];"
                 : "=r"(r0), "=r"(r1), "=r"(r2), "=r"(r3) : "r"(a));
}
__device__ __forceinline__ void mma16816(float* d, unsigned a0, unsigned a1, unsigned a2, unsigned a3,
                                         unsigned b0, unsigned b1) {
    asm volatile("mma.sync.aligned.m16n8k16.row.col.f32.f16.f16.f32 "
                 "{%0,%1,%2,%3}, {%4,%5,%6,%7}, {%8,%9}, {%0,%1,%2,%3};"
                 : "+f"(d[0]), "+f"(d[1]), "+f"(d[2]), "+f"(d[3])
                 : "r"(a0), "r"(a1), "r"(a2), "r"(a3), "r"(b0), "r"(b1));
}
__device__ __forceinline__ unsigned packh2(float lo, float hi) {
    __half2 h = __floats2half2_rn(lo, hi);
    return *(unsigned*)&h;
}

// ---------------- windowed attention: tensor-core fp16 QK/PV, fp32 LN+softmax ----------------
__global__ __launch_bounds__(128)
void attn_kernel(const float* __restrict__ radiance,
                 const float* __restrict__ qg, const float* __restrict__ qb,
                 const float* __restrict__ kg, const float* __restrict__ kb,
                 const float* __restrict__ vg, const float* __restrict__ vb) {
    extern __shared__ char smraw[];
    __half* Qh = (__half*)smraw;           // 64 x PAD
    __half* Kh = Qh + 64*PAD;
    __half* Vh = Kh + 64*PAD;
    float* Raw0 = (float*)(Vh + 64*PAD);   // 64 x 65
    float* Raw1 = Raw0 + 64*65;

    int tid = threadIdx.x;
    int lane = tid & 31;
    int w = tid >> 5;
    int n = blockIdx.x >> 10;
    int l = blockIdx.x & 1023;
    int by = (l >> 5) * 8, bx = (l & 31) * 8;

    for (int idx = tid; idx < 4096; idx += 128) {
        int r = idx & 63, c = idx >> 6;
        int y = by + (r >> 3), x = bx + (r & 7);
        Raw0[r*65 + c] = g_SU[(size_t)(n*189 + c) * HW + y*256 + x];
    }
    __syncthreads();
    if (tid < 64) {
        const float* row = Raw0 + tid*65;
        float mu = 0.f;
        #pragma unroll 8
        for (int c = 0; c < 64; c++) mu += row[c];
        mu *= (1.f/64.f);
        float var = 0.f;
        #pragma unroll 8
        for (int c = 0; c < 64; c++) { float d = row[c] - mu; var += d*d; }
        float rs = rsqrtf(var * (1.f/64.f) + 1e-5f);
        #pragma unroll 8
        for (int c = 0; c < 64; c++)
            Qh[tid*PAD + c] = __float2half_rn(((row[c] - mu) * rs * qg[c] + qb[c]) * 0.125f);
    }
    __syncthreads();

    unsigned qa[4][4];
    {
        int q0 = w * 16;
        #pragma unroll
        for (int kk = 0; kk < 4; kk++) {
            const __half* p = Qh + (q0 + (lane & 15))*PAD + kk*16 + ((lane >> 4) << 3);
            ldm4(qa[kk][0], qa[kk][1], qa[kk][2], qa[kk][3], p);
        }
    }

    float o[8][4];
    #pragma unroll
    for (int t = 0; t < 8; t++)
        #pragma unroll
        for (int j = 0; j < 4; j++) o[t][j] = 0.f;
    float m0 = -1e30f, m1 = -1e30f, l0 = 0.f, l1 = 0.f;

    for (int ci = 0; ci < 6; ci++) {
        for (int idx = tid; idx < 4096; idx += 128) {
            int r = idx & 63, c = idx >> 6;
            float kvv, vvv;
            if (ci < 4) {
                int ky = ci*4 + (r >> 4), kx = r & 15;
                int y = by - 4 + ky, x = bx - 4 + kx;
                if (y >= 0 && y < 256 && x >= 0 && x < 256) {
                    int off = y*256 + x;
                    kvv = g_SU[(size_t)(n*189 + 64 + c) * HW + off];
                    vvv = (c < 61) ? g_SU[(size_t)(n*189 + 128 + c) * HW + off]
                                   : radiance[(size_t)(n*3 + c - 61) * HW + off];
                } else { kvv = 0.f; vvv = 0.f; }
            } else {
                int y = by + (r >> 3), x = bx + (r & 7);
                int off = y*256 + x;
                const float* src = (ci == 4) ? g_WARP : g_DSE;
                kvv = src[(size_t)(n*128 + c) * HW + off];
                vvv = src[(size_t)(n*128 + 64 + c) * HW + off];
            }
            Raw0[r*65 + c] = kvv; Raw1[r*65 + c] = vvv;
        }
        __syncthreads();
        if (tid < 64) {
            const float* row = Raw0 + tid*65;
            float mu = 0.f;
            #pragma unroll 8
            for (int c = 0; c < 64; c++) mu += row[c];
            mu *= (1.f/64.f);
            float var = 0.f;
            #pragma unroll 8
            for (int c = 0; c < 64; c++) { float d = row[c] - mu; var += d*d; }
            float rs = rsqrtf(var * (1.f/64.f) + 1e-5f);
            #pragma unroll 8
            for (int c = 0; c < 64; c++)
                Kh[tid*PAD + c] = __float2half_rn((row[c] - mu) * rs * kg[c] + kb[c]);
        } else {
            int r = tid - 64;
            const float* row = Raw1 + r*65;
            float mu = 0.f;
            for (int c = 0; c < 61; c++) mu += row[c];
            mu *= (1.f/61.f);
            float var = 0.f;
            for (int c = 0; c < 61; c++) { float d = row[c] - mu; var += d*d; }
            float rs = rsqrtf(var * (1.f/61.f) + 1e-5f);
            for (int c = 0; c < 61; c++)
                Vh[r*PAD + c] = __float2half_rn((row[c] - mu) * rs * vg[c] + vb[c]);
            for (int c = 61; c < 64; c++)
                Vh[r*PAD + c] = __float2half_rn(row[c]);
        }
        __syncthreads();

        float s[8][4];
        #pragma unroll
        for (int t = 0; t < 8; t++)
            #pragma unroll
            for (int j = 0; j < 4; j++) s[t][j] = 0.f;
        #pragma unroll
        for (int kk = 0; kk < 4; kk++) {
            #pragma unroll
            for (int np = 0; np < 4; np++) {
                unsigned b0, b1, b2, b3;
                const __half* p = Kh + (np*16 + (lane & 7) + ((lane >> 4) << 3))*PAD
                                     + kk*16 + (((lane >> 3) & 1) << 3);
                ldm4(b0, b1, b2, b3, p);
                mma16816(s[2*np],   qa[kk][0], qa[kk][1], qa[kk][2], qa[kk][3], b0, b1);
                mma16816(s[2*np+1], qa[kk][0], qa[kk][1], qa[kk][2], qa[kk][3], b2, b3);
            }
        }

        float mx0 = -1e30f, mx1 = -1e30f;
        #pragma unroll
        for (int t = 0; t < 8; t++) {
            mx0 = fmaxf(mx0, fmaxf(s[t][0], s[t][1]));
            mx1 = fmaxf(mx1, fmaxf(s[t][2], s[t][3]));
        }
        mx0 = fmaxf(mx0, __shfl_xor_sync(0xffffffffu, mx0, 1));
        mx0 = fmaxf(mx0, __shfl_xor_sync(0xffffffffu, mx0, 2));
        mx1 = fmaxf(mx1, __shfl_xor_sync(0xffffffffu, mx1, 1));
        mx1 = fmaxf(mx1, __shfl_xor_sync(0xffffffffu, mx1, 2));
        float mn0 = fmaxf(m0, mx0), mn1 = fmaxf(m1, mx1);
        float corr0 = __expf(m0 - mn0), corr1 = __expf(m1 - mn1);
        m0 = mn0; m1 = mn1;
        float sum0 = 0.f, sum1 = 0.f;
        #pragma unroll
        for (int t = 0; t < 8; t++) {
            s[t][0] = __expf(s[t][0] - m0); s[t][1] = __expf(s[t][1] - m0);
            s[t][2] = __expf(s[t][2] - m1); s[t][3] = __expf(s[t][3] - m1);
            sum0 += s[t][0] + s[t][1];
            sum1 += s[t][2] + s[t][3];
        }
        sum0 += __shfl_xor_sync(0xffffffffu, sum0, 1);
        sum0 += __shfl_xor_sync(0xffffffffu, sum0, 2);
        sum1 += __shfl_xor_sync(0xffffffffu, sum1, 1);
        sum1 += __shfl_xor_sync(0xffffffffu, sum1, 2);
        l0 = l0 * corr0 + sum0;
        l1 = l1 * corr1 + sum1;
        #pragma unroll
        for (int t = 0; t < 8; t++) {
            o[t][0] *= corr0; o[t][1] *= corr0;
            o[t][2] *= corr1; o[t][3] *= corr1;
        }

        #pragma unroll
        for (int jp = 0; jp < 4; jp++) {
            unsigned a0 = packh2(s[2*jp][0],   s[2*jp][1]);
            unsigned a1 = packh2(s[2*jp][2],   s[2*jp][3]);
            unsigned a2 = packh2(s[2*jp+1][0], s[2*jp+1][1]);
            unsigned a3 = packh2(s[2*jp+1][2], s[2*jp+1][3]);
            #pragma unroll
            for (int np = 0; np < 4; np++) {
                unsigned b0, b1, b2, b3;
                const __half* p = Vh + (jp*16 + (lane & 7) + (((lane >> 3) & 1) << 3))*PAD
                                     + np*16 + ((lane >> 4) << 3);
                ldm4t(b0, b1, b2, b3, p);
                mma16816(o[2*np],   a0, a1, a2, a3, b0, b1);
                mma16816(o[2*np+1], a0, a1, a2, a3, b2, b3);
            }
        }
        __syncthreads();
    }

    float inv0 = 1.f / l0, inv1 = 1.f / l1;
    int r0 = w*16 + (lane >> 2);
    int r1 = r0 + 8;
    int y0 = by + (r0 >> 3), x0 = bx + (r0 & 7);
    int y1 = by + (r1 >> 3), x1 = bx + (r1 & 7);
    #pragma unroll
    for (int t = 0; t < 8; t++) {
        int c = t*8 + 2*(lane & 3);
        g_ATT[(size_t)(n*64 + c    ) * HW + y0*256 + x0] = o[t][0] * inv0;
        g_ATT[(size_t)(n*64 + c + 1) * HW + y0*256 + x0] = o[t][1] * inv0;
        g_ATT[(size_t)(n*64 + c    ) * HW + y1*256 + x1] = o[t][2] * inv1;
        g_ATT[(size_t)(n*64 + c + 1) * HW + y1*256 + x1] = o[t][3] * inv1;
    }
}

// ---------------- output tail: only the g_ATT-sourced channels (float4) ----------------
// decoded ch 61..63  <- g_ATT ch 61..63
// temporal ch 125..127 <- g_ATT ch 61..63  (same values, two destinations)
__global__ void tail_kernel(float* __restrict__ out) {
    int idx = blockIdx.x * blockDim.x + threadIdx.x;   // float4 index over NB*3*HW/4
    const int HW4 = HW / 4;
    if (idx >= NB * 3 * HW4) return;
    int n = idx / (3 * HW4); int rem = idx % (3 * HW4);
    int c = rem / HW4; int hw4 = rem % HW4;
    float4 v = *(const float4*)&g_ATT[(size_t)(n*64 + 61 + c) * HW + hw4*4];
    *(float4*)&out[(size_t)(n*64 + 61 + c) * HW + hw4*4] = v;
    *(float4*)&out[(size_t)NB*64*HW + (size_t)(n*128 + 125 + c) * HW + hw4*4] = v;
}

// ---------------- host launcher ----------------
extern "C" void kernel_launch(void* const* d_in, const int* in_sizes, int n_in,
                              void* d_out, int out_size) {
    const float* radiance = (const float*)d_in[0];
    const float* skip     = (const float*)d_in[1];
    const float* dsl      = (const float*)d_in[2];
    const float* temporal = (const float*)d_in[3];
    const float* mv       = (const float*)d_in[4];
    const float* su_bn_g  = (const float*)d_in[5];
    const float* su_bn_b  = (const float*)d_in[6];
    const float* su_w     = (const float*)d_in[7];
    const float* su_b     = (const float*)d_in[8];
    const float* ds_bn_g  = (const float*)d_in[9];
    const float* ds_bn_b  = (const float*)d_in[10];
    const float* ds_w     = (const float*)d_in[11];
    const float* ds_b     = (const float*)d_in[12];
    const float* qln_g    = (const float*)d_in[13];
    const float* qln_b    = (const float*)d_in[14];
    const float* kln_g    = (const float*)d_in[15];
    const float* kln_b    = (const float*)d_in[16];
    const float* vln_g    = (const float*)d_in[17];
    const float* vln_b    = (const float*)d_in[18];
    const float* f1_g     = (const float*)d_in[19];
    const float* f1_b     = (const float*)d_in[20];
    const float* w1       = (const float*)d_in[21];
    const float* b1       = (const float*)d_in[22];
    const float* f2_g     = (const float*)d_in[23];
    const float* f2_b     = (const float*)d_in[24];
    const float* w2       = (const float*)d_in[25];
    const float* b2       = (const float*)d_in[26];
    float* out = (float*)d_out;

    float *dUS, *dSU, *dDSS, *dDSE, *dATT, *dH1;
    cudaGetSymbolAddress((void**)&dUS,  g_US);
    cudaGetSymbolAddress((void**)&dSU,  g_SU);
    cudaGetSymbolAddress((void**)&dDSS, g_DSS);
    cudaGetSymbolAddress((void**)&dDSE, g_DSE);
    cudaGetSymbolAddress((void**)&dATT, g_ATT);
    cudaGetSymbolAddress((void**)&dH1,  g_H1);

    float* outTemporal = out + (size_t)NB*64*HW;   // temporal_out section, 128-ch stride

    const int ATTN_SMEM = 3*64*PAD*2 + 2*64*65*4;  // 60928 B
    cudaFuncSetAttribute(attn_kernel, cudaFuncAttributeMaxDynamicSharedMemorySize, ATTN_SMEM);

    // 1. us = resize(ds_latent, 128->256)
    resize_kernel<<<(NB*96*HW + 255)/256, 256>>>(dsl, dUS, 96, 128, 128, 256, 256);
    // 2-3. su BN stats + conv1x1 -> su_emb (189 ch); channels 64..188 mirrored to temporal_out
    bn_stats1_kernel<<<dim3(192, NSLAB), 256>>>(skip, 96, dUS, 96, HW);
    bn_stats2_kernel<<<192, 32>>>(su_bn_g, su_bn_b, HW);
    conv1x1_kernel<<<dim3((NB*HW)/256, 3), 256>>>(skip, 96, dUS, 96, su_w, su_b, 189, HW, dSU, 189, 0, outTemporal);
    // 4. warped temporal kv (16 channel-chunks for occupancy)
    warp_kernel<<<dim3((NB*HW + 255)/256, 16), 256>>>(temporal, mv);
    // 5-8. ds embedding
    bn_stats1_kernel<<<dim3(96, NSLAB), 256>>>(dsl, 96, (const float*)0, 0, DHW);
    bn_stats2_kernel<<<96, 32>>>(ds_bn_g, ds_bn_b, DHW);
    conv1x1_kernel<<<dim3((NB*DHW)/256, 2), 256>>>(dsl, 96, (const float*)0, 0, ds_w, ds_b, 125, DHW, dDSS, 128, 0, (float*)0);
    dscopy_kernel<<<(NB*3*DHW + 255)/256, 256>>>(dsl);
    resize_kernel<<<(NB*128*HW + 255)/256, 256>>>(dDSS, dDSE, 128, 128, 128, 256, 256);
    // 9. attention (tensor-core)
    attn_kernel<<<NB*1024, 128, ATTN_SMEM>>>(radiance, qln_g, qln_b, kln_g, kln_b, vln_g, vln_b);
    // 10-13. FFN
    bn_stats1_kernel<<<dim3(64, NSLAB), 256>>>(dATT, 64, (const float*)0, 0, HW);
    bn_stats2_kernel<<<64, 32>>>(f1_g, f1_b, HW);
    conv1x1_kernel<<<dim3((NB*HW)/256, 2), 256>>>(dATT, 64, (const float*)0, 0, w1, b1, 128, HW, dH1, 128, 1, (float*)0);
    bn_stats1_kernel<<<dim3(128, NSLAB), 256>>>(dH1, 128, (const float*)0, 0, HW);
    bn_stats2_kernel<<<128, 32>>>(f2_g, f2_b, HW);
    conv1x1_kernel<<<dim3((NB*HW)/256, 1), 256>>>(dH1, 128, (const float*)0, 0, w2, b2, 61, HW, out, 64, 0, (float*)0);
    // 14. remaining tail channels (attention-sourced)
    tail_kernel<<<(NB*3*HW/4 + 255)/256, 256>>>(out);
}

// round 8
// speedup vs baseline: 3.5698x; 1.1011x over previous
#include <cuda_runtime.h>
#include <cuda_fp16.h>
#include <math.h>

#define NB 2
#define HH 256
#define WW 256
#define HW 65536
#define DHW 16384   // 128*128
#define PAD 72      // fp16 row stride for ldmatrix tiles (attention)
#define NSLAB 16
#define PADX 264    // conv x smem row stride in halves ([k][px], 256 px + 8 pad)
#define PADK 40     // conv w smem row stride in halves ([oc][k])

// ---------------- scratch (static device allocations) ----------------
__device__ float g_US [NB*96 *HW];
__device__ float g_SU [NB*189*HW];
__device__ float g_WARP[NB*128*HW];
__device__ float g_DSS[NB*128*DHW];
__device__ float g_DSE[NB*128*HW];
__device__ float g_ATT[NB*64 *HW];
__device__ float g_H1 [NB*128*HW];
__device__ float g_S[192];
__device__ float g_T[192];
__device__ float g_PSUM[192*NSLAB];
__device__ float g_PSQ [192*NSLAB];

// ---------------- BN stats stage 1 ----------------
__global__ void bn_stats1_kernel(const float* __restrict__ src0, int C0,
                                 const float* __restrict__ src1, int C1,
                                 int hw) {
    int c = blockIdx.x;
    int slab = blockIdx.y;
    const float* base; int cs;
    if (c < C0) { base = src0 + (size_t)c * hw; cs = C0; }
    else        { base = src1 + (size_t)(c - C0) * hw; cs = C1; }
    int sl = hw / NSLAB;
    float sum = 0.f, sq = 0.f;
    for (int n = 0; n < NB; n++) {
        const float4* p = (const float4*)(base + (size_t)n * cs * hw + (size_t)slab * sl);
        int nv = sl >> 2;
        for (int i = threadIdx.x; i < nv; i += blockDim.x) {
            float4 v = p[i];
            sum += v.x + v.y + v.z + v.w;
            sq  += v.x*v.x + v.y*v.y + v.z*v.z + v.w*v.w;
        }
    }
    __shared__ float ssum[256], ssq[256];
    ssum[threadIdx.x] = sum; ssq[threadIdx.x] = sq; __syncthreads();
    for (int o = 128; o > 0; o >>= 1) {
        if (threadIdx.x < o) { ssum[threadIdx.x] += ssum[threadIdx.x+o]; ssq[threadIdx.x] += ssq[threadIdx.x+o]; }
        __syncthreads();
    }
    if (threadIdx.x == 0) {
        g_PSUM[c*NSLAB + slab] = ssum[0];
        g_PSQ [c*NSLAB + slab] = ssq[0];
    }
}

// ---------------- BN stats stage 2 ----------------
__global__ void bn_stats2_kernel(const float* __restrict__ g, const float* __restrict__ b,
                                 int hw) {
    int c = blockIdx.x;
    if (threadIdx.x == 0) {
        float sum = 0.f, sq = 0.f;
        #pragma unroll
        for (int s = 0; s < NSLAB; s++) { sum += g_PSUM[c*NSLAB + s]; sq += g_PSQ[c*NSLAB + s]; }
        float inv = 1.f / (float)(NB * hw);
        float m = sum * inv;
        float v = sq * inv - m * m;
        float s = g[c] * rsqrtf(v + 1e-5f);
        g_S[c] = s; g_T[c] = b[c] - m * s;
    }
}

// ---------------- mma helpers ----------------
__device__ __forceinline__ void ldm4(unsigned& r0, unsigned& r1, unsigned& r2, unsigned& r3,
                                     const __half* p) {
    unsigned a = (unsigned)__cvta_generic_to_shared(p);
    asm volatile("ldmatrix.sync.aligned.m8n8.x4.shared.b16 {%0,%1,%2,%3}, [%4];"
                 : "=r"(r0), "=r"(r1), "=r"(r2), "=r"(r3) : "r"(a));
}
__device__ __forceinline__ void ldm4t(unsigned& r0, unsigned& r1, unsigned& r2, unsigned& r3,
                                      const __half* p) {
    unsigned a = (unsigned)__cvta_generic_to_shared(p);
    asm volatile("ldmatrix.sync.aligned.m8n8.x4.trans.shared.b16 {%0,%1,%2,%3}, [%4];"
                 : "=r"(r0), "=r"(r1), "=r"(r2), "=r"(r3) : "r"(a));
}
__device__ __forceinline__ void mma16816(float* d, unsigned a0, unsigned a1, unsigned a2, unsigned a3,
                                         unsigned b0, unsigned b1) {
    asm volatile("mma.sync.aligned.m16n8k16.row.col.f32.f16.f16.f32 "
                 "{%0,%1,%2,%3}, {%4,%5,%6,%7}, {%8,%9}, {%0,%1,%2,%3};"
                 : "+f"(d[0]), "+f"(d[1]), "+f"(d[2]), "+f"(d[3])
                 : "r"(a0), "r"(a1), "r"(a2), "r"(a3), "r"(b0), "r"(b1));
}
__device__ __forceinline__ unsigned packh2(float lo, float hi) {
    __half2 h = __floats2half2_rn(lo, hi);
    return *(unsigned*)&h;
}

// ---------------- fused BN + conv1x1, tensor-core fp16 hi/lo split ----------------
// block tile: 256 px x 64 oc; 256 threads = 8 warps; warp = 32 px (2 m16 tiles) x 64 oc
// x staged [k][px] (PADX); A via ldmatrix.x4.trans. w staged [oc][k] (PADK); B via direct LDS.
__global__ __launch_bounds__(256)
void conv1x1_tc_kernel(const float* __restrict__ src0, int C0,
                       const float* __restrict__ src1, int C1,
                       const float* __restrict__ w, const float* __restrict__ bias,
                       int Cout, int hw, float* __restrict__ out, int outStride, int relu,
                       float* __restrict__ mirror) {
    extern __shared__ char cvsm[];
    __half* xh = (__half*)cvsm;            // 32 x PADX halves
    __half* xl = xh + 32*PADX;
    __half* wh = xl + 32*PADX;             // 64 x PADK halves
    __half* wl = wh + 64*PADK;
    const int Cin = C0 + C1;
    int tid = threadIdx.x;
    int lane = tid & 31;
    int wid = tid >> 5;                    // 0..7
    int g = lane >> 2, t = lane & 3;
    int p0 = blockIdx.x * 256;
    int n = p0 / hw, hw0 = p0 % hw;
    int ot = blockIdx.y;

    float acc[2][8][4];
    #pragma unroll
    for (int mt = 0; mt < 2; mt++)
        #pragma unroll
        for (int j = 0; j < 8; j++)
            #pragma unroll
            for (int e = 0; e < 4; e++) acc[mt][j][e] = 0.f;

    for (int cc = 0; cc < Cin; cc += 32) {
        // ---- stage x: 32 ch x 256 px into [k][px]; coalesced loads, contiguous 8B stores ----
        #pragma unroll
        for (int it = 0; it < 8; it++) {
            int idx = tid + it * 256;          // 0..2047
            int c = idx >> 6, p4 = idx & 63;   // channel 0..31, px quad 0..63
            int ch = cc + c;
            const float* src = (ch < C0) ? (src0 + (size_t)(n*C0 + ch) * hw)
                                         : (src1 + (size_t)(n*C1 + (ch - C0)) * hw);
            float4 v = *(const float4*)(src + hw0 + p4*4);
            float s = g_S[ch], tt = g_T[ch];
            float f0 = v.x*s + tt, f1 = v.y*s + tt, f2 = v.z*s + tt, f3 = v.w*s + tt;
            __half h0 = __float2half_rn(f0), h1 = __float2half_rn(f1);
            __half h2 = __float2half_rn(f2), h3 = __float2half_rn(f3);
            __half l0 = __float2half_rn(f0 - __half2float(h0));
            __half l1 = __float2half_rn(f1 - __half2float(h1));
            __half l2 = __float2half_rn(f2 - __half2float(h2));
            __half l3 = __float2half_rn(f3 - __half2float(h3));
            int off = c*PADX + p4*4;
            *(__half2*)&xh[off]     = __halves2half2(h0, h1);
            *(__half2*)&xh[off + 2] = __halves2half2(h2, h3);
            *(__half2*)&xl[off]     = __halves2half2(l0, l1);
            *(__half2*)&xl[off + 2] = __halves2half2(l2, l3);
        }
        // ---- stage w: [oc][k] ----
        #pragma unroll
        for (int it = 0; it < 2; it++) {
            int idx = tid + it * 256;          // 0..511
            int o = idx >> 3, k4 = idx & 7;
            int oc = ot*64 + o;
            float4 v;
            if (oc < Cout) v = *(const float4*)(w + (size_t)oc * Cin + cc + k4*4);
            else { v.x = 0.f; v.y = 0.f; v.z = 0.f; v.w = 0.f; }
            __half h0 = __float2half_rn(v.x), h1 = __float2half_rn(v.y);
            __half h2 = __float2half_rn(v.z), h3 = __float2half_rn(v.w);
            __half l0 = __float2half_rn(v.x - __half2float(h0));
            __half l1 = __float2half_rn(v.y - __half2float(h1));
            __half l2 = __float2half_rn(v.z - __half2float(h2));
            __half l3 = __float2half_rn(v.w - __half2float(h3));
            int off = o*PADK + k4*4;
            *(__half2*)&wh[off]     = __halves2half2(h0, h1);
            *(__half2*)&wh[off + 2] = __halves2half2(h2, h3);
            *(__half2*)&wl[off]     = __halves2half2(l0, l1);
            *(__half2*)&wl[off + 2] = __halves2half2(l2, l3);
        }
        __syncthreads();

        #pragma unroll
        for (int kk = 0; kk < 32; kk += 16) {
            // A fragments (hi & lo) via ldmatrix.trans from [k][px]
            unsigned ah[2][4], al[2][4];
            #pragma unroll
            for (int mt = 0; mt < 2; mt++) {
                int m0 = wid*32 + mt*16;       // 0..240, +15 max -> in [0,256)
                const __half* pa = xh + (kk + (lane & 7) + ((lane >> 4) << 3))*PADX
                                      + m0 + (((lane >> 3) & 1) << 3);
                const __half* pb = xl + (kk + (lane & 7) + ((lane >> 4) << 3))*PADX
                                      + m0 + (((lane >> 3) & 1) << 3);
                ldm4t(ah[mt][0], ah[mt][1], ah[mt][2], ah[mt][3], pa);
                ldm4t(al[mt][0], al[mt][1], al[mt][2], al[mt][3], pb);
            }
            #pragma unroll
            for (int j = 0; j < 8; j++) {
                // B fragment: b0 = {w[j*8+g][kk+2t], [kk+2t+1]}, b1 = +8 in k
                int bo = (j*8 + g)*PADK + kk + 2*t;
                unsigned bh0 = *(const unsigned*)(wh + bo);
                unsigned bh1 = *(const unsigned*)(wh + bo + 8);
                unsigned bl0 = *(const unsigned*)(wl + bo);
                unsigned bl1 = *(const unsigned*)(wl + bo + 8);
                #pragma unroll
                for (int mt = 0; mt < 2; mt++) {
                    mma16816(acc[mt][j], ah[mt][0], ah[mt][1], ah[mt][2], ah[mt][3], bh0, bh1);
                    mma16816(acc[mt][j], ah[mt][0], ah[mt][1], ah[mt][2], ah[mt][3], bl0, bl1);
                    mma16816(acc[mt][j], al[mt][0], al[mt][1], al[mt][2], al[mt][3], bh0, bh1);
                }
            }
        }
        __syncthreads();
    }

    // writeback: C row = px (pr, pr+8), col = oc (2t, 2t+1)
    #pragma unroll
    for (int mt = 0; mt < 2; mt++) {
        int pr = wid*32 + mt*16 + g;           // 0..255
        #pragma unroll
        for (int j = 0; j < 8; j++) {
            int o = ot*64 + j*8 + 2*t;
            if (o < Cout) {
                float bv = bias[o];
                float v0 = acc[mt][j][0] + bv;
                float v2 = acc[mt][j][2] + bv;
                if (relu) { v0 = fmaxf(v0, 0.f); v2 = fmaxf(v2, 0.f); }
                float* op = out + (size_t)(n*outStride + o) * hw + hw0;
                op[pr] = v0; op[pr + 8] = v2;
                if (mirror != 0 && o >= 64) {
                    float* mp = mirror + (size_t)(n*128 + (o - 64)) * hw + hw0;
                    mp[pr] = v0; mp[pr + 8] = v2;
                }
            }
            if (o + 1 < Cout) {
                float bv = bias[o+1];
                float v1 = acc[mt][j][1] + bv;
                float v3 = acc[mt][j][3] + bv;
                if (relu) { v1 = fmaxf(v1, 0.f); v3 = fmaxf(v3, 0.f); }
                float* op = out + (size_t)(n*outStride + o + 1) * hw + hw0;
                op[pr] = v1; op[pr + 8] = v3;
                if (mirror != 0 && o + 1 >= 64) {
                    float* mp = mirror + (size_t)(n*128 + (o + 1 - 64)) * hw + hw0;
                    mp[pr] = v1; mp[pr + 8] = v3;
                }
            }
        }
    }
}

// ---------------- align-corners bilinear resize ----------------
__global__ void resize_kernel(const float* __restrict__ src, float* __restrict__ dst,
                              int C, int Hs, int Ws, int Hd, int Wd) {
    int idx = blockIdx.x * blockDim.x + threadIdx.x;
    int total = NB * C * Hd * Wd;
    if (idx >= total) return;
    int x = idx % Wd; int y = (idx / Wd) % Hd; int nc = idx / (Wd * Hd);
    float sy = y * (float)(Hs - 1) / (float)(Hd - 1);
    float sx = x * (float)(Ws - 1) / (float)(Wd - 1);
    int y0 = (int)floorf(sy); int x0 = (int)floorf(sx);
    float wy = sy - y0, wx = sx - x0;
    int y1 = min(y0 + 1, Hs - 1), x1 = min(x0 + 1, Ws - 1);
    const float* p = src + (size_t)nc * Hs * Ws;
    float v00 = p[y0*Ws + x0], v01 = p[y0*Ws + x1];
    float v10 = p[y1*Ws + x0], v11 = p[y1*Ws + x1];
    float top = v00 + (v10 - v00) * wy;
    float bot = v01 + (v11 - v01) * wy;
    dst[idx] = top + (bot - top) * wx;
}

// ---------------- grid_sample (border) of temporal_kv; 8 channels per thread ----------------
__global__ void warp_kernel(const float* __restrict__ temporal, const float* __restrict__ mv) {
    int p = blockIdx.x * blockDim.x + threadIdx.x;
    if (p >= NB * HW) return;
    int chunk = blockIdx.y;             // 0..15
    int n = p / HW; int hw = p % HW;
    int h = hw >> 8; int w = hw & 255;
    float xsv = -1.f + 2.f * w / (float)(WW - 1);
    float ysv = -1.f + 2.f * h / (float)(HH - 1);
    float gx = mv[(size_t)(n*2 + 0) * HW + hw] * (2.f / WW) + xsv;
    float gy = ysv - mv[(size_t)(n*2 + 1) * HW + hw] * (2.f / HH);
    float ix = fminf(fmaxf((gx + 1.f) * 0.5f * (WW - 1), 0.f), (float)(WW - 1));
    float iy = fminf(fmaxf((gy + 1.f) * 0.5f * (HH - 1), 0.f), (float)(HH - 1));
    int x0 = (int)floorf(ix), y0 = (int)floorf(iy);
    float wx = ix - x0, wy = iy - y0;
    int x1 = min(x0 + 1, WW - 1), y1 = min(y0 + 1, HH - 1);
    float w00 = (1.f-wy)*(1.f-wx), w01 = (1.f-wy)*wx, w10 = wy*(1.f-wx), w11 = wy*wx;
    int i00 = y0*WW + x0, i01 = y0*WW + x1, i10 = y1*WW + x0, i11 = y1*WW + x1;
    const float* base = temporal + (size_t)(n*128 + chunk*8) * HW;
    float* dst = &g_WARP[(size_t)(n*128 + chunk*8) * HW + hw];
    #pragma unroll
    for (int c = 0; c < 8; c++) {
        const float* pp = base + (size_t)c * HW;
        dst[(size_t)c * HW] = pp[i00]*w00 + pp[i01]*w01 + pp[i10]*w10 + pp[i11]*w11;
    }
}

// ---------------- copy ds_latent tail channels into g_DSS ----------------
__global__ void dscopy_kernel(const float* __restrict__ dsl) {
    int idx = blockIdx.x * blockDim.x + threadIdx.x;
    if (idx >= NB * 3 * DHW) return;
    int n = idx / (3 * DHW); int rem = idx % (3 * DHW);
    int c = rem / DHW; int i = rem % DHW;
    g_DSS[(size_t)(n*128 + 125 + c) * DHW + i] = dsl[(size_t)(n*96 + 93 + c) * DHW + i];
}

// ---------------- windowed attention: tensor-core fp16 QK/PV, fp32 LN+softmax ----------------
__global__ __launch_bounds__(128)
void attn_kernel(const float* __restrict__ radiance,
                 const float* __restrict__ qg, const float* __restrict__ qb,
                 const float* __restrict__ kg, const float* __restrict__ kb,
                 const float* __restrict__ vg, const float* __restrict__ vb) {
    extern __shared__ char smraw[];
    __half* Qh = (__half*)smraw;           // 64 x PAD
    __half* Kh = Qh + 64*PAD;
    __half* Vh = Kh + 64*PAD;
    float* Raw0 = (float*)(Vh + 64*PAD);   // 64 x 65
    float* Raw1 = Raw0 + 64*65;

    int tid = threadIdx.x;
    int lane = tid & 31;
    int w = tid >> 5;
    int n = blockIdx.x >> 10;
    int l = blockIdx.x & 1023;
    int by = (l >> 5) * 8, bx = (l & 31) * 8;

    for (int idx = tid; idx < 4096; idx += 128) {
        int r = idx & 63, c = idx >> 6;
        int y = by + (r >> 3), x = bx + (r & 7);
        Raw0[r*65 + c] = g_SU[(size_t)(n*189 + c) * HW + y*256 + x];
    }
    __syncthreads();
    if (tid < 64) {
        const float* row = Raw0 + tid*65;
        float mu = 0.f;
        #pragma unroll 8
        for (int c = 0; c < 64; c++) mu += row[c];
        mu *= (1.f/64.f);
        float var = 0.f;
        #pragma unroll 8
        for (int c = 0; c < 64; c++) { float d = row[c] - mu; var += d*d; }
        float rs = rsqrtf(var * (1.f/64.f) + 1e-5f);
        #pragma unroll 8
        for (int c = 0; c < 64; c++)
            Qh[tid*PAD + c] = __float2half_rn(((row[c] - mu) * rs * qg[c] + qb[c]) * 0.125f);
    }
    __syncthreads();

    unsigned qa[4][4];
    {
        int q0 = w * 16;
        #pragma unroll
        for (int kk = 0; kk < 4; kk++) {
            const __half* p = Qh + (q0 + (lane & 15))*PAD + kk*16 + ((lane >> 4) << 3);
            ldm4(qa[kk][0], qa[kk][1], qa[kk][2], qa[kk][3], p);
        }
    }

    float o[8][4];
    #pragma unroll
    for (int t = 0; t < 8; t++)
        #pragma unroll
        for (int j = 0; j < 4; j++) o[t][j] = 0.f;
    float m0 = -1e30f, m1 = -1e30f, l0 = 0.f, l1 = 0.f;

    for (int ci = 0; ci < 6; ci++) {
        for (int idx = tid; idx < 4096; idx += 128) {
            int r = idx & 63, c = idx >> 6;
            float kvv, vvv;
            if (ci < 4) {
                int ky = ci*4 + (r >> 4), kx = r & 15;
                int y = by - 4 + ky, x = bx - 4 + kx;
                if (y >= 0 && y < 256 && x >= 0 && x < 256) {
                    int off = y*256 + x;
                    kvv = g_SU[(size_t)(n*189 + 64 + c) * HW + off];
                    vvv = (c < 61) ? g_SU[(size_t)(n*189 + 128 + c) * HW + off]
                                   : radiance[(size_t)(n*3 + c - 61) * HW + off];
                } else { kvv = 0.f; vvv = 0.f; }
            } else {
                int y = by + (r >> 3), x = bx + (r & 7);
                int off = y*256 + x;
                const float* src = (ci == 4) ? g_WARP : g_DSE;
                kvv = src[(size_t)(n*128 + c) * HW + off];
                vvv = src[(size_t)(n*128 + 64 + c) * HW + off];
            }
            Raw0[r*65 + c] = kvv; Raw1[r*65 + c] = vvv;
        }
        __syncthreads();
        if (tid < 64) {
            const float* row = Raw0 + tid*65;
            float mu = 0.f;
            #pragma unroll 8
            for (int c = 0; c < 64; c++) mu += row[c];
            mu *= (1.f/64.f);
            float var = 0.f;
            #pragma unroll 8
            for (int c = 0; c < 64; c++) { float d = row[c] - mu; var += d*d; }
            float rs = rsqrtf(var * (1.f/64.f) + 1e-5f);
            #pragma unroll 8
            for (int c = 0; c < 64; c++)
                Kh[tid*PAD + c] = __float2half_rn((row[c] - mu) * rs * kg[c] + kb[c]);
        } else {
            int r = tid - 64;
            const float* row = Raw1 + r*65;
            float mu = 0.f;
            for (int c = 0; c < 61; c++) mu += row[c];
            mu *= (1.f/61.f);
            float var = 0.f;
            for (int c = 0; c < 61; c++) { float d = row[c] - mu; var += d*d; }
            float rs = rsqrtf(var * (1.f/61.f) + 1e-5f);
            for (int c = 0; c < 61; c++)
                Vh[r*PAD + c] = __float2half_rn((row[c] - mu) * rs * vg[c] + vb[c]);
            for (int c = 61; c < 64; c++)
                Vh[r*PAD + c] = __float2half_rn(row[c]);
        }
        __syncthreads();

        float s[8][4];
        #pragma unroll
        for (int t = 0; t < 8; t++)
            #pragma unroll
            for (int j = 0; j < 4; j++) s[t][j] = 0.f;
        #pragma unroll
        for (int kk = 0; kk < 4; kk++) {
            #pragma unroll
            for (int np = 0; np < 4; np++) {
                unsigned b0, b1, b2, b3;
                const __half* p = Kh + (np*16 + (lane & 7) + ((lane >> 4) << 3))*PAD
                                     + kk*16 + (((lane >> 3) & 1) << 3);
                ldm4(b0, b1, b2, b3, p);
                mma16816(s[2*np],   qa[kk][0], qa[kk][1], qa[kk][2], qa[kk][3], b0, b1);
                mma16816(s[2*np+1], qa[kk][0], qa[kk][1], qa[kk][2], qa[kk][3], b2, b3);
            }
        }

        float mx0 = -1e30f, mx1 = -1e30f;
        #pragma unroll
        for (int t = 0; t < 8; t++) {
            mx0 = fmaxf(mx0, fmaxf(s[t][0], s[t][1]));
            mx1 = fmaxf(mx1, fmaxf(s[t][2], s[t][3]));
        }
        mx0 = fmaxf(mx0, __shfl_xor_sync(0xffffffffu, mx0, 1));
        mx0 = fmaxf(mx0, __shfl_xor_sync(0xffffffffu, mx0, 2));
        mx1 = fmaxf(mx1, __shfl_xor_sync(0xffffffffu, mx1, 1));
        mx1 = fmaxf(mx1, __shfl_xor_sync(0xffffffffu, mx1, 2));
        float mn0 = fmaxf(m0, mx0), mn1 = fmaxf(m1, mx1);
        float corr0 = __expf(m0 - mn0), corr1 = __expf(m1 - mn1);
        m0 = mn0; m1 = mn1;
        float sum0 = 0.f, sum1 = 0.f;
        #pragma unroll
        for (int t = 0; t < 8; t++) {
            s[t][0] = __expf(s[t][0] - m0); s[t][1] = __expf(s[t][1] - m0);
            s[t][2] = __expf(s[t][2] - m1); s[t][3] = __expf(s[t][3] - m1);
            sum0 += s[t][0] + s[t][1];
            sum1 += s[t][2] + s[t][3];
        }
        sum0 += __shfl_xor_sync(0xffffffffu, sum0, 1);
        sum0 += __shfl_xor_sync(0xffffffffu, sum0, 2);
        sum1 += __shfl_xor_sync(0xffffffffu, sum1, 1);
        sum1 += __shfl_xor_sync(0xffffffffu, sum1, 2);
        l0 = l0 * corr0 + sum0;
        l1 = l1 * corr1 + sum1;
        #pragma unroll
        for (int t = 0; t < 8; t++) {
            o[t][0] *= corr0; o[t][1] *= corr0;
            o[t][2] *= corr1; o[t][3] *= corr1;
        }

        #pragma unroll
        for (int jp = 0; jp < 4; jp++) {
            unsigned a0 = packh2(s[2*jp][0],   s[2*jp][1]);
            unsigned a1 = packh2(s[2*jp][2],   s[2*jp][3]);
            unsigned a2 = packh2(s[2*jp+1][0], s[2*jp+1][1]);
            unsigned a3 = packh2(s[2*jp+1][2], s[2*jp+1][3]);
            #pragma unroll
            for (int np = 0; np < 4; np++) {
                unsigned b0, b1, b2, b3;
                const __half* p = Vh + (jp*16 + (lane & 7) + (((lane >> 3) & 1) << 3))*PAD
                                     + np*16 + ((lane >> 4) << 3);
                ldm4t(b0, b1, b2, b3, p);
                mma16816(o[2*np],   a0, a1, a2, a3, b0, b1);
                mma16816(o[2*np+1], a0, a1, a2, a3, b2, b3);
            }
        }
        __syncthreads();
    }

    float inv0 = 1.f / l0, inv1 = 1.f / l1;
    int r0 = w*16 + (lane >> 2);
    int r1 = r0 + 8;
    int y0 = by + (r0 >> 3), x0 = bx + (r0 & 7);
    int y1 = by + (r1 >> 3), x1 = bx + (r1 & 7);
    #pragma unroll
    for (int t = 0; t < 8; t++) {
        int c = t*8 + 2*(lane & 3);
        g_ATT[(size_t)(n*64 + c    ) * HW + y0*256 + x0] = o[t][0] * inv0;
        g_ATT[(size_t)(n*64 + c + 1) * HW + y0*256 + x0] = o[t][1] * inv0;
        g_ATT[(size_t)(n*64 + c    ) * HW + y1*256 + x1] = o[t][2] * inv1;
        g_ATT[(size_t)(n*64 + c + 1) * HW + y1*256 + x1] = o[t][3] * inv1;
    }
}

// ---------------- output tail: only the g_ATT-sourced channels (float4) ----------------
__global__ void tail_kernel(float* __restrict__ out) {
    int idx = blockIdx.x * blockDim.x + threadIdx.x;
    const int HW4 = HW / 4;
    if (idx >= NB * 3 * HW4) return;
    int n = idx / (3 * HW4); int rem = idx % (3 * HW4);
    int c = rem / HW4; int hw4 = rem % HW4;
    float4 v = *(const float4*)&g_ATT[(size_t)(n*64 + 61 + c) * HW + hw4*4];
    *(float4*)&out[(size_t)(n*64 + 61 + c) * HW + hw4*4] = v;
    *(float4*)&out[(size_t)NB*64*HW + (size_t)(n*128 + 125 + c) * HW + hw4*4] = v;
}

// ---------------- host launcher ----------------
extern "C" void kernel_launch(void* const* d_in, const int* in_sizes, int n_in,
                              void* d_out, int out_size) {
    const float* radiance = (const float*)d_in[0];
    const float* skip     = (const float*)d_in[1];
    const float* dsl      = (const float*)d_in[2];
    const float* temporal = (const float*)d_in[3];
    const float* mv       = (const float*)d_in[4];
    const float* su_bn_g  = (const float*)d_in[5];
    const float* su_bn_b  = (const float*)d_in[6];
    const float* su_w     = (const float*)d_in[7];
    const float* su_b     = (const float*)d_in[8];
    const float* ds_bn_g  = (const float*)d_in[9];
    const float* ds_bn_b  = (const float*)d_in[10];
    const float* ds_w     = (const float*)d_in[11];
    const float* ds_b     = (const float*)d_in[12];
    const float* qln_g    = (const float*)d_in[13];
    const float* qln_b    = (const float*)d_in[14];
    const float* kln_g    = (const float*)d_in[15];
    const float* kln_b    = (const float*)d_in[16];
    const float* vln_g    = (const float*)d_in[17];
    const float* vln_b    = (const float*)d_in[18];
    const float* f1_g     = (const float*)d_in[19];
    const float* f1_b     = (const float*)d_in[20];
    const float* w1       = (const float*)d_in[21];
    const float* b1       = (const float*)d_in[22];
    const float* f2_g     = (const float*)d_in[23];
    const float* f2_b     = (const float*)d_in[24];
    const float* w2       = (const float*)d_in[25];
    const float* b2       = (const float*)d_in[26];
    float* out = (float*)d_out;

    float *dUS, *dSU, *dDSS, *dDSE, *dATT, *dH1;
    cudaGetSymbolAddress((void**)&dUS,  g_US);
    cudaGetSymbolAddress((void**)&dSU,  g_SU);
    cudaGetSymbolAddress((void**)&dDSS, g_DSS);
    cudaGetSymbolAddress((void**)&dDSE, g_DSE);
    cudaGetSymbolAddress((void**)&dATT, g_ATT);
    cudaGetSymbolAddress((void**)&dH1,  g_H1);

    float* outTemporal = out + (size_t)NB*64*HW;

    const int ATTN_SMEM = 3*64*PAD*2 + 2*64*65*4;   // 60928 B
    cudaFuncSetAttribute(attn_kernel, cudaFuncAttributeMaxDynamicSharedMemorySize, ATTN_SMEM);
    const int CONV_SMEM = (2*32*PADX + 2*64*PADK) * 2;  // 44032 B

    // 1. us = resize(ds_latent, 128->256)
    resize_kernel<<<(NB*96*HW + 255)/256, 256>>>(dsl, dUS, 96, 128, 128, 256, 256);
    // 2-3. su BN stats + conv1x1 -> su_emb (189 ch); ch 64..188 mirrored to temporal_out
    bn_stats1_kernel<<<dim3(192, NSLAB), 256>>>(skip, 96, dUS, 96, HW);
    bn_stats2_kernel<<<192, 32>>>(su_bn_g, su_bn_b, HW);
    conv1x1_tc_kernel<<<dim3((NB*HW)/256, 3), 256, CONV_SMEM>>>(skip, 96, dUS, 96, su_w, su_b, 189, HW, dSU, 189, 0, outTemporal);
    // 4. warped temporal kv
    warp_kernel<<<dim3((NB*HW + 255)/256, 16), 256>>>(temporal, mv);
    // 5-8. ds embedding
    bn_stats1_kernel<<<dim3(96, NSLAB), 256>>>(dsl, 96, (const float*)0, 0, DHW);
    bn_stats2_kernel<<<96, 32>>>(ds_bn_g, ds_bn_b, DHW);
    conv1x1_tc_kernel<<<dim3((NB*DHW)/256, 2), 256, CONV_SMEM>>>(dsl, 96, (const float*)0, 0, ds_w, ds_b, 125, DHW, dDSS, 128, 0, (float*)0);
    dscopy_kernel<<<(NB*3*DHW + 255)/256, 256>>>(dsl);
    resize_kernel<<<(NB*128*HW + 255)/256, 256>>>(dDSS, dDSE, 128, 128, 128, 256, 256);
    // 9. attention (tensor-core)
    attn_kernel<<<NB*1024, 128, ATTN_SMEM>>>(radiance, qln_g, qln_b, kln_g, kln_b, vln_g, vln_b);
    // 10-13. FFN
    bn_stats1_kernel<<<dim3(64, NSLAB), 256>>>(dATT, 64, (const float*)0, 0, HW);
    bn_stats2_kernel<<<64, 32>>>(f1_g, f1_b, HW);
    conv1x1_tc_kernel<<<dim3((NB*HW)/256, 2), 256, CONV_SMEM>>>(dATT, 64, (const float*)0, 0, w1, b1, 128, HW, dH1, 128, 1, (float*)0);
    bn_stats1_kernel<<<dim3(128, NSLAB), 256>>>(dH1, 128, (const float*)0, 0, HW);
    bn_stats2_kernel<<<128, 32>>>(f2_g, f2_b, HW);
    conv1x1_tc_kernel<<<dim3((NB*HW)/256, 1), 256, CONV_SMEM>>>(dH1, 128, (const float*)0, 0, w2, b2, 61, HW, out, 64, 0, (float*)0);
    // 14. remaining tail channels (attention-sourced)
    tail_kernel<<<(NB*3*HW/4 + 255)/256, 256>>>(out);
}

// round 9
// speedup vs baseline: 3.7628x; 1.0541x over previous
#include <cuda_runtime.h>
#include <cuda_fp16.h>
#include <math.h>

#define NB 2
#define HH 256
#define WW 256
#define HW 65536
#define DHW 16384   // 128*128
#define PAD 72      // fp16 row stride for ldmatrix tiles (attention)
#define NSLAB 16
#define PADX 264    // conv x smem row stride in halves ([k][px], 256 px + 8 pad)
#define PADK 40     // conv w smem row stride in halves ([oc][k])

// ---------------- scratch (static device allocations) ----------------
__device__ float g_US [NB*96 *HW];
__device__ float g_SU [NB*189*HW];
__device__ float g_WARP[NB*128*HW];
__device__ float g_DSS[NB*128*DHW];
__device__ float g_DSE[NB*128*HW];
__device__ float g_ATT[NB*64 *HW];
__device__ float g_H1 [NB*128*HW];
__device__ float g_S[192];
__device__ float g_T[192];
__device__ float g_PSUM[192*NSLAB];
__device__ float g_PSQ [192*NSLAB];

// ---------------- BN stats stage 1 ----------------
__global__ void bn_stats1_kernel(const float* __restrict__ src0, int C0,
                                 const float* __restrict__ src1, int C1,
                                 int hw) {
    int c = blockIdx.x;
    int slab = blockIdx.y;
    const float* base; int cs;
    if (c < C0) { base = src0 + (size_t)c * hw; cs = C0; }
    else        { base = src1 + (size_t)(c - C0) * hw; cs = C1; }
    int sl = hw / NSLAB;
    float sum = 0.f, sq = 0.f;
    for (int n = 0; n < NB; n++) {
        const float4* p = (const float4*)(base + (size_t)n * cs * hw + (size_t)slab * sl);
        int nv = sl >> 2;
        for (int i = threadIdx.x; i < nv; i += blockDim.x) {
            float4 v = p[i];
            sum += v.x + v.y + v.z + v.w;
            sq  += v.x*v.x + v.y*v.y + v.z*v.z + v.w*v.w;
        }
    }
    __shared__ float ssum[256], ssq[256];
    ssum[threadIdx.x] = sum; ssq[threadIdx.x] = sq; __syncthreads();
    for (int o = 128; o > 0; o >>= 1) {
        if (threadIdx.x < o) { ssum[threadIdx.x] += ssum[threadIdx.x+o]; ssq[threadIdx.x] += ssq[threadIdx.x+o]; }
        __syncthreads();
    }
    if (threadIdx.x == 0) {
        g_PSUM[c*NSLAB + slab] = ssum[0];
        g_PSQ [c*NSLAB + slab] = ssq[0];
    }
}

// ---------------- BN stats stage 2 ----------------
__global__ void bn_stats2_kernel(const float* __restrict__ g, const float* __restrict__ b,
                                 int hw) {
    int c = blockIdx.x;
    if (threadIdx.x == 0) {
        float sum = 0.f, sq = 0.f;
        #pragma unroll
        for (int s = 0; s < NSLAB; s++) { sum += g_PSUM[c*NSLAB + s]; sq += g_PSQ[c*NSLAB + s]; }
        float inv = 1.f / (float)(NB * hw);
        float m = sum * inv;
        float v = sq * inv - m * m;
        float s = g[c] * rsqrtf(v + 1e-5f);
        g_S[c] = s; g_T[c] = b[c] - m * s;
    }
}

// ---------------- mma helpers ----------------
__device__ __forceinline__ void ldm4(unsigned& r0, unsigned& r1, unsigned& r2, unsigned& r3,
                                     const __half* p) {
    unsigned a = (unsigned)__cvta_generic_to_shared(p);
    asm volatile("ldmatrix.sync.aligned.m8n8.x4.shared.b16 {%0,%1,%2,%3}, [%4];"
                 : "=r"(r0), "=r"(r1), "=r"(r2), "=r"(r3) : "r"(a));
}
__device__ __forceinline__ void ldm4t(unsigned& r0, unsigned& r1, unsigned& r2, unsigned& r3,
                                      const __half* p) {
    unsigned a = (unsigned)__cvta_generic_to_shared(p);
    asm volatile("ldmatrix.sync.aligned.m8n8.x4.trans.shared.b16 {%0,%1,%2,%3}, [%4];"
                 : "=r"(r0), "=r"(r1), "=r"(r2), "=r"(r3) : "r"(a));
}
__device__ __forceinline__ void mma16816(float* d, unsigned a0, unsigned a1, unsigned a2, unsigned a3,
                                         unsigned b0, unsigned b1) {
    asm volatile("mma.sync.aligned.m16n8k16.row.col.f32.f16.f16.f32 "
                 "{%0,%1,%2,%3}, {%4,%5,%6,%7}, {%8,%9}, {%0,%1,%2,%3};"
                 : "+f"(d[0]), "+f"(d[1]), "+f"(d[2]), "+f"(d[3])
                 : "r"(a0), "r"(a1), "r"(a2), "r"(a3), "r"(b0), "r"(b1));
}
__device__ __forceinline__ unsigned packh2(float lo, float hi) {
    __half2 h = __floats2half2_rn(lo, hi);
    return *(unsigned*)&h;
}

// ---------------- fused BN + conv1x1, tensor-core fp16 hi/lo split + reg double-buffer ----------------
// block tile: 256 px x 64 oc; 256 threads = 8 warps; warp = 32 px (2 m16 tiles) x 64 oc
__global__ __launch_bounds__(256)
void conv1x1_tc_kernel(const float* __restrict__ src0, int C0,
                       const float* __restrict__ src1, int C1,
                       const float* __restrict__ w, const float* __restrict__ bias,
                       int Cout, int hw, float* __restrict__ out, int outStride, int relu,
                       float* __restrict__ mirror) {
    extern __shared__ char cvsm[];
    __half* xh = (__half*)cvsm;            // 32 x PADX halves
    __half* xl = xh + 32*PADX;
    __half* wh = xl + 32*PADX;             // 64 x PADK halves
    __half* wl = wh + 64*PADK;
    const int Cin = C0 + C1;
    int tid = threadIdx.x;
    int lane = tid & 31;
    int wid = tid >> 5;                    // 0..7
    int g = lane >> 2, t = lane & 3;
    int p0 = blockIdx.x * 256;
    int n = p0 / hw, hw0 = p0 % hw;
    int ot = blockIdx.y;

    float acc[2][8][4];
    #pragma unroll
    for (int mt = 0; mt < 2; mt++)
        #pragma unroll
        for (int j = 0; j < 8; j++)
            #pragma unroll
            for (int e = 0; e < 4; e++) acc[mt][j][e] = 0.f;

    float4 xv[8];
    float4 wv[2];
    float  sS[8], sT[8];

    // ---- prologue: load slab 0 into registers ----
    #pragma unroll
    for (int it = 0; it < 8; it++) {
        int idx = tid + it * 256;
        int c = idx >> 6, p4 = idx & 63;
        const float* src = (c < C0) ? (src0 + (size_t)(n*C0 + c) * hw)
                                    : (src1 + (size_t)(n*C1 + (c - C0)) * hw);
        xv[it] = *(const float4*)(src + hw0 + p4*4);
        sS[it] = g_S[c]; sT[it] = g_T[c];
    }
    #pragma unroll
    for (int it = 0; it < 2; it++) {
        int idx = tid + it * 256;
        int o = idx >> 3, k4 = idx & 7;
        int oc = ot*64 + o;
        if (oc < Cout) wv[it] = *(const float4*)(w + (size_t)oc * Cin + k4*4);
        else { wv[it].x = 0.f; wv[it].y = 0.f; wv[it].z = 0.f; wv[it].w = 0.f; }
    }

    for (int cc = 0; cc < Cin; cc += 32) {
        // ---- convert registers -> smem ----
        #pragma unroll
        for (int it = 0; it < 8; it++) {
            int idx = tid + it * 256;
            int c = idx >> 6, p4 = idx & 63;
            float s = sS[it], tt = sT[it];
            float f0 = xv[it].x*s + tt, f1 = xv[it].y*s + tt;
            float f2 = xv[it].z*s + tt, f3 = xv[it].w*s + tt;
            __half h0 = __float2half_rn(f0), h1 = __float2half_rn(f1);
            __half h2 = __float2half_rn(f2), h3 = __float2half_rn(f3);
            __half l0 = __float2half_rn(f0 - __half2float(h0));
            __half l1 = __float2half_rn(f1 - __half2float(h1));
            __half l2 = __float2half_rn(f2 - __half2float(h2));
            __half l3 = __float2half_rn(f3 - __half2float(h3));
            int off = c*PADX + p4*4;
            *(__half2*)&xh[off]     = __halves2half2(h0, h1);
            *(__half2*)&xh[off + 2] = __halves2half2(h2, h3);
            *(__half2*)&xl[off]     = __halves2half2(l0, l1);
            *(__half2*)&xl[off + 2] = __halves2half2(l2, l3);
        }
        #pragma unroll
        for (int it = 0; it < 2; it++) {
            int idx = tid + it * 256;
            int o = idx >> 3, k4 = idx & 7;
            float4 v = wv[it];
            __half h0 = __float2half_rn(v.x), h1 = __float2half_rn(v.y);
            __half h2 = __float2half_rn(v.z), h3 = __float2half_rn(v.w);
            __half l0 = __float2half_rn(v.x - __half2float(h0));
            __half l1 = __float2half_rn(v.y - __half2float(h1));
            __half l2 = __float2half_rn(v.z - __half2float(h2));
            __half l3 = __float2half_rn(v.w - __half2float(h3));
            int off = o*PADK + k4*4;
            *(__half2*)&wh[off]     = __halves2half2(h0, h1);
            *(__half2*)&wh[off + 2] = __halves2half2(h2, h3);
            *(__half2*)&wl[off]     = __halves2half2(l0, l1);
            *(__half2*)&wl[off + 2] = __halves2half2(l2, l3);
        }
        __syncthreads();

        // ---- issue next slab's loads (overlap with MMAs below) ----
        int nc = cc + 32;
        if (nc < Cin) {
            #pragma unroll
            for (int it = 0; it < 8; it++) {
                int idx = tid + it * 256;
                int c = nc + (idx >> 6); int p4 = idx & 63;
                const float* src = (c < C0) ? (src0 + (size_t)(n*C0 + c) * hw)
                                            : (src1 + (size_t)(n*C1 + (c - C0)) * hw);
                xv[it] = *(const float4*)(src + hw0 + p4*4);
                sS[it] = g_S[c]; sT[it] = g_T[c];
            }
            #pragma unroll
            for (int it = 0; it < 2; it++) {
                int idx = tid + it * 256;
                int o = idx >> 3, k4 = idx & 7;
                int oc = ot*64 + o;
                if (oc < Cout) wv[it] = *(const float4*)(w + (size_t)oc * Cin + nc + k4*4);
                else { wv[it].x = 0.f; wv[it].y = 0.f; wv[it].z = 0.f; wv[it].w = 0.f; }
            }
        }

        // ---- MMAs on current slab ----
        #pragma unroll
        for (int kk = 0; kk < 32; kk += 16) {
            unsigned ah[2][4], al[2][4];
            #pragma unroll
            for (int mt = 0; mt < 2; mt++) {
                int m0 = wid*32 + mt*16;
                const __half* pa = xh + (kk + (lane & 7) + ((lane >> 4) << 3))*PADX
                                      + m0 + (((lane >> 3) & 1) << 3);
                const __half* pb = xl + (kk + (lane & 7) + ((lane >> 4) << 3))*PADX
                                      + m0 + (((lane >> 3) & 1) << 3);
                ldm4t(ah[mt][0], ah[mt][1], ah[mt][2], ah[mt][3], pa);
                ldm4t(al[mt][0], al[mt][1], al[mt][2], al[mt][3], pb);
            }
            #pragma unroll
            for (int j = 0; j < 8; j++) {
                int bo = (j*8 + g)*PADK + kk + 2*t;
                unsigned bh0 = *(const unsigned*)(wh + bo);
                unsigned bh1 = *(const unsigned*)(wh + bo + 8);
                unsigned bl0 = *(const unsigned*)(wl + bo);
                unsigned bl1 = *(const unsigned*)(wl + bo + 8);
                #pragma unroll
                for (int mt = 0; mt < 2; mt++) {
                    mma16816(acc[mt][j], ah[mt][0], ah[mt][1], ah[mt][2], ah[mt][3], bh0, bh1);
                    mma16816(acc[mt][j], ah[mt][0], ah[mt][1], ah[mt][2], ah[mt][3], bl0, bl1);
                    mma16816(acc[mt][j], al[mt][0], al[mt][1], al[mt][2], al[mt][3], bh0, bh1);
                }
            }
        }
        __syncthreads();
    }

    // ---- writeback ----
    #pragma unroll
    for (int mt = 0; mt < 2; mt++) {
        int pr = wid*32 + mt*16 + g;
        #pragma unroll
        for (int j = 0; j < 8; j++) {
            int o = ot*64 + j*8 + 2*t;
            if (o < Cout) {
                float bv = bias[o];
                float v0 = acc[mt][j][0] + bv;
                float v2 = acc[mt][j][2] + bv;
                if (relu) { v0 = fmaxf(v0, 0.f); v2 = fmaxf(v2, 0.f); }
                float* op = out + (size_t)(n*outStride + o) * hw + hw0;
                op[pr] = v0; op[pr + 8] = v2;
                if (mirror != 0 && o >= 64) {
                    float* mp = mirror + (size_t)(n*128 + (o - 64)) * hw + hw0;
                    mp[pr] = v0; mp[pr + 8] = v2;
                }
            }
            if (o + 1 < Cout) {
                float bv = bias[o+1];
                float v1 = acc[mt][j][1] + bv;
                float v3 = acc[mt][j][3] + bv;
                if (relu) { v1 = fmaxf(v1, 0.f); v3 = fmaxf(v3, 0.f); }
                float* op = out + (size_t)(n*outStride + o + 1) * hw + hw0;
                op[pr] = v1; op[pr + 8] = v3;
                if (mirror != 0 && o + 1 >= 64) {
                    float* mp = mirror + (size_t)(n*128 + (o + 1 - 64)) * hw + hw0;
                    mp[pr] = v1; mp[pr + 8] = v3;
                }
            }
        }
    }
}

// ---------------- align-corners bilinear resize ----------------
__global__ void resize_kernel(const float* __restrict__ src, float* __restrict__ dst,
                              int C, int Hs, int Ws, int Hd, int Wd) {
    int idx = blockIdx.x * blockDim.x + threadIdx.x;
    int total = NB * C * Hd * Wd;
    if (idx >= total) return;
    int x = idx % Wd; int y = (idx / Wd) % Hd; int nc = idx / (Wd * Hd);
    float sy = y * (float)(Hs - 1) / (float)(Hd - 1);
    float sx = x * (float)(Ws - 1) / (float)(Wd - 1);
    int y0 = (int)floorf(sy); int x0 = (int)floorf(sx);
    float wy = sy - y0, wx = sx - x0;
    int y1 = min(y0 + 1, Hs - 1), x1 = min(x0 + 1, Ws - 1);
    const float* p = src + (size_t)nc * Hs * Ws;
    float v00 = p[y0*Ws + x0], v01 = p[y0*Ws + x1];
    float v10 = p[y1*Ws + x0], v11 = p[y1*Ws + x1];
    float top = v00 + (v10 - v00) * wy;
    float bot = v01 + (v11 - v01) * wy;
    dst[idx] = top + (bot - top) * wx;
}

// ---------------- grid_sample (border) of temporal_kv ----------------
__global__ void warp_kernel(const float* __restrict__ temporal, const float* __restrict__ mv) {
    int p = blockIdx.x * blockDim.x + threadIdx.x;
    if (p >= NB * HW) return;
    int chunk = blockIdx.y;             // 0..15
    int n = p / HW; int hw = p % HW;
    int h = hw >> 8; int w = hw & 255;
    float xsv = -1.f + 2.f * w / (float)(WW - 1);
    float ysv = -1.f + 2.f * h / (float)(HH - 1);
    float gx = mv[(size_t)(n*2 + 0) * HW + hw] * (2.f / WW) + xsv;
    float gy = ysv - mv[(size_t)(n*2 + 1) * HW + hw] * (2.f / HH);
    float ix = fminf(fmaxf((gx + 1.f) * 0.5f * (WW - 1), 0.f), (float)(WW - 1));
    float iy = fminf(fmaxf((gy + 1.f) * 0.5f * (HH - 1), 0.f), (float)(HH - 1));
    int x0 = (int)floorf(ix), y0 = (int)floorf(iy);
    float wx = ix - x0, wy = iy - y0;
    int x1 = min(x0 + 1, WW - 1), y1 = min(y0 + 1, HH - 1);
    float w00 = (1.f-wy)*(1.f-wx), w01 = (1.f-wy)*wx, w10 = wy*(1.f-wx), w11 = wy*wx;
    int i00 = y0*WW + x0, i01 = y0*WW + x1, i10 = y1*WW + x0, i11 = y1*WW + x1;
    const float* base = temporal + (size_t)(n*128 + chunk*8) * HW;
    float* dst = &g_WARP[(size_t)(n*128 + chunk*8) * HW + hw];
    #pragma unroll
    for (int c = 0; c < 8; c++) {
        const float* pp = base + (size_t)c * HW;
        dst[(size_t)c * HW] = pp[i00]*w00 + pp[i01]*w01 + pp[i10]*w10 + pp[i11]*w11;
    }
}

// ---------------- copy ds_latent tail channels into g_DSS ----------------
__global__ void dscopy_kernel(const float* __restrict__ dsl) {
    int idx = blockIdx.x * blockDim.x + threadIdx.x;
    if (idx >= NB * 3 * DHW) return;
    int n = idx / (3 * DHW); int rem = idx % (3 * DHW);
    int c = rem / DHW; int i = rem % DHW;
    g_DSS[(size_t)(n*128 + 125 + c) * DHW + i] = dsl[(size_t)(n*96 + 93 + c) * DHW + i];
}

// ---------------- windowed attention: tensor-core fp16 QK/PV, fp32 LN+softmax ----------------
__global__ __launch_bounds__(128)
void attn_kernel(const float* __restrict__ radiance,
                 const float* __restrict__ qg, const float* __restrict__ qb,
                 const float* __restrict__ kg, const float* __restrict__ kb,
                 const float* __restrict__ vg, const float* __restrict__ vb) {
    extern __shared__ char smraw[];
    __half* Qh = (__half*)smraw;           // 64 x PAD
    __half* Kh = Qh + 64*PAD;
    __half* Vh = Kh + 64*PAD;
    float* Raw0 = (float*)(Vh + 64*PAD);   // 64 x 65
    float* Raw1 = Raw0 + 64*65;

    int tid = threadIdx.x;
    int lane = tid & 31;
    int w = tid >> 5;
    int n = blockIdx.x >> 10;
    int l = blockIdx.x & 1023;
    int by = (l >> 5) * 8, bx = (l & 31) * 8;

    for (int idx = tid; idx < 4096; idx += 128) {
        int r = idx & 63, c = idx >> 6;
        int y = by + (r >> 3), x = bx + (r & 7);
        Raw0[r*65 + c] = g_SU[(size_t)(n*189 + c) * HW + y*256 + x];
    }
    __syncthreads();
    if (tid < 64) {
        const float* row = Raw0 + tid*65;
        float mu = 0.f;
        #pragma unroll 8
        for (int c = 0; c < 64; c++) mu += row[c];
        mu *= (1.f/64.f);
        float var = 0.f;
        #pragma unroll 8
        for (int c = 0; c < 64; c++) { float d = row[c] - mu; var += d*d; }
        float rs = rsqrtf(var * (1.f/64.f) + 1e-5f);
        #pragma unroll 8
        for (int c = 0; c < 64; c++)
            Qh[tid*PAD + c] = __float2half_rn(((row[c] - mu) * rs * qg[c] + qb[c]) * 0.125f);
    }
    __syncthreads();

    unsigned qa[4][4];
    {
        int q0 = w * 16;
        #pragma unroll
        for (int kk = 0; kk < 4; kk++) {
            const __half* p = Qh + (q0 + (lane & 15))*PAD + kk*16 + ((lane >> 4) << 3);
            ldm4(qa[kk][0], qa[kk][1], qa[kk][2], qa[kk][3], p);
        }
    }

    float o[8][4];
    #pragma unroll
    for (int t = 0; t < 8; t++)
        #pragma unroll
        for (int j = 0; j < 4; j++) o[t][j] = 0.f;
    float m0 = -1e30f, m1 = -1e30f, l0 = 0.f, l1 = 0.f;

    for (int ci = 0; ci < 6; ci++) {
        for (int idx = tid; idx < 4096; idx += 128) {
            int r = idx & 63, c = idx >> 6;
            float kvv, vvv;
            if (ci < 4) {
                int ky = ci*4 + (r >> 4), kx = r & 15;
                int y = by - 4 + ky, x = bx - 4 + kx;
                if (y >= 0 && y < 256 && x >= 0 && x < 256) {
                    int off = y*256 + x;
                    kvv = g_SU[(size_t)(n*189 + 64 + c) * HW + off];
                    vvv = (c < 61) ? g_SU[(size_t)(n*189 + 128 + c) * HW + off]
                                   : radiance[(size_t)(n*3 + c - 61) * HW + off];
                } else { kvv = 0.f; vvv = 0.f; }
            } else {
                int y = by + (r >> 3), x = bx + (r & 7);
                int off = y*256 + x;
                const float* src = (ci == 4) ? g_WARP : g_DSE;
                kvv = src[(size_t)(n*128 + c) * HW + off];
                vvv = src[(size_t)(n*128 + 64 + c) * HW + off];
            }
            Raw0[r*65 + c] = kvv; Raw1[r*65 + c] = vvv;
        }
        __syncthreads();
        if (tid < 64) {
            const float* row = Raw0 + tid*65;
            float mu = 0.f;
            #pragma unroll 8
            for (int c = 0; c < 64; c++) mu += row[c];
            mu *= (1.f/64.f);
            float var = 0.f;
            #pragma unroll 8
            for (int c = 0; c < 64; c++) { float d = row[c] - mu; var += d*d; }
            float rs = rsqrtf(var * (1.f/64.f) + 1e-5f);
            #pragma unroll 8
            for (int c = 0; c < 64; c++)
                Kh[tid*PAD + c] = __float2half_rn((row[c] - mu) * rs * kg[c] + kb[c]);
        } else {
            int r = tid - 64;
            const float* row = Raw1 + r*65;
            float mu = 0.f;
            for (int c = 0; c < 61; c++) mu += row[c];
            mu *= (1.f/61.f);
            float var = 0.f;
            for (int c = 0; c < 61; c++) { float d = row[c] - mu; var += d*d; }
            float rs = rsqrtf(var * (1.f/61.f) + 1e-5f);
            for (int c = 0; c < 61; c++)
                Vh[r*PAD + c] = __float2half_rn((row[c] - mu) * rs * vg[c] + vb[c]);
            for (int c = 61; c < 64; c++)
                Vh[r*PAD + c] = __float2half_rn(row[c]);
        }
        __syncthreads();

        float s[8][4];
        #pragma unroll
        for (int t = 0; t < 8; t++)
            #pragma unroll
            for (int j = 0; j < 4; j++) s[t][j] = 0.f;
        #pragma unroll
        for (int kk = 0; kk < 4; kk++) {
            #pragma unroll
            for (int np = 0; np < 4; np++) {
                unsigned b0, b1, b2, b3;
                const __half* p = Kh + (np*16 + (lane & 7) + ((lane >> 4) << 3))*PAD
                                     + kk*16 + (((lane >> 3) & 1) << 3);
                ldm4(b0, b1, b2, b3, p);
                mma16816(s[2*np],   qa[kk][0], qa[kk][1], qa[kk][2], qa[kk][3], b0, b1);
                mma16816(s[2*np+1], qa[kk][0], qa[kk][1], qa[kk][2], qa[kk][3], b2, b3);
            }
        }

        float mx0 = -1e30f, mx1 = -1e30f;
        #pragma unroll
        for (int t = 0; t < 8; t++) {
            mx0 = fmaxf(mx0, fmaxf(s[t][0], s[t][1]));
            mx1 = fmaxf(mx1, fmaxf(s[t][2], s[t][3]));
        }
        mx0 = fmaxf(mx0, __shfl_xor_sync(0xffffffffu, mx0, 1));
        mx0 = fmaxf(mx0, __shfl_xor_sync(0xffffffffu, mx0, 2));
        mx1 = fmaxf(mx1, __shfl_xor_sync(0xffffffffu, mx1, 1));
        mx1 = fmaxf(mx1, __shfl_xor_sync(0xffffffffu, mx1, 2));
        float mn0 = fmaxf(m0, mx0), mn1 = fmaxf(m1, mx1);
        float corr0 = __expf(m0 - mn0), corr1 = __expf(m1 - mn1);
        m0 = mn0; m1 = mn1;
        float sum0 = 0.f, sum1 = 0.f;
        #pragma unroll
        for (int t = 0; t < 8; t++) {
            s[t][0] = __expf(s[t][0] - m0); s[t][1] = __expf(s[t][1] - m0);
            s[t][2] = __expf(s[t][2] - m1); s[t][3] = __expf(s[t][3] - m1);
            sum0 += s[t][0] + s[t][1];
            sum1 += s[t][2] + s[t][3];
        }
        sum0 += __shfl_xor_sync(0xffffffffu, sum0, 1);
        sum0 += __shfl_xor_sync(0xffffffffu, sum0, 2);
        sum1 += __shfl_xor_sync(0xffffffffu, sum1, 1);
        sum1 += __shfl_xor_sync(0xffffffffu, sum1, 2);
        l0 = l0 * corr0 + sum0;
        l1 = l1 * corr1 + sum1;
        #pragma unroll
        for (int t = 0; t < 8; t++) {
            o[t][0] *= corr0; o[t][1] *= corr0;
            o[t][2] *= corr1; o[t][3] *= corr1;
        }

        #pragma unroll
        for (int jp = 0; jp < 4; jp++) {
            unsigned a0 = packh2(s[2*jp][0],   s[2*jp][1]);
            unsigned a1 = packh2(s[2*jp][2],   s[2*jp][3]);
            unsigned a2 = packh2(s[2*jp+1][0], s[2*jp+1][1]);
            unsigned a3 = packh2(s[2*jp+1][2], s[2*jp+1][3]);
            #pragma unroll
            for (int np = 0; np < 4; np++) {
                unsigned b0, b1, b2, b3;
                const __half* p = Vh + (jp*16 + (lane & 7) + (((lane >> 3) & 1) << 3))*PAD
                                     + np*16 + ((lane >> 4) << 3);
                ldm4t(b0, b1, b2, b3, p);
                mma16816(o[2*np],   a0, a1, a2, a3, b0, b1);
                mma16816(o[2*np+1], a0, a1, a2, a3, b2, b3);
            }
        }
        __syncthreads();
    }

    float inv0 = 1.f / l0, inv1 = 1.f / l1;
    int r0 = w*16 + (lane >> 2);
    int r1 = r0 + 8;
    int y0 = by + (r0 >> 3), x0 = bx + (r0 & 7);
    int y1 = by + (r1 >> 3), x1 = bx + (r1 & 7);
    #pragma unroll
    for (int t = 0; t < 8; t++) {
        int c = t*8 + 2*(lane & 3);
        g_ATT[(size_t)(n*64 + c    ) * HW + y0*256 + x0] = o[t][0] * inv0;
        g_ATT[(size_t)(n*64 + c + 1) * HW + y0*256 + x0] = o[t][1] * inv0;
        g_ATT[(size_t)(n*64 + c    ) * HW + y1*256 + x1] = o[t][2] * inv1;
        g_ATT[(size_t)(n*64 + c + 1) * HW + y1*256 + x1] = o[t][3] * inv1;
    }
}

// ---------------- output tail: only the g_ATT-sourced channels (float4) ----------------
__global__ void tail_kernel(float* __restrict__ out) {
    int idx = blockIdx.x * blockDim.x + threadIdx.x;
    const int HW4 = HW / 4;
    if (idx >= NB * 3 * HW4) return;
    int n = idx / (3 * HW4); int rem = idx % (3 * HW4);
    int c = rem / HW4; int hw4 = rem % HW4;
    float4 v = *(const float4*)&g_ATT[(size_t)(n*64 + 61 + c) * HW + hw4*4];
    *(float4*)&out[(size_t)(n*64 + 61 + c) * HW + hw4*4] = v;
    *(float4*)&out[(size_t)NB*64*HW + (size_t)(n*128 + 125 + c) * HW + hw4*4] = v;
}

// ---------------- host launcher ----------------
extern "C" void kernel_launch(void* const* d_in, const int* in_sizes, int n_in,
                              void* d_out, int out_size) {
    const float* radiance = (const float*)d_in[0];
    const float* skip     = (const float*)d_in[1];
    const float* dsl      = (const float*)d_in[2];
    const float* temporal = (const float*)d_in[3];
    const float* mv       = (const float*)d_in[4];
    const float* su_bn_g  = (const float*)d_in[5];
    const float* su_bn_b  = (const float*)d_in[6];
    const float* su_w     = (const float*)d_in[7];
    const float* su_b     = (const float*)d_in[8];
    const float* ds_bn_g  = (const float*)d_in[9];
    const float* ds_bn_b  = (const float*)d_in[10];
    const float* ds_w     = (const float*)d_in[11];
    const float* ds_b     = (const float*)d_in[12];
    const float* qln_g    = (const float*)d_in[13];
    const float* qln_b    = (const float*)d_in[14];
    const float* kln_g    = (const float*)d_in[15];
    const float* kln_b    = (const float*)d_in[16];
    const float* vln_g    = (const float*)d_in[17];
    const float* vln_b    = (const float*)d_in[18];
    const float* f1_g     = (const float*)d_in[19];
    const float* f1_b     = (const float*)d_in[20];
    const float* w1       = (const float*)d_in[21];
    const float* b1       = (const float*)d_in[22];
    const float* f2_g     = (const float*)d_in[23];
    const float* f2_b     = (const float*)d_in[24];
    const float* w2       = (const float*)d_in[25];
    const float* b2       = (const float*)d_in[26];
    float* out = (float*)d_out;

    float *dUS, *dSU, *dDSS, *dDSE, *dATT, *dH1;
    cudaGetSymbolAddress((void**)&dUS,  g_US);
    cudaGetSymbolAddress((void**)&dSU,  g_SU);
    cudaGetSymbolAddress((void**)&dDSS, g_DSS);
    cudaGetSymbolAddress((void**)&dDSE, g_DSE);
    cudaGetSymbolAddress((void**)&dATT, g_ATT);
    cudaGetSymbolAddress((void**)&dH1,  g_H1);

    float* outTemporal = out + (size_t)NB*64*HW;

    const int ATTN_SMEM = 3*64*PAD*2 + 2*64*65*4;   // 60928 B
    cudaFuncSetAttribute(attn_kernel, cudaFuncAttributeMaxDynamicSharedMemorySize, ATTN_SMEM);
    const int CONV_SMEM = (2*32*PADX + 2*64*PADK) * 2;  // 44032 B

    // 1. us = resize(ds_latent, 128->256)
    resize_kernel<<<(NB*96*HW + 255)/256, 256>>>(dsl, dUS, 96, 128, 128, 256, 256);
    // 2-3. su BN stats + conv1x1 -> su_emb (189 ch); ch 64..188 mirrored to temporal_out
    bn_stats1_kernel<<<dim3(192, NSLAB), 256>>>(skip, 96, dUS, 96, HW);
    bn_stats2_kernel<<<192, 32>>>(su_bn_g, su_bn_b, HW);
    conv1x1_tc_kernel<<<dim3((NB*HW)/256, 3), 256, CONV_SMEM>>>(skip, 96, dUS, 96, su_w, su_b, 189, HW, dSU, 189, 0, outTemporal);
    // 4. warped temporal kv
    warp_kernel<<<dim3((NB*HW + 255)/256, 16), 256>>>(temporal, mv);
    // 5-8. ds embedding
    bn_stats1_kernel<<<dim3(96, NSLAB), 256>>>(dsl, 96, (const float*)0, 0, DHW);
    bn_stats2_kernel<<<96, 32>>>(ds_bn_g, ds_bn_b, DHW);
    conv1x1_tc_kernel<<<dim3((NB*DHW)/256, 2), 256, CONV_SMEM>>>(dsl, 96, (const float*)0, 0, ds_w, ds_b, 125, DHW, dDSS, 128, 0, (float*)0);
    dscopy_kernel<<<(NB*3*DHW + 255)/256, 256>>>(dsl);
    resize_kernel<<<(NB*128*HW + 255)/256, 256>>>(dDSS, dDSE, 128, 128, 128, 256, 256);
    // 9. attention (tensor-core)
    attn_kernel<<<NB*1024, 128, ATTN_SMEM>>>(radiance, qln_g, qln_b, kln_g, kln_b, vln_g, vln_b);
    // 10-13. FFN
    bn_stats1_kernel<<<dim3(64, NSLAB), 256>>>(dATT, 64, (const float*)0, 0, HW);
    bn_stats2_kernel<<<64, 32>>>(f1_g, f1_b, HW);
    conv1x1_tc_kernel<<<dim3((NB*HW)/256, 2), 256, CONV_SMEM>>>(dATT, 64, (const float*)0, 0, w1, b1, 128, HW, dH1, 128, 1, (float*)0);
    bn_stats1_kernel<<<dim3(128, NSLAB), 256>>>(dH1, 128, (const float*)0, 0, HW);
    bn_stats2_kernel<<<128, 32>>>(f2_g, f2_b, HW);
    conv1x1_tc_kernel<<<dim3((NB*HW)/256, 1), 256, CONV_SMEM>>>(dH1, 128, (const float*)0, 0, w2, b2, 61, HW, out, 64, 0, (float*)0);
    // 14. remaining tail channels (attention-sourced)
    tail_kernel<<<(NB*3*HW/4 + 255)/256, 256>>>(out);
}

// round 10
// speedup vs baseline: 4.0900x; 1.0870x over previous
#include <cuda_runtime.h>
#include <cuda_fp16.h>
#include <math.h>

#define NB 2
#define HH 256
#define WW 256
#define HW 65536
#define DHW 16384   // 128*128
#define PAD 72      // fp16 row stride for ldmatrix tiles (attention)
#define RSTR 66     // attention raw fp32 row stride (even -> float2 aligned)
#define NSLAB 16
#define PADX 264    // conv x smem row stride in halves ([k][px], 256 px + 8 pad)
#define PADK 40     // conv w smem row stride in halves ([oc][k])

// ---------------- scratch (static device allocations) ----------------
__device__ float g_US [NB*96 *HW];
__device__ float g_SU [NB*189*HW];
__device__ float g_WARP[NB*128*HW];
__device__ float g_DSS[NB*128*DHW];
__device__ float g_DSE[NB*128*HW];
__device__ float g_ATT[NB*64 *HW];
__device__ float g_H1 [NB*128*HW];
__device__ float g_S[192];
__device__ float g_T[192];
__device__ float g_PSUM[192*NSLAB];
__device__ float g_PSQ [192*NSLAB];

// ---------------- BN stats stage 1 ----------------
__global__ void bn_stats1_kernel(const float* __restrict__ src0, int C0,
                                 const float* __restrict__ src1, int C1,
                                 int hw) {
    int c = blockIdx.x;
    int slab = blockIdx.y;
    const float* base; int cs;
    if (c < C0) { base = src0 + (size_t)c * hw; cs = C0; }
    else        { base = src1 + (size_t)(c - C0) * hw; cs = C1; }
    int sl = hw / NSLAB;
    float sum = 0.f, sq = 0.f;
    for (int n = 0; n < NB; n++) {
        const float4* p = (const float4*)(base + (size_t)n * cs * hw + (size_t)slab * sl);
        int nv = sl >> 2;
        for (int i = threadIdx.x; i < nv; i += blockDim.x) {
            float4 v = p[i];
            sum += v.x + v.y + v.z + v.w;
            sq  += v.x*v.x + v.y*v.y + v.z*v.z + v.w*v.w;
        }
    }
    __shared__ float ssum[256], ssq[256];
    ssum[threadIdx.x] = sum; ssq[threadIdx.x] = sq; __syncthreads();
    for (int o = 128; o > 0; o >>= 1) {
        if (threadIdx.x < o) { ssum[threadIdx.x] += ssum[threadIdx.x+o]; ssq[threadIdx.x] += ssq[threadIdx.x+o]; }
        __syncthreads();
    }
    if (threadIdx.x == 0) {
        g_PSUM[c*NSLAB + slab] = ssum[0];
        g_PSQ [c*NSLAB + slab] = ssq[0];
    }
}

// ---------------- BN stats stage 2 ----------------
__global__ void bn_stats2_kernel(const float* __restrict__ g, const float* __restrict__ b,
                                 int hw) {
    int c = blockIdx.x;
    if (threadIdx.x == 0) {
        float sum = 0.f, sq = 0.f;
        #pragma unroll
        for (int s = 0; s < NSLAB; s++) { sum += g_PSUM[c*NSLAB + s]; sq += g_PSQ[c*NSLAB + s]; }
        float inv = 1.f / (float)(NB * hw);
        float m = sum * inv;
        float v = sq * inv - m * m;
        float s = g[c] * rsqrtf(v + 1e-5f);
        g_S[c] = s; g_T[c] = b[c] - m * s;
    }
}

// ---------------- mma helpers ----------------
__device__ __forceinline__ void ldm4(unsigned& r0, unsigned& r1, unsigned& r2, unsigned& r3,
                                     const __half* p) {
    unsigned a = (unsigned)__cvta_generic_to_shared(p);
    asm volatile("ldmatrix.sync.aligned.m8n8.x4.shared.b16 {%0,%1,%2,%3}, [%4];"
                 : "=r"(r0), "=r"(r1), "=r"(r2), "=r"(r3) : "r"(a));
}
__device__ __forceinline__ void ldm4t(unsigned& r0, unsigned& r1, unsigned& r2, unsigned& r3,
                                      const __half* p) {
    unsigned a = (unsigned)__cvta_generic_to_shared(p);
    asm volatile("ldmatrix.sync.aligned.m8n8.x4.trans.shared.b16 {%0,%1,%2,%3}, [%4];"
                 : "=r"(r0), "=r"(r1), "=r"(r2), "=r"(r3) : "r"(a));
}
__device__ __forceinline__ void mma16816(float* d, unsigned a0, unsigned a1, unsigned a2, unsigned a3,
                                         unsigned b0, unsigned b1) {
    asm volatile("mma.sync.aligned.m16n8k16.row.col.f32.f16.f16.f32 "
                 "{%0,%1,%2,%3}, {%4,%5,%6,%7}, {%8,%9}, {%0,%1,%2,%3};"
                 : "+f"(d[0]), "+f"(d[1]), "+f"(d[2]), "+f"(d[3])
                 : "r"(a0), "r"(a1), "r"(a2), "r"(a3), "r"(b0), "r"(b1));
}
__device__ __forceinline__ unsigned packh2(float lo, float hi) {
    __half2 h = __floats2half2_rn(lo, hi);
    return *(unsigned*)&h;
}

// ---------------- fused BN + conv1x1, tensor-core fp16 hi/lo split + reg double-buffer ----------------
__global__ __launch_bounds__(256)
void conv1x1_tc_kernel(const float* __restrict__ src0, int C0,
                       const float* __restrict__ src1, int C1,
                       const float* __restrict__ w, const float* __restrict__ bias,
                       int Cout, int hw, float* __restrict__ out, int outStride, int relu,
                       float* __restrict__ mirror) {
    extern __shared__ char cvsm[];
    __half* xh = (__half*)cvsm;            // 32 x PADX halves
    __half* xl = xh + 32*PADX;
    __half* wh = xl + 32*PADX;             // 64 x PADK halves
    __half* wl = wh + 64*PADK;
    const int Cin = C0 + C1;
    int tid = threadIdx.x;
    int lane = tid & 31;
    int wid = tid >> 5;
    int g = lane >> 2, t = lane & 3;
    int p0 = blockIdx.x * 256;
    int n = p0 / hw, hw0 = p0 % hw;
    int ot = blockIdx.y;

    float acc[2][8][4];
    #pragma unroll
    for (int mt = 0; mt < 2; mt++)
        #pragma unroll
        for (int j = 0; j < 8; j++)
            #pragma unroll
            for (int e = 0; e < 4; e++) acc[mt][j][e] = 0.f;

    float4 xv[8];
    float4 wv[2];
    float  sS[8], sT[8];

    #pragma unroll
    for (int it = 0; it < 8; it++) {
        int idx = tid + it * 256;
        int c = idx >> 6, p4 = idx & 63;
        const float* src = (c < C0) ? (src0 + (size_t)(n*C0 + c) * hw)
                                    : (src1 + (size_t)(n*C1 + (c - C0)) * hw);
        xv[it] = *(const float4*)(src + hw0 + p4*4);
        sS[it] = g_S[c]; sT[it] = g_T[c];
    }
    #pragma unroll
    for (int it = 0; it < 2; it++) {
        int idx = tid + it * 256;
        int o = idx >> 3, k4 = idx & 7;
        int oc = ot*64 + o;
        if (oc < Cout) wv[it] = *(const float4*)(w + (size_t)oc * Cin + k4*4);
        else { wv[it].x = 0.f; wv[it].y = 0.f; wv[it].z = 0.f; wv[it].w = 0.f; }
    }

    for (int cc = 0; cc < Cin; cc += 32) {
        #pragma unroll
        for (int it = 0; it < 8; it++) {
            int idx = tid + it * 256;
            int c = idx >> 6, p4 = idx & 63;
            float s = sS[it], tt = sT[it];
            float f0 = xv[it].x*s + tt, f1 = xv[it].y*s + tt;
            float f2 = xv[it].z*s + tt, f3 = xv[it].w*s + tt;
            __half h0 = __float2half_rn(f0), h1 = __float2half_rn(f1);
            __half h2 = __float2half_rn(f2), h3 = __float2half_rn(f3);
            __half l0 = __float2half_rn(f0 - __half2float(h0));
            __half l1 = __float2half_rn(f1 - __half2float(h1));
            __half l2 = __float2half_rn(f2 - __half2float(h2));
            __half l3 = __float2half_rn(f3 - __half2float(h3));
            int off = c*PADX + p4*4;
            *(__half2*)&xh[off]     = __halves2half2(h0, h1);
            *(__half2*)&xh[off + 2] = __halves2half2(h2, h3);
            *(__half2*)&xl[off]     = __halves2half2(l0, l1);
            *(__half2*)&xl[off + 2] = __halves2half2(l2, l3);
        }
        #pragma unroll
        for (int it = 0; it < 2; it++) {
            int idx = tid + it * 256;
            int o = idx >> 3, k4 = idx & 7;
            float4 v = wv[it];
            __half h0 = __float2half_rn(v.x), h1 = __float2half_rn(v.y);
            __half h2 = __float2half_rn(v.z), h3 = __float2half_rn(v.w);
            __half l0 = __float2half_rn(v.x - __half2float(h0));
            __half l1 = __float2half_rn(v.y - __half2float(h1));
            __half l2 = __float2half_rn(v.z - __half2float(h2));
            __half l3 = __float2half_rn(v.w - __half2float(h3));
            int off = o*PADK + k4*4;
            *(__half2*)&wh[off]     = __halves2half2(h0, h1);
            *(__half2*)&wh[off + 2] = __halves2half2(h2, h3);
            *(__half2*)&wl[off]     = __halves2half2(l0, l1);
            *(__half2*)&wl[off + 2] = __halves2half2(l2, l3);
        }
        __syncthreads();

        int nc = cc + 32;
        if (nc < Cin) {
            #pragma unroll
            for (int it = 0; it < 8; it++) {
                int idx = tid + it * 256;
                int c = nc + (idx >> 6); int p4 = idx & 63;
                const float* src = (c < C0) ? (src0 + (size_t)(n*C0 + c) * hw)
                                            : (src1 + (size_t)(n*C1 + (c - C0)) * hw);
                xv[it] = *(const float4*)(src + hw0 + p4*4);
                sS[it] = g_S[c]; sT[it] = g_T[c];
            }
            #pragma unroll
            for (int it = 0; it < 2; it++) {
                int idx = tid + it * 256;
                int o = idx >> 3, k4 = idx & 7;
                int oc = ot*64 + o;
                if (oc < Cout) wv[it] = *(const float4*)(w + (size_t)oc * Cin + nc + k4*4);
                else { wv[it].x = 0.f; wv[it].y = 0.f; wv[it].z = 0.f; wv[it].w = 0.f; }
            }
        }

        #pragma unroll
        for (int kk = 0; kk < 32; kk += 16) {
            unsigned ah[2][4], al[2][4];
            #pragma unroll
            for (int mt = 0; mt < 2; mt++) {
                int m0 = wid*32 + mt*16;
                const __half* pa = xh + (kk + (lane & 7) + ((lane >> 4) << 3))*PADX
                                      + m0 + (((lane >> 3) & 1) << 3);
                const __half* pb = xl + (kk + (lane & 7) + ((lane >> 4) << 3))*PADX
                                      + m0 + (((lane >> 3) & 1) << 3);
                ldm4t(ah[mt][0], ah[mt][1], ah[mt][2], ah[mt][3], pa);
                ldm4t(al[mt][0], al[mt][1], al[mt][2], al[mt][3], pb);
            }
            #pragma unroll
            for (int j = 0; j < 8; j++) {
                int bo = (j*8 + g)*PADK + kk + 2*t;
                unsigned bh0 = *(const unsigned*)(wh + bo);
                unsigned bh1 = *(const unsigned*)(wh + bo + 8);
                unsigned bl0 = *(const unsigned*)(wl + bo);
                unsigned bl1 = *(const unsigned*)(wl + bo + 8);
                #pragma unroll
                for (int mt = 0; mt < 2; mt++) {
                    mma16816(acc[mt][j], ah[mt][0], ah[mt][1], ah[mt][2], ah[mt][3], bh0, bh1);
                    mma16816(acc[mt][j], ah[mt][0], ah[mt][1], ah[mt][2], ah[mt][3], bl0, bl1);
                    mma16816(acc[mt][j], al[mt][0], al[mt][1], al[mt][2], al[mt][3], bh0, bh1);
                }
            }
        }
        __syncthreads();
    }

    #pragma unroll
    for (int mt = 0; mt < 2; mt++) {
        int pr = wid*32 + mt*16 + g;
        #pragma unroll
        for (int j = 0; j < 8; j++) {
            int o = ot*64 + j*8 + 2*t;
            if (o < Cout) {
                float bv = bias[o];
                float v0 = acc[mt][j][0] + bv;
                float v2 = acc[mt][j][2] + bv;
                if (relu) { v0 = fmaxf(v0, 0.f); v2 = fmaxf(v2, 0.f); }
                float* op = out + (size_t)(n*outStride + o) * hw + hw0;
                op[pr] = v0; op[pr + 8] = v2;
                if (mirror != 0 && o >= 64) {
                    float* mp = mirror + (size_t)(n*128 + (o - 64)) * hw + hw0;
                    mp[pr] = v0; mp[pr + 8] = v2;
                }
            }
            if (o + 1 < Cout) {
                float bv = bias[o+1];
                float v1 = acc[mt][j][1] + bv;
                float v3 = acc[mt][j][3] + bv;
                if (relu) { v1 = fmaxf(v1, 0.f); v3 = fmaxf(v3, 0.f); }
                float* op = out + (size_t)(n*outStride + o + 1) * hw + hw0;
                op[pr] = v1; op[pr + 8] = v3;
                if (mirror != 0 && o + 1 >= 64) {
                    float* mp = mirror + (size_t)(n*128 + (o + 1 - 64)) * hw + hw0;
                    mp[pr] = v1; mp[pr + 8] = v3;
                }
            }
        }
    }
}

// ---------------- align-corners bilinear resize ----------------
__global__ void resize_kernel(const float* __restrict__ src, float* __restrict__ dst,
                              int C, int Hs, int Ws, int Hd, int Wd) {
    int idx = blockIdx.x * blockDim.x + threadIdx.x;
    int total = NB * C * Hd * Wd;
    if (idx >= total) return;
    int x = idx % Wd; int y = (idx / Wd) % Hd; int nc = idx / (Wd * Hd);
    float sy = y * (float)(Hs - 1) / (float)(Hd - 1);
    float sx = x * (float)(Ws - 1) / (float)(Wd - 1);
    int y0 = (int)floorf(sy); int x0 = (int)floorf(sx);
    float wy = sy - y0, wx = sx - x0;
    int y1 = min(y0 + 1, Hs - 1), x1 = min(x0 + 1, Ws - 1);
    const float* p = src + (size_t)nc * Hs * Ws;
    float v00 = p[y0*Ws + x0], v01 = p[y0*Ws + x1];
    float v10 = p[y1*Ws + x0], v11 = p[y1*Ws + x1];
    float top = v00 + (v10 - v00) * wy;
    float bot = v01 + (v11 - v01) * wy;
    dst[idx] = top + (bot - top) * wx;
}

// ---------------- grid_sample (border) of temporal_kv ----------------
__global__ void warp_kernel(const float* __restrict__ temporal, const float* __restrict__ mv) {
    int p = blockIdx.x * blockDim.x + threadIdx.x;
    if (p >= NB * HW) return;
    int chunk = blockIdx.y;             // 0..15
    int n = p / HW; int hw = p % HW;
    int h = hw >> 8; int w = hw & 255;
    float xsv = -1.f + 2.f * w / (float)(WW - 1);
    float ysv = -1.f + 2.f * h / (float)(HH - 1);
    float gx = mv[(size_t)(n*2 + 0) * HW + hw] * (2.f / WW) + xsv;
    float gy = ysv - mv[(size_t)(n*2 + 1) * HW + hw] * (2.f / HH);
    float ix = fminf(fmaxf((gx + 1.f) * 0.5f * (WW - 1), 0.f), (float)(WW - 1));
    float iy = fminf(fmaxf((gy + 1.f) * 0.5f * (HH - 1), 0.f), (float)(HH - 1));
    int x0 = (int)floorf(ix), y0 = (int)floorf(iy);
    float wx = ix - x0, wy = iy - y0;
    int x1 = min(x0 + 1, WW - 1), y1 = min(y0 + 1, HH - 1);
    float w00 = (1.f-wy)*(1.f-wx), w01 = (1.f-wy)*wx, w10 = wy*(1.f-wx), w11 = wy*wx;
    int i00 = y0*WW + x0, i01 = y0*WW + x1, i10 = y1*WW + x0, i11 = y1*WW + x1;
    const float* base = temporal + (size_t)(n*128 + chunk*8) * HW;
    float* dst = &g_WARP[(size_t)(n*128 + chunk*8) * HW + hw];
    #pragma unroll
    for (int c = 0; c < 8; c++) {
        const float* pp = base + (size_t)c * HW;
        dst[(size_t)c * HW] = pp[i00]*w00 + pp[i01]*w01 + pp[i10]*w10 + pp[i11]*w11;
    }
}

// ---------------- copy ds_latent tail channels into g_DSS ----------------
__global__ void dscopy_kernel(const float* __restrict__ dsl) {
    int idx = blockIdx.x * blockDim.x + threadIdx.x;
    if (idx >= NB * 3 * DHW) return;
    int n = idx / (3 * DHW); int rem = idx % (3 * DHW);
    int c = rem / DHW; int i = rem % DHW;
    g_DSS[(size_t)(n*128 + 125 + c) * DHW + i] = dsl[(size_t)(n*96 + 93 + c) * DHW + i];
}

// ---------------- warp tree-reduce of (sum, sumsq) ----------------
__device__ __forceinline__ void warp_red2(float& s, float& q) {
    #pragma unroll
    for (int off = 16; off > 0; off >>= 1) {
        s += __shfl_xor_sync(0xffffffffu, s, off);
        q += __shfl_xor_sync(0xffffffffu, q, off);
    }
}

// ---------------- windowed attention: tensor-core fp16 QK/PV, warp-coop LN ----------------
__global__ __launch_bounds__(128)
void attn_kernel(const float* __restrict__ radiance,
                 const float* __restrict__ qg, const float* __restrict__ qb,
                 const float* __restrict__ kg, const float* __restrict__ kb,
                 const float* __restrict__ vg, const float* __restrict__ vb) {
    extern __shared__ char smraw[];
    __half* Qh = (__half*)smraw;           // 64 x PAD
    __half* Kh = Qh + 64*PAD;
    __half* Vh = Kh + 64*PAD;
    float* Raw0 = (float*)(Vh + 64*PAD);   // 64 x RSTR
    float* Raw1 = Raw0 + 64*RSTR;

    int tid = threadIdx.x;
    int lane = tid & 31;
    int w = tid >> 5;
    int n = blockIdx.x >> 10;
    int l = blockIdx.x & 1023;
    int by = (l >> 5) * 8, bx = (l & 31) * 8;
    int cch = 2*lane;                      // this lane's channel pair for LN

    // ---- gather Q (float4 quads) ----
    #pragma unroll
    for (int it = 0; it < 8; it++) {
        int idx = tid + it * 128;          // 0..1023
        int c = idx >> 4, q = idx & 15;
        int y = by + (q >> 1), x = bx + (q & 1)*4;
        int r0 = 4*q;
        float4 v = *(const float4*)&g_SU[(size_t)(n*189 + c) * HW + y*256 + x];
        Raw0[(r0  )*RSTR + c] = v.x;
        Raw0[(r0+1)*RSTR + c] = v.y;
        Raw0[(r0+2)*RSTR + c] = v.z;
        Raw0[(r0+3)*RSTR + c] = v.w;
    }
    __syncthreads();
    // ---- Q LN: warp-cooperative, 16 rows per warp ----
    {
        float gq0 = qg[cch], gq1 = qg[cch+1], bq0 = qb[cch], bq1 = qb[cch+1];
        #pragma unroll
        for (int rr = 0; rr < 16; rr++) {
            int r = w*16 + rr;
            float2 v = *(const float2*)&Raw0[r*RSTR + cch];
            float s = v.x + v.y, q2 = v.x*v.x + v.y*v.y;
            warp_red2(s, q2);
            float mu = s * (1.f/64.f);
            float var = q2 * (1.f/64.f) - mu*mu;
            float rs = rsqrtf(var + 1e-5f);
            *(__half2*)&Qh[r*PAD + cch] = __floats2half2_rn(
                ((v.x - mu) * rs * gq0 + bq0) * 0.125f,
                ((v.y - mu) * rs * gq1 + bq1) * 0.125f);
        }
    }
    __syncthreads();

    unsigned qa[4][4];
    {
        int q0 = w * 16;
        #pragma unroll
        for (int kk = 0; kk < 4; kk++) {
            const __half* p = Qh + (q0 + (lane & 15))*PAD + kk*16 + ((lane >> 4) << 3);
            ldm4(qa[kk][0], qa[kk][1], qa[kk][2], qa[kk][3], p);
        }
    }

    float o[8][4];
    #pragma unroll
    for (int t = 0; t < 8; t++)
        #pragma unroll
        for (int j = 0; j < 4; j++) o[t][j] = 0.f;
    float m0 = -1e30f, m1 = -1e30f, l0 = 0.f, l1 = 0.f;

    float gk0 = kg[cch], gk1 = kg[cch+1], bk0 = kb[cch], bk1 = kb[cch+1];
    float gv0 = (cch   < 61) ? vg[cch]   : 0.f;
    float gv1 = (cch+1 < 61) ? vg[cch+1] : 0.f;
    float bv0 = (cch   < 61) ? vb[cch]   : 0.f;
    float bv1 = (cch+1 < 61) ? vb[cch+1] : 0.f;

    for (int ci = 0; ci < 6; ci++) {
        // ---- gather K/V chunk (float4 quads) ----
        if (ci < 4) {
            #pragma unroll
            for (int it = 0; it < 8; it++) {
                int idx = tid + it * 128;      // 0..1023
                int c = idx >> 4, q = idx & 15;
                int ky = ci*4 + (q >> 2), xq = q & 3;
                int y = by - 4 + ky, x = bx - 4 + xq*4;
                int r0 = (q >> 2)*16 + xq*4;
                float4 kv4, vv4;
                if (y >= 0 && y < 256 && x >= 0 && x < 256) {
                    int off = y*256 + x;
                    kv4 = *(const float4*)&g_SU[(size_t)(n*189 + 64 + c) * HW + off];
                    vv4 = (c < 61)
                        ? *(const float4*)&g_SU[(size_t)(n*189 + 128 + c) * HW + off]
                        : *(const float4*)&radiance[(size_t)(n*3 + c - 61) * HW + off];
                } else {
                    kv4.x = kv4.y = kv4.z = kv4.w = 0.f;
                    vv4.x = vv4.y = vv4.z = vv4.w = 0.f;
                }
                Raw0[(r0  )*RSTR + c] = kv4.x;  Raw1[(r0  )*RSTR + c] = vv4.x;
                Raw0[(r0+1)*RSTR + c] = kv4.y;  Raw1[(r0+1)*RSTR + c] = vv4.y;
                Raw0[(r0+2)*RSTR + c] = kv4.z;  Raw1[(r0+2)*RSTR + c] = vv4.z;
                Raw0[(r0+3)*RSTR + c] = kv4.w;  Raw1[(r0+3)*RSTR + c] = vv4.w;
            }
        } else {
            const float* src = (ci == 4) ? g_WARP : g_DSE;
            #pragma unroll
            for (int it = 0; it < 8; it++) {
                int idx = tid + it * 128;
                int c = idx >> 4, q = idx & 15;
                int y = by + (q >> 1), x = bx + (q & 1)*4;
                int r0 = 4*q;
                int off = y*256 + x;
                float4 kv4 = *(const float4*)&src[(size_t)(n*128 + c) * HW + off];
                float4 vv4 = *(const float4*)&src[(size_t)(n*128 + 64 + c) * HW + off];
                Raw0[(r0  )*RSTR + c] = kv4.x;  Raw1[(r0  )*RSTR + c] = vv4.x;
                Raw0[(r0+1)*RSTR + c] = kv4.y;  Raw1[(r0+1)*RSTR + c] = vv4.y;
                Raw0[(r0+2)*RSTR + c] = kv4.z;  Raw1[(r0+2)*RSTR + c] = vv4.z;
                Raw0[(r0+3)*RSTR + c] = kv4.w;  Raw1[(r0+3)*RSTR + c] = vv4.w;
            }
        }
        __syncthreads();

        // ---- K LN (warp-coop, 16 rows per warp) ----
        #pragma unroll
        for (int rr = 0; rr < 16; rr++) {
            int r = w*16 + rr;
            float2 v = *(const float2*)&Raw0[r*RSTR + cch];
            float s = v.x + v.y, q2 = v.x*v.x + v.y*v.y;
            warp_red2(s, q2);
            float mu = s * (1.f/64.f);
            float var = q2 * (1.f/64.f) - mu*mu;
            float rs = rsqrtf(var + 1e-5f);
            *(__half2*)&Kh[r*PAD + cch] = __floats2half2_rn(
                (v.x - mu) * rs * gk0 + bk0,
                (v.y - mu) * rs * gk1 + bk1);
        }
        // ---- V LN (61 channels + 3 pass-through) ----
        #pragma unroll
        for (int rr = 0; rr < 16; rr++) {
            int r = w*16 + rr;
            float2 v = *(const float2*)&Raw1[r*RSTR + cch];
            float e0 = (cch   < 61) ? v.x : 0.f;
            float e1 = (cch+1 < 61) ? v.y : 0.f;
            float s = e0 + e1, q2 = e0*e0 + e1*e1;
            warp_red2(s, q2);
            float mu = s * (1.f/61.f);
            float var = q2 * (1.f/61.f) - mu*mu;
            float rs = rsqrtf(var + 1e-5f);
            float o0 = (cch   < 61) ? (v.x - mu) * rs * gv0 + bv0 : v.x;
            float o1 = (cch+1 < 61) ? (v.y - mu) * rs * gv1 + bv1 : v.y;
            *(__half2*)&Vh[r*PAD + cch] = __floats2half2_rn(o0, o1);
        }
        __syncthreads();

        float s[8][4];
        #pragma unroll
        for (int t = 0; t < 8; t++)
            #pragma unroll
            for (int j = 0; j < 4; j++) s[t][j] = 0.f;
        #pragma unroll
        for (int kk = 0; kk < 4; kk++) {
            #pragma unroll
            for (int np = 0; np < 4; np++) {
                unsigned b0, b1, b2, b3;
                const __half* p = Kh + (np*16 + (lane & 7) + ((lane >> 4) << 3))*PAD
                                     + kk*16 + (((lane >> 3) & 1) << 3);
                ldm4(b0, b1, b2, b3, p);
                mma16816(s[2*np],   qa[kk][0], qa[kk][1], qa[kk][2], qa[kk][3], b0, b1);
                mma16816(s[2*np+1], qa[kk][0], qa[kk][1], qa[kk][2], qa[kk][3], b2, b3);
            }
        }

        float mx0 = -1e30f, mx1 = -1e30f;
        #pragma unroll
        for (int t = 0; t < 8; t++) {
            mx0 = fmaxf(mx0, fmaxf(s[t][0], s[t][1]));
            mx1 = fmaxf(mx1, fmaxf(s[t][2], s[t][3]));
        }
        mx0 = fmaxf(mx0, __shfl_xor_sync(0xffffffffu, mx0, 1));
        mx0 = fmaxf(mx0, __shfl_xor_sync(0xffffffffu, mx0, 2));
        mx1 = fmaxf(mx1, __shfl_xor_sync(0xffffffffu, mx1, 1));
        mx1 = fmaxf(mx1, __shfl_xor_sync(0xffffffffu, mx1, 2));
        float mn0 = fmaxf(m0, mx0), mn1 = fmaxf(m1, mx1);
        float corr0 = __expf(m0 - mn0), corr1 = __expf(m1 - mn1);
        m0 = mn0; m1 = mn1;
        float sum0 = 0.f, sum1 = 0.f;
        #pragma unroll
        for (int t = 0; t < 8; t++) {
            s[t][0] = __expf(s[t][0] - m0); s[t][1] = __expf(s[t][1] - m0);
            s[t][2] = __expf(s[t][2] - m1); s[t][3] = __expf(s[t][3] - m1);
            sum0 += s[t][0] + s[t][1];
            sum1 += s[t][2] + s[t][3];
        }
        sum0 += __shfl_xor_sync(0xffffffffu, sum0, 1);
        sum0 += __shfl_xor_sync(0xffffffffu, sum0, 2);
        sum1 += __shfl_xor_sync(0xffffffffu, sum1, 1);
        sum1 += __shfl_xor_sync(0xffffffffu, sum1, 2);
        l0 = l0 * corr0 + sum0;
        l1 = l1 * corr1 + sum1;
        #pragma unroll
        for (int t = 0; t < 8; t++) {
            o[t][0] *= corr0; o[t][1] *= corr0;
            o[t][2] *= corr1; o[t][3] *= corr1;
        }

        #pragma unroll
        for (int jp = 0; jp < 4; jp++) {
            unsigned a0 = packh2(s[2*jp][0],   s[2*jp][1]);
            unsigned a1 = packh2(s[2*jp][2],   s[2*jp][3]);
            unsigned a2 = packh2(s[2*jp+1][0], s[2*jp+1][1]);
            unsigned a3 = packh2(s[2*jp+1][2], s[2*jp+1][3]);
            #pragma unroll
            for (int np = 0; np < 4; np++) {
                unsigned b0, b1, b2, b3;
                const __half* p = Vh + (jp*16 + (lane & 7) + (((lane >> 3) & 1) << 3))*PAD
                                     + np*16 + ((lane >> 4) << 3);
                ldm4t(b0, b1, b2, b3, p);
                mma16816(o[2*np],   a0, a1, a2, a3, b0, b1);
                mma16816(o[2*np+1], a0, a1, a2, a3, b2, b3);
            }
        }
        __syncthreads();
    }

    float inv0 = 1.f / l0, inv1 = 1.f / l1;
    int r0 = w*16 + (lane >> 2);
    int r1 = r0 + 8;
    int y0 = by + (r0 >> 3), x0 = bx + (r0 & 7);
    int y1 = by + (r1 >> 3), x1 = bx + (r1 & 7);
    #pragma unroll
    for (int t = 0; t < 8; t++) {
        int c = t*8 + 2*(lane & 3);
        g_ATT[(size_t)(n*64 + c    ) * HW + y0*256 + x0] = o[t][0] * inv0;
        g_ATT[(size_t)(n*64 + c + 1) * HW + y0*256 + x0] = o[t][1] * inv0;
        g_ATT[(size_t)(n*64 + c    ) * HW + y1*256 + x1] = o[t][2] * inv1;
        g_ATT[(size_t)(n*64 + c + 1) * HW + y1*256 + x1] = o[t][3] * inv1;
    }
}

// ---------------- output tail: only the g_ATT-sourced channels (float4) ----------------
__global__ void tail_kernel(float* __restrict__ out) {
    int idx = blockIdx.x * blockDim.x + threadIdx.x;
    const int HW4 = HW / 4;
    if (idx >= NB * 3 * HW4) return;
    int n = idx / (3 * HW4); int rem = idx % (3 * HW4);
    int c = rem / HW4; int hw4 = rem % HW4;
    float4 v = *(const float4*)&g_ATT[(size_t)(n*64 + 61 + c) * HW + hw4*4];
    *(float4*)&out[(size_t)(n*64 + 61 + c) * HW + hw4*4] = v;
    *(float4*)&out[(size_t)NB*64*HW + (size_t)(n*128 + 125 + c) * HW + hw4*4] = v;
}

// ---------------- host launcher ----------------
extern "C" void kernel_launch(void* const* d_in, const int* in_sizes, int n_in,
                              void* d_out, int out_size) {
    const float* radiance = (const float*)d_in[0];
    const float* skip     = (const float*)d_in[1];
    const float* dsl      = (const float*)d_in[2];
    const float* temporal = (const float*)d_in[3];
    const float* mv       = (const float*)d_in[4];
    const float* su_bn_g  = (const float*)d_in[5];
    const float* su_bn_b  = (const float*)d_in[6];
    const float* su_w     = (const float*)d_in[7];
    const float* su_b     = (const float*)d_in[8];
    const float* ds_bn_g  = (const float*)d_in[9];
    const float* ds_bn_b  = (const float*)d_in[10];
    const float* ds_w     = (const float*)d_in[11];
    const float* ds_b     = (const float*)d_in[12];
    const float* qln_g    = (const float*)d_in[13];
    const float* qln_b    = (const float*)d_in[14];
    const float* kln_g    = (const float*)d_in[15];
    const float* kln_b    = (const float*)d_in[16];
    const float* vln_g    = (const float*)d_in[17];
    const float* vln_b    = (const float*)d_in[18];
    const float* f1_g     = (const float*)d_in[19];
    const float* f1_b     = (const float*)d_in[20];
    const float* w1       = (const float*)d_in[21];
    const float* b1       = (const float*)d_in[22];
    const float* f2_g     = (const float*)d_in[23];
    const float* f2_b     = (const float*)d_in[24];
    const float* w2       = (const float*)d_in[25];
    const float* b2       = (const float*)d_in[26];
    float* out = (float*)d_out;

    float *dUS, *dSU, *dDSS, *dDSE, *dATT, *dH1;
    cudaGetSymbolAddress((void**)&dUS,  g_US);
    cudaGetSymbolAddress((void**)&dSU,  g_SU);
    cudaGetSymbolAddress((void**)&dDSS, g_DSS);
    cudaGetSymbolAddress((void**)&dDSE, g_DSE);
    cudaGetSymbolAddress((void**)&dATT, g_ATT);
    cudaGetSymbolAddress((void**)&dH1,  g_H1);

    float* outTemporal = out + (size_t)NB*64*HW;

    const int ATTN_SMEM = 3*64*PAD*2 + 2*64*RSTR*4;   // 27648 + 33792 = 61440 B
    cudaFuncSetAttribute(attn_kernel, cudaFuncAttributeMaxDynamicSharedMemorySize, ATTN_SMEM);
    const int CONV_SMEM = (2*32*PADX + 2*64*PADK) * 2;  // 44032 B

    // 1. us = resize(ds_latent, 128->256)
    resize_kernel<<<(NB*96*HW + 255)/256, 256>>>(dsl, dUS, 96, 128, 128, 256, 256);
    // 2-3. su BN stats + conv1x1 -> su_emb (189 ch); ch 64..188 mirrored to temporal_out
    bn_stats1_kernel<<<dim3(192, NSLAB), 256>>>(skip, 96, dUS, 96, HW);
    bn_stats2_kernel<<<192, 32>>>(su_bn_g, su_bn_b, HW);
    conv1x1_tc_kernel<<<dim3((NB*HW)/256, 3), 256, CONV_SMEM>>>(skip, 96, dUS, 96, su_w, su_b, 189, HW, dSU, 189, 0, outTemporal);
    // 4. warped temporal kv
    warp_kernel<<<dim3((NB*HW + 255)/256, 16), 256>>>(temporal, mv);
    // 5-8. ds embedding
    bn_stats1_kernel<<<dim3(96, NSLAB), 256>>>(dsl, 96, (const float*)0, 0, DHW);
    bn_stats2_kernel<<<96, 32>>>(ds_bn_g, ds_bn_b, DHW);
    conv1x1_tc_kernel<<<dim3((NB*DHW)/256, 2), 256, CONV_SMEM>>>(dsl, 96, (const float*)0, 0, ds_w, ds_b, 125, DHW, dDSS, 128, 0, (float*)0);
    dscopy_kernel<<<(NB*3*DHW + 255)/256, 256>>>(dsl);
    resize_kernel<<<(NB*128*HW + 255)/256, 256>>>(dDSS, dDSE, 128, 128, 128, 256, 256);
    // 9. attention (tensor-core)
    attn_kernel<<<NB*1024, 128, ATTN_SMEM>>>(radiance, qln_g, qln_b, kln_g, kln_b, vln_g, vln_b);
    // 10-13. FFN
    bn_stats1_kernel<<<dim3(64, NSLAB), 256>>>(dATT, 64, (const float*)0, 0, HW);
    bn_stats2_kernel<<<64, 32>>>(f1_g, f1_b, HW);
    conv1x1_tc_kernel<<<dim3((NB*HW)/256, 2), 256, CONV_SMEM>>>(dATT, 64, (const float*)0, 0, w1, b1, 128, HW, dH1, 128, 1, (float*)0);
    bn_stats1_kernel<<<dim3(128, NSLAB), 256>>>(dH1, 128, (const float*)0, 0, HW);
    bn_stats2_kernel<<<128, 32>>>(f2_g, f2_b, HW);
    conv1x1_tc_kernel<<<dim3((NB*HW)/256, 1), 256, CONV_SMEM>>>(dH1, 128, (const float*)0, 0, w2, b2, 61, HW, out, 64, 0, (float*)0);
    // 14. remaining tail channels (attention-sourced)
    tail_kernel<<<(NB*3*HW/4 + 255)/256, 256>>>(out);
}